// round 1
// baseline (speedup 1.0000x reference)
#include <cuda_runtime.h>
#include <cuda_bf16.h>
#include <math.h>

// Problem constants
#define B_  8
#define S_  1024
#define D_  256
#define H_  8
#define DH_ 32
#define L_  4
#define V_  100
#define DFF_ 1024
#define M_TOK (B_ * S_)   // 8192

// -------- scratch (static device globals; no runtime allocation) --------
__device__ float g_x [M_TOK * D_];
__device__ float g_q [M_TOK * D_];
__device__ float g_k [M_TOK * D_];
__device__ float g_v [M_TOK * D_];
__device__ float g_y [M_TOK * D_];
__device__ float g_ff[M_TOK * DFF_];

// ================= embedding + sinusoidal position encoding ==============
__global__ void embed_kernel(const int* __restrict__ ids,
                             const float* __restrict__ emb,
                             float* __restrict__ X)
{
    int t = blockIdx.x;            // token index b*S + s
    int d = threadIdx.x;           // 0..255
    int s = t & (S_ - 1);
    int id = ids[t];
    float f = (d < D_ / 2) ? (2.0f * d) : (2.0f * (d - D_ / 2) + 1.0f);
    // 10000^(-f/D) = 2^(-f*log2(10000)/D)
    float inv = exp2f(-f * 13.287712379549449f / (float)D_);
    X[(size_t)t * D_ + d] = emb[(size_t)id * D_ + d] + sinf((float)s * inv);
}

// ======================= generic fp32 GEMM: C = A*W + bias ================
// A [M,K] row-major, W [K,N] row-major, bias [N]. Optional ReLU.
// BM=128, BN=64, BK=16, 256 threads, thread tile 8x4.
#define BM 128
#define BN 64
#define BK 16
#define TM 8
#define TN 4

__global__ __launch_bounds__(256)
void gemm_kernel(const float* __restrict__ A, const float* __restrict__ W,
                 const float* __restrict__ bias, float* __restrict__ C,
                 int M, int N, int K, int relu)
{
    __shared__ float As[BK][BM + 4];   // padded to kill store bank conflicts
    __shared__ float Ws[BK][BN];

    int tid = threadIdx.x;
    int bm = blockIdx.y * BM;
    int bn = blockIdx.x * BN;
    int tm = (tid >> 4) * TM;   // 0..120
    int tn = (tid & 15) * TN;   // 0..60

    float acc[TM][TN];
#pragma unroll
    for (int i = 0; i < TM; i++)
#pragma unroll
        for (int j = 0; j < TN; j++) acc[i][j] = 0.0f;

    for (int kt = 0; kt < K; kt += BK) {
        // ---- load A tile [128 rows x 16 cols] as 512 float4, 2 per thread
#pragma unroll
        for (int i = 0; i < 2; i++) {
            int j   = tid + 256 * i;          // float4 index 0..511
            int row = j >> 2;                 // 0..127
            int c4  = (j & 3) * 4;            // 0,4,8,12
            float4 a = *(const float4*)(A + (size_t)(bm + row) * K + kt + c4);
            As[c4 + 0][row] = a.x;
            As[c4 + 1][row] = a.y;
            As[c4 + 2][row] = a.z;
            As[c4 + 3][row] = a.w;
        }
        // ---- load W tile [16 rows x 64 cols], 1 float4 per thread
        {
            int row = tid >> 4;               // 0..15
            int col = (tid & 15) * 4;         // 0..60
            float4 w;
            if (bn + col + 3 < N)
                w = *(const float4*)(W + (size_t)(kt + row) * N + bn + col);
            else
                w = make_float4(0.f, 0.f, 0.f, 0.f);
            *(float4*)(&Ws[row][col]) = w;
        }
        __syncthreads();

#pragma unroll
        for (int k = 0; k < BK; k++) {
            float rm[TM], rn[TN];
#pragma unroll
            for (int i = 0; i < TM; i += 4) {
                float4 v = *(const float4*)(&As[k][tm + i]);
                rm[i] = v.x; rm[i + 1] = v.y; rm[i + 2] = v.z; rm[i + 3] = v.w;
            }
            {
                float4 v = *(const float4*)(&Ws[k][tn]);
                rn[0] = v.x; rn[1] = v.y; rn[2] = v.z; rn[3] = v.w;
            }
#pragma unroll
            for (int i = 0; i < TM; i++)
#pragma unroll
                for (int j = 0; j < TN; j++)
                    acc[i][j] += rm[i] * rn[j];
        }
        __syncthreads();
    }

#pragma unroll
    for (int i = 0; i < TM; i++) {
        int m = bm + tm + i;
#pragma unroll
        for (int j = 0; j < TN; j++) {
            int n = bn + tn + j;
            if (n < N) {
                float v = acc[i][j] + bias[n];
                if (relu) v = fmaxf(v, 0.0f);
                C[(size_t)m * N + n] = v;
            }
        }
    }
}

// ===================== causal flash-style attention =======================
// One thread per query row. dh=32. K/V tiles of 64 keys in shared memory.
// Online softmax with chunked (16-key) rescale.
__global__ __launch_bounds__(128)
void attn_kernel(const float* __restrict__ Q, const float* __restrict__ Kg,
                 const float* __restrict__ Vg, float* __restrict__ Y,
                 const int* __restrict__ tsl)
{
    __shared__ float Ks[64][32];
    __shared__ float Vs[64][32];

    int tid = threadIdx.x;
    int b = blockIdx.z, h = blockIdx.y;
    int q = blockIdx.x * 128 + tid;
    int len = tsl[b];

    float4 qv[8];
    {
        const float* qp = Q + ((size_t)(b * S_ + q)) * D_ + h * DH_;
        float sc = rsqrtf((float)DH_);
#pragma unroll
        for (int i = 0; i < 8; i++) {
            qv[i] = *(const float4*)(qp + 4 * i);
            qv[i].x *= sc; qv[i].y *= sc; qv[i].z *= sc; qv[i].w *= sc;
        }
    }

    float m = -1e30f, l = 0.0f;
    float y[32];
#pragma unroll
    for (int d = 0; d < 32; d++) y[d] = 0.0f;

    int qmax = blockIdx.x * 128 + 127;
    for (int kt = 0; kt <= qmax; kt += 64) {
        // cooperative K/V tile load: 512 float4 each, 4 per thread
#pragma unroll
        for (int i = 0; i < 4; i++) {
            int j = tid + 128 * i;        // 0..511
            int row = j >> 3;             // 0..63
            int c = (j & 7) * 4;          // 0..28
            size_t g = ((size_t)(b * S_ + kt + row)) * D_ + h * DH_ + c;
            *(float4*)(&Ks[row][c]) = *(const float4*)(Kg + g);
            *(float4*)(&Vs[row][c]) = *(const float4*)(Vg + g);
        }
        __syncthreads();

#pragma unroll 1
        for (int c0 = 0; c0 < 64; c0 += 16) {
            float s[16];
            float tmax = -1e30f;
#pragma unroll
            for (int i = 0; i < 16; i++) {
                int kk = c0 + i;
                int kg = kt + kk;
                const float4* kp = (const float4*)(&Ks[kk][0]);
                float acc = 0.0f;
#pragma unroll
                for (int t = 0; t < 8; t++) {
                    float4 kv = kp[t];
                    acc += qv[t].x * kv.x + qv[t].y * kv.y
                         + qv[t].z * kv.z + qv[t].w * kv.w;
                }
                bool valid = (kg <= q) && (kg < len) && (q < len);
                s[i] = valid ? acc : -1e30f;
                tmax = fmaxf(tmax, s[i]);
            }
            if (tmax > -1e29f) {
                float mnew = fmaxf(m, tmax);
                float corr = __expf(m - mnew);
                m = mnew;
                l *= corr;
#pragma unroll
                for (int d = 0; d < 32; d++) y[d] *= corr;
#pragma unroll
                for (int i = 0; i < 16; i++) {
                    float p = __expf(s[i] - m);
                    l += p;
                    const float4* vp = (const float4*)(&Vs[c0 + i][0]);
#pragma unroll
                    for (int t = 0; t < 8; t++) {
                        float4 vv = vp[t];
                        y[4 * t + 0] += p * vv.x;
                        y[4 * t + 1] += p * vv.y;
                        y[4 * t + 2] += p * vv.z;
                        y[4 * t + 3] += p * vv.w;
                    }
                }
            }
        }
        __syncthreads();
    }

    float inv = (l > 0.0f) ? (1.0f / l) : 0.0f;
    float* yp = Y + ((size_t)(b * S_ + q)) * D_ + h * DH_;
#pragma unroll
    for (int d = 0; d < 32; d += 4) {
        float4 o = make_float4(y[d] * inv, y[d + 1] * inv,
                               y[d + 2] * inv, y[d + 3] * inv);
        *(float4*)(yp + d) = o;
    }
}

// ====================== residual add + LayerNorm (in place) ===============
__global__ __launch_bounds__(256)
void add_ln_kernel(float* X, const float* __restrict__ Yb,
                   const float* __restrict__ g, const float* __restrict__ be)
{
    int row = blockIdx.x;
    int d = threadIdx.x;
    size_t idx = (size_t)row * D_ + d;
    float h = X[idx] + Yb[idx];

    float s = h, s2 = h * h;
#pragma unroll
    for (int o = 16; o; o >>= 1) {
        s  += __shfl_xor_sync(0xFFFFFFFFu, s,  o);
        s2 += __shfl_xor_sync(0xFFFFFFFFu, s2, o);
    }
    __shared__ float ws[8], ws2[8];
    int w = d >> 5;
    if ((d & 31) == 0) { ws[w] = s; ws2[w] = s2; }
    __syncthreads();
    float tot = 0.f, tot2 = 0.f;
#pragma unroll
    for (int i = 0; i < 8; i++) { tot += ws[i]; tot2 += ws2[i]; }

    float mean = tot * (1.0f / D_);
    float var  = tot2 * (1.0f / D_) - mean * mean;
    float r = rsqrtf(var + 1e-5f);
    X[idx] = (h - mean) * r * g[d] + be[d];
}

// =========================== launcher ====================================
extern "C" void kernel_launch(void* const* d_in, const int* in_sizes, int n_in,
                              void* d_out, int out_size)
{
    const int*   ids = (const int*)  d_in[0];
    const int*   tsl = (const int*)  d_in[1];
    const float* emb = (const float*)d_in[2];
    const float* Wq  = (const float*)d_in[3];
    const float* bq  = (const float*)d_in[4];
    const float* Wk  = (const float*)d_in[5];
    const float* bk  = (const float*)d_in[6];
    const float* Wv  = (const float*)d_in[7];
    const float* bv  = (const float*)d_in[8];
    const float* Wo  = (const float*)d_in[9];
    const float* bo  = (const float*)d_in[10];
    const float* W1  = (const float*)d_in[11];
    const float* b1  = (const float*)d_in[12];
    const float* W2  = (const float*)d_in[13];
    const float* b2  = (const float*)d_in[14];
    const float* g1  = (const float*)d_in[15];
    const float* be1 = (const float*)d_in[16];
    const float* g2  = (const float*)d_in[17];
    const float* be2 = (const float*)d_in[18];
    const float* Wc  = (const float*)d_in[19];
    const float* bc  = (const float*)d_in[20];
    float* out = (float*)d_out;

    float *x, *q, *k, *v, *y, *ff;
    cudaGetSymbolAddress((void**)&x,  g_x);
    cudaGetSymbolAddress((void**)&q,  g_q);
    cudaGetSymbolAddress((void**)&k,  g_k);
    cudaGetSymbolAddress((void**)&v,  g_v);
    cudaGetSymbolAddress((void**)&y,  g_y);
    cudaGetSymbolAddress((void**)&ff, g_ff);

    embed_kernel<<<M_TOK, D_>>>(ids, emb, x);

    dim3 gD  (D_  / BN, M_TOK / BM);   // N=256
    dim3 gF1 (DFF_/ BN, M_TOK / BM);   // N=1024
    dim3 gCls((V_ + BN - 1) / BN, M_TOK / BM); // N=100

    for (int l = 0; l < L_; l++) {
        const float* wq = Wq + (size_t)l * D_ * D_;
        const float* wk = Wk + (size_t)l * D_ * D_;
        const float* wv = Wv + (size_t)l * D_ * D_;
        const float* wo = Wo + (size_t)l * D_ * D_;
        const float* w1 = W1 + (size_t)l * D_ * DFF_;
        const float* w2 = W2 + (size_t)l * DFF_ * D_;

        gemm_kernel<<<gD, 256>>>(x, wq, bq + l * D_, q, M_TOK, D_, D_, 0);
        gemm_kernel<<<gD, 256>>>(x, wk, bk + l * D_, k, M_TOK, D_, D_, 0);
        gemm_kernel<<<gD, 256>>>(x, wv, bv + l * D_, v, M_TOK, D_, D_, 0);

        attn_kernel<<<dim3(S_ / 128, H_, B_), 128>>>(q, k, v, y, tsl);

        gemm_kernel<<<gD, 256>>>(y, wo, bo + l * D_, q, M_TOK, D_, D_, 0);
        add_ln_kernel<<<M_TOK, D_>>>(x, q, g1 + l * D_, be1 + l * D_);

        gemm_kernel<<<gF1, 256>>>(x, w1, b1 + l * DFF_, ff, M_TOK, DFF_, D_, 1);
        gemm_kernel<<<gD, 256>>>(ff, w2, b2 + l * D_, y, M_TOK, D_, DFF_, 0);
        add_ln_kernel<<<M_TOK, D_>>>(x, y, g2 + l * D_, be2 + l * D_);
    }

    gemm_kernel<<<gCls, 256>>>(x, Wc, bc, out, M_TOK, V_, D_, 0);
}

// round 3
// speedup vs baseline: 1.4417x; 1.4417x over previous
#include <cuda_runtime.h>
#include <cuda_bf16.h>
#include <math.h>
#include <stdint.h>

// Problem constants
#define B_  8
#define S_  1024
#define D_  256
#define H_  8
#define DH_ 32
#define L_  4
#define V_  100
#define DFF_ 1024
#define M_TOK (B_ * S_)   // 8192
#define QKV_N 768

// -------- scratch (static device globals; no runtime allocation) --------
__device__ float g_x  [M_TOK * D_];
__device__ float g_qkv[M_TOK * QKV_N];
__device__ float g_y  [M_TOK * D_];
__device__ float g_t  [M_TOK * D_];
__device__ float g_ff [M_TOK * DFF_];

// K-major ([N,K]) bf16 hi/lo weight planes
__device__ __nv_bfloat16 g_qkvT_hi[L_*QKV_N*D_], g_qkvT_lo[L_*QKV_N*D_];
__device__ __nv_bfloat16 g_oT_hi [L_*D_*D_],     g_oT_lo [L_*D_*D_];
__device__ __nv_bfloat16 g_1T_hi [L_*DFF_*D_],   g_1T_lo [L_*DFF_*D_];
__device__ __nv_bfloat16 g_2T_hi [L_*D_*DFF_],   g_2T_lo [L_*D_*DFF_];
__device__ __nv_bfloat16 g_cT_hi [128*D_],       g_cT_lo [128*D_];
__device__ float g_bqkv[L_ * QKV_N];

// =========================== PTX helpers ==================================
__device__ __forceinline__ uint32_t smem_u32(const void* p) {
    uint32_t r;
    asm("{ .reg .u64 t; cvta.to.shared.u64 t, %1; cvt.u32.u64 %0, t; }"
        : "=r"(r) : "l"(p));
    return r;
}
__device__ __forceinline__ void cp_async16(uint32_t dst, const void* src) {
    asm volatile("cp.async.cg.shared.global [%0], [%1], 16;"
                 :: "r"(dst), "l"(src));
}
__device__ __forceinline__ void cp_commit() {
    asm volatile("cp.async.commit_group;" ::: "memory");
}
__device__ __forceinline__ void cp_wait1() {
    asm volatile("cp.async.wait_group 1;" ::: "memory");
}
__device__ __forceinline__ void cp_wait0() {
    asm volatile("cp.async.wait_group 0;" ::: "memory");
}
__device__ __forceinline__ void ldsm_x4(uint32_t* r, uint32_t addr) {
    asm volatile("ldmatrix.sync.aligned.m8n8.x4.shared.b16 {%0,%1,%2,%3}, [%4];"
                 : "=r"(r[0]), "=r"(r[1]), "=r"(r[2]), "=r"(r[3]) : "r"(addr));
}
__device__ __forceinline__ void mma_bf16(float* d, const uint32_t* a,
                                         uint32_t b0, uint32_t b1) {
    asm volatile(
        "mma.sync.aligned.m16n8k16.row.col.f32.bf16.bf16.f32 "
        "{%0,%1,%2,%3}, {%4,%5,%6,%7}, {%8,%9}, {%0,%1,%2,%3};"
        : "+f"(d[0]), "+f"(d[1]), "+f"(d[2]), "+f"(d[3])
        : "r"(a[0]), "r"(a[1]), "r"(a[2]), "r"(a[3]), "r"(b0), "r"(b1));
}
__device__ __forceinline__ uint32_t swz128(uint32_t x) {
    return x ^ ((x >> 3) & 0x70u);
}
__device__ __forceinline__ uint32_t pack_bf2(__nv_bfloat16 a, __nv_bfloat16 b) {
    __nv_bfloat162 t(a, b);
    return *reinterpret_cast<uint32_t*>(&t);
}

// ===================== GEMM tiling constants ==============================
#define GBM 128
#define GBN 64
#define GKB 64
#define APLANE 16384            // 128 rows x 128B
#define BPLANE 8192             // 64 rows x 128B
#define BUFB (2*APLANE + 2*BPLANE)  // 49152
#define GEMM_SMEM (2*BUFB + 1024)

// ============ weight transpose + bf16 hi/lo split:  W[K,N] -> WT[N,K] =====
__global__ void convert_w_kernel(const float* __restrict__ W,
                                 __nv_bfloat16* __restrict__ Hi,
                                 __nv_bfloat16* __restrict__ Lo,
                                 int K, int N, int Npad)
{
    __shared__ float t[32][33];
    const float* Wz = W + (size_t)blockIdx.z * K * N;
    __nv_bfloat16* Hz = Hi + (size_t)blockIdx.z * Npad * K;
    __nv_bfloat16* Lz = Lo + (size_t)blockIdx.z * Npad * K;
    int k0 = blockIdx.x * 32, n0 = blockIdx.y * 32;
    int tx = threadIdx.x, ty = threadIdx.y;
#pragma unroll
    for (int r = 0; r < 4; r++) {
        int k = k0 + ty + 8 * r;
        int n = n0 + tx;
        t[ty + 8 * r][tx] = (n < N) ? Wz[(size_t)k * N + n] : 0.0f;
    }
    __syncthreads();
#pragma unroll
    for (int r = 0; r < 4; r++) {
        int n = n0 + ty + 8 * r;
        int k = k0 + tx;
        float v = t[tx][ty + 8 * r];
        __nv_bfloat16 h = __float2bfloat16(v);
        __nv_bfloat16 l = __float2bfloat16(v - __bfloat162float(h));
        Hz[(size_t)n * K + k] = h;
        Lz[(size_t)n * K + k] = l;
    }
}

__global__ void pack_bias_kernel(const float* __restrict__ bq,
                                 const float* __restrict__ bk,
                                 const float* __restrict__ bv,
                                 float* __restrict__ o)
{
    int l = blockIdx.x, j = threadIdx.x;   // 768 threads
    float v;
    if (j < 256)      v = bq[l * 256 + j];
    else if (j < 512) v = bk[l * 256 + j - 256];
    else              v = bv[l * 256 + j - 512];
    o[l * QKV_N + j] = v;
}

// ====================== HMMA bf16 split-precision GEMM ====================
// C[M,N] = A[M,K](fp32) * B^T + bias.  B stored [Npad,K] bf16 hi/lo planes.
__device__ __forceinline__ void gemm_fill(
    char* sm, uint32_t smU, int b, int kb,
    const float* __restrict__ A,
    const __nv_bfloat16* __restrict__ BHi, const __nv_bfloat16* __restrict__ BLo,
    int K, int bm, int bn, int tid)
{
    const int k0 = kb * GKB;
    char* aHi = sm + b * BUFB;
    char* aLo = aHi + APLANE;
    uint32_t bHiU = smU + b * BUFB + 2 * APLANE;
    uint32_t bLoU = bHiU + BPLANE;

    const float* Ab = A + (size_t)bm * K + k0;
#pragma unroll
    for (int i = 0; i < 8; i++) {
        int j   = tid + 256 * i;          // 0..2047
        int row = j >> 4;                 // 0..127
        int c4  = (j & 15) << 2;          // 0..60 (float col)
        float4 a = *(const float4*)(Ab + (size_t)row * K + c4);
        __nv_bfloat16 h0 = __float2bfloat16(a.x);
        __nv_bfloat16 h1 = __float2bfloat16(a.y);
        __nv_bfloat16 h2 = __float2bfloat16(a.z);
        __nv_bfloat16 h3 = __float2bfloat16(a.w);
        __nv_bfloat16 l0 = __float2bfloat16(a.x - __bfloat162float(h0));
        __nv_bfloat16 l1 = __float2bfloat16(a.y - __bfloat162float(h1));
        __nv_bfloat16 l2 = __float2bfloat16(a.z - __bfloat162float(h2));
        __nv_bfloat16 l3 = __float2bfloat16(a.w - __bfloat162float(h3));
        uint32_t off = swz128((uint32_t)(row * 128 + c4 * 2));
        uint2 ph; ph.x = pack_bf2(h0, h1); ph.y = pack_bf2(h2, h3);
        uint2 pl; pl.x = pack_bf2(l0, l1); pl.y = pack_bf2(l2, l3);
        *(uint2*)(aHi + off) = ph;
        *(uint2*)(aLo + off) = pl;
    }
#pragma unroll
    for (int i = 0; i < 2; i++) {
        int j   = tid + 256 * i;          // 0..511
        int row = j >> 3;                 // 0..63
        int ch  = (j & 7) << 4;           // byte 0..112
        uint32_t off = swz128((uint32_t)(row * 128 + ch));
        const char* sh = (const char*)(BHi + (size_t)(bn + row) * K + k0) + ch;
        const char* sl = (const char*)(BLo + (size_t)(bn + row) * K + k0) + ch;
        cp_async16(bHiU + off, sh);
        cp_async16(bLoU + off, sl);
    }
}

__device__ __forceinline__ void gemm_compute(
    uint32_t smU, int b, int m0, int n0, int lane, float (*acc)[4][4])
{
    const uint32_t aU = smU + b * BUFB;
    const uint32_t bU = aU + 2 * APLANE;

    const int a_row = m0 + (lane & 15);
    const int a_kb  = (lane >> 4) * 16;                 // byte
    const int b_row = n0 + ((lane >> 4) << 3) + (lane & 7);
    const int b_kb  = ((lane >> 3) & 1) * 16;           // byte

#pragma unroll
    for (int ks = 0; ks < 4; ks++) {
        const int kbase = ks * 32;                      // byte offset of k0
        uint32_t ah[2][4], al[2][4], bh[2][4], bl[2][4];
#pragma unroll
        for (int mi = 0; mi < 2; mi++) {
            uint32_t off = swz128((uint32_t)((a_row + mi * 16) * 128 + kbase + a_kb));
            ldsm_x4(ah[mi], aU + off);
            ldsm_x4(al[mi], aU + APLANE + off);
        }
#pragma unroll
        for (int bi = 0; bi < 2; bi++) {
            uint32_t off = swz128((uint32_t)((b_row + bi * 16) * 128 + kbase + b_kb));
            ldsm_x4(bh[bi], bU + off);
            ldsm_x4(bl[bi], bU + BPLANE + off);
        }
#pragma unroll
        for (int mi = 0; mi < 2; mi++)
#pragma unroll
            for (int ni = 0; ni < 4; ni++) {
                uint32_t h0 = bh[ni >> 1][(ni & 1) * 2];
                uint32_t h1 = bh[ni >> 1][(ni & 1) * 2 + 1];
                uint32_t l0 = bl[ni >> 1][(ni & 1) * 2];
                uint32_t l1 = bl[ni >> 1][(ni & 1) * 2 + 1];
                mma_bf16(acc[mi][ni], ah[mi], h0, h1);
                mma_bf16(acc[mi][ni], ah[mi], l0, l1);
                mma_bf16(acc[mi][ni], al[mi], h0, h1);
            }
    }
}

__global__ __launch_bounds__(256)
void gemm_tc(const float* __restrict__ A,
             const __nv_bfloat16* __restrict__ BHi,
             const __nv_bfloat16* __restrict__ BLo,
             const float* __restrict__ bias,
             float* __restrict__ C,
             int K, int N, int relu)
{
    extern __shared__ char dsm_raw[];
    const int tid  = threadIdx.x;
    const int lane = tid & 31;
    const int wid  = tid >> 5;
    const int m0   = (wid >> 1) * 32;
    const int n0   = (wid & 1) * 32;
    const int bm   = blockIdx.y * GBM;
    const int bn   = blockIdx.x * GBN;
    const int nk   = K / GKB;

    uint32_t rawU = smem_u32(dsm_raw);
    uint32_t smU  = (rawU + 1023u) & ~1023u;
    char* sm = dsm_raw + (smU - rawU);

    float acc[2][4][4];
#pragma unroll
    for (int mi = 0; mi < 2; mi++)
#pragma unroll
        for (int ni = 0; ni < 4; ni++)
#pragma unroll
            for (int e = 0; e < 4; e++) acc[mi][ni][e] = 0.0f;

    gemm_fill(sm, smU, 0, 0, A, BHi, BLo, K, bm, bn, tid);
    cp_commit();

    for (int kb = 0; kb < nk; kb++) {
        const int b = kb & 1;
        if (kb + 1 < nk) {
            gemm_fill(sm, smU, b ^ 1, kb + 1, A, BHi, BLo, K, bm, bn, tid);
            cp_commit();
            cp_wait1();
        } else {
            cp_wait0();
        }
        __syncthreads();
        gemm_compute(smU, b, m0, n0, lane, acc);
        __syncthreads();
    }

    // epilogue
    const int gr = lane >> 2;
    const int gc = (lane & 3) * 2;
#pragma unroll
    for (int mi = 0; mi < 2; mi++) {
        int r0 = bm + m0 + mi * 16 + gr;
#pragma unroll
        for (int ni = 0; ni < 4; ni++) {
            int c = bn + n0 + ni * 8 + gc;
            if (c + 1 < N) {
                float2 v0, v1;
                v0.x = acc[mi][ni][0] + bias[c];
                v0.y = acc[mi][ni][1] + bias[c + 1];
                v1.x = acc[mi][ni][2] + bias[c];
                v1.y = acc[mi][ni][3] + bias[c + 1];
                if (relu) {
                    v0.x = fmaxf(v0.x, 0.f); v0.y = fmaxf(v0.y, 0.f);
                    v1.x = fmaxf(v1.x, 0.f); v1.y = fmaxf(v1.y, 0.f);
                }
                *(float2*)(C + (size_t)r0 * N + c) = v0;
                *(float2*)(C + (size_t)(r0 + 8) * N + c) = v1;
            } else if (c < N) {
                float v0 = acc[mi][ni][0] + bias[c];
                float v1 = acc[mi][ni][2] + bias[c];
                if (relu) { v0 = fmaxf(v0, 0.f); v1 = fmaxf(v1, 0.f); }
                C[(size_t)r0 * N + c] = v0;
                C[(size_t)(r0 + 8) * N + c] = v1;
            }
        }
    }
}

// ================= embedding + sinusoidal position encoding ==============
__global__ void embed_kernel(const int* __restrict__ ids,
                             const float* __restrict__ emb,
                             float* __restrict__ X)
{
    int t = blockIdx.x;
    int d = threadIdx.x;
    int s = t & (S_ - 1);
    int id = ids[t];
    float f = (d < D_ / 2) ? (2.0f * d) : (2.0f * (d - D_ / 2) + 1.0f);
    float inv = exp2f(-f * 13.287712379549449f / (float)D_);
    X[(size_t)t * D_ + d] = emb[(size_t)id * D_ + d] + sinf((float)s * inv);
}

// ===================== causal flash-style attention =======================
// Q/K/V read from fused [M, 768] buffer (cols 0/256/512).
__global__ __launch_bounds__(128)
void attn_kernel(const float* __restrict__ QKV, float* __restrict__ Y,
                 const int* __restrict__ tsl)
{
    __shared__ float Ks[64][32];
    __shared__ float Vs[64][32];

    int tid = threadIdx.x;
    int b = blockIdx.z, h = blockIdx.y;
    int q = blockIdx.x * 128 + tid;
    int len = tsl[b];

    float4 qv[8];
    {
        const float* qp = QKV + (size_t)(b * S_ + q) * QKV_N + h * DH_;
        float sc = rsqrtf((float)DH_);
#pragma unroll
        for (int i = 0; i < 8; i++) {
            qv[i] = *(const float4*)(qp + 4 * i);
            qv[i].x *= sc; qv[i].y *= sc; qv[i].z *= sc; qv[i].w *= sc;
        }
    }

    float m = -1e30f, l = 0.0f;
    float y[32];
#pragma unroll
    for (int d = 0; d < 32; d++) y[d] = 0.0f;

    int qmax = blockIdx.x * 128 + 127;
    for (int kt = 0; kt <= qmax; kt += 64) {
#pragma unroll
        for (int i = 0; i < 4; i++) {
            int j = tid + 128 * i;
            int row = j >> 3;
            int c = (j & 7) * 4;
            size_t g = (size_t)(b * S_ + kt + row) * QKV_N + h * DH_ + c;
            *(float4*)(&Ks[row][c]) = *(const float4*)(QKV + g + 256);
            *(float4*)(&Vs[row][c]) = *(const float4*)(QKV + g + 512);
        }
        __syncthreads();

#pragma unroll 1
        for (int c0 = 0; c0 < 64; c0 += 16) {
            float s[16];
            float tmax = -1e30f;
#pragma unroll
            for (int i = 0; i < 16; i++) {
                int kk = c0 + i;
                int kg = kt + kk;
                const float4* kp = (const float4*)(&Ks[kk][0]);
                float acc = 0.0f;
#pragma unroll
                for (int t = 0; t < 8; t++) {
                    float4 kv = kp[t];
                    acc += qv[t].x * kv.x + qv[t].y * kv.y
                         + qv[t].z * kv.z + qv[t].w * kv.w;
                }
                bool valid = (kg <= q) && (kg < len) && (q < len);
                s[i] = valid ? acc : -1e30f;
                tmax = fmaxf(tmax, s[i]);
            }
            if (tmax > -1e29f) {
                float mnew = fmaxf(m, tmax);
                float corr = __expf(m - mnew);
                m = mnew;
                l *= corr;
#pragma unroll
                for (int d = 0; d < 32; d++) y[d] *= corr;
#pragma unroll
                for (int i = 0; i < 16; i++) {
                    float p = __expf(s[i] - m);
                    l += p;
                    const float4* vp = (const float4*)(&Vs[c0 + i][0]);
#pragma unroll
                    for (int t = 0; t < 8; t++) {
                        float4 vv = vp[t];
                        y[4 * t + 0] += p * vv.x;
                        y[4 * t + 1] += p * vv.y;
                        y[4 * t + 2] += p * vv.z;
                        y[4 * t + 3] += p * vv.w;
                    }
                }
            }
        }
        __syncthreads();
    }

    float inv = (l > 0.0f) ? (1.0f / l) : 0.0f;
    float* yp = Y + (size_t)(b * S_ + q) * D_ + h * DH_;
#pragma unroll
    for (int d = 0; d < 32; d += 4) {
        float4 o = make_float4(y[d] * inv, y[d + 1] * inv,
                               y[d + 2] * inv, y[d + 3] * inv);
        *(float4*)(yp + d) = o;
    }
}

// ====================== residual add + LayerNorm (in place) ===============
__global__ __launch_bounds__(256)
void add_ln_kernel(float* X, const float* __restrict__ Yb,
                   const float* __restrict__ g, const float* __restrict__ be)
{
    int row = blockIdx.x;
    int d = threadIdx.x;
    size_t idx = (size_t)row * D_ + d;
    float h = X[idx] + Yb[idx];

    float s = h, s2 = h * h;
#pragma unroll
    for (int o = 16; o; o >>= 1) {
        s  += __shfl_xor_sync(0xFFFFFFFFu, s,  o);
        s2 += __shfl_xor_sync(0xFFFFFFFFu, s2, o);
    }
    __shared__ float ws[8], ws2[8];
    int w = d >> 5;
    if ((d & 31) == 0) { ws[w] = s; ws2[w] = s2; }
    __syncthreads();
    float tot = 0.f, tot2 = 0.f;
#pragma unroll
    for (int i = 0; i < 8; i++) { tot += ws[i]; tot2 += ws2[i]; }

    float mean = tot * (1.0f / D_);
    float var  = tot2 * (1.0f / D_) - mean * mean;
    float r = rsqrtf(var + 1e-5f);
    X[idx] = (h - mean) * r * g[d] + be[d];
}

// =========================== launcher ====================================
extern "C" void kernel_launch(void* const* d_in, const int* in_sizes, int n_in,
                              void* d_out, int out_size)
{
    const int*   ids = (const int*)  d_in[0];
    const int*   tsl = (const int*)  d_in[1];
    const float* emb = (const float*)d_in[2];
    const float* Wq  = (const float*)d_in[3];
    const float* bq  = (const float*)d_in[4];
    const float* Wk  = (const float*)d_in[5];
    const float* bk  = (const float*)d_in[6];
    const float* Wv  = (const float*)d_in[7];
    const float* bv  = (const float*)d_in[8];
    const float* Wo  = (const float*)d_in[9];
    const float* bo  = (const float*)d_in[10];
    const float* W1  = (const float*)d_in[11];
    const float* b1  = (const float*)d_in[12];
    const float* W2  = (const float*)d_in[13];
    const float* b2  = (const float*)d_in[14];
    const float* g1  = (const float*)d_in[15];
    const float* be1 = (const float*)d_in[16];
    const float* g2  = (const float*)d_in[17];
    const float* be2 = (const float*)d_in[18];
    const float* Wc  = (const float*)d_in[19];
    const float* bc  = (const float*)d_in[20];
    float* out = (float*)d_out;

    float *x, *qkv, *y, *t, *ff, *bqkv;
    cudaGetSymbolAddress((void**)&x,   g_x);
    cudaGetSymbolAddress((void**)&qkv, g_qkv);
    cudaGetSymbolAddress((void**)&y,   g_y);
    cudaGetSymbolAddress((void**)&t,   g_t);
    cudaGetSymbolAddress((void**)&ff,  g_ff);
    cudaGetSymbolAddress((void**)&bqkv, g_bqkv);

    __nv_bfloat16 *qkvTh, *qkvTl, *oTh, *oTl, *w1h, *w1l, *w2h, *w2l, *wch, *wcl;
    cudaGetSymbolAddress((void**)&qkvTh, g_qkvT_hi); cudaGetSymbolAddress((void**)&qkvTl, g_qkvT_lo);
    cudaGetSymbolAddress((void**)&oTh,  g_oT_hi);    cudaGetSymbolAddress((void**)&oTl,  g_oT_lo);
    cudaGetSymbolAddress((void**)&w1h,  g_1T_hi);    cudaGetSymbolAddress((void**)&w1l,  g_1T_lo);
    cudaGetSymbolAddress((void**)&w2h,  g_2T_hi);    cudaGetSymbolAddress((void**)&w2l,  g_2T_lo);
    cudaGetSymbolAddress((void**)&wch,  g_cT_hi);    cudaGetSymbolAddress((void**)&wcl,  g_cT_lo);

    cudaFuncSetAttribute((const void*)gemm_tc,
                         cudaFuncAttributeMaxDynamicSharedMemorySize, GEMM_SMEM);

    dim3 tb(32, 8);
    // fused QKV planes: layer stride QKV_N*D via Npad=768
    convert_w_kernel<<<dim3(8, 8, L_),  tb>>>(Wq, qkvTh,             qkvTl,             256, 256, QKV_N);
    convert_w_kernel<<<dim3(8, 8, L_),  tb>>>(Wk, qkvTh + 256 * D_,  qkvTl + 256 * D_,  256, 256, QKV_N);
    convert_w_kernel<<<dim3(8, 8, L_),  tb>>>(Wv, qkvTh + 512 * D_,  qkvTl + 512 * D_,  256, 256, QKV_N);
    convert_w_kernel<<<dim3(8, 8, L_),  tb>>>(Wo, oTh, oTl, 256, 256, 256);
    convert_w_kernel<<<dim3(8, 32, L_), tb>>>(W1, w1h, w1l, 256, 1024, 1024);
    convert_w_kernel<<<dim3(32, 8, L_), tb>>>(W2, w2h, w2l, 1024, 256, 256);
    convert_w_kernel<<<dim3(8, 4, 1),   tb>>>(Wc, wch, wcl, 256, 100, 128);
    pack_bias_kernel<<<L_, QKV_N>>>(bq, bk, bv, bqkv);

    embed_kernel<<<M_TOK, D_>>>(ids, emb, x);

    dim3 gQKV(QKV_N / GBN, M_TOK / GBM);  // 12 x 64
    dim3 gD  (D_ / GBN,    M_TOK / GBM);  // 4 x 64
    dim3 gF  (DFF_ / GBN,  M_TOK / GBM);  // 16 x 64
    dim3 gC  (2,           M_TOK / GBM);  // 100 -> 2 tiles

    for (int l = 0; l < L_; l++) {
        size_t qoff  = (size_t)l * QKV_N * D_;
        size_t ooff  = (size_t)l * D_ * D_;
        size_t w1off = (size_t)l * DFF_ * D_;

        gemm_tc<<<gQKV, 256, GEMM_SMEM>>>(x, qkvTh + qoff, qkvTl + qoff,
                                          bqkv + l * QKV_N, qkv, D_, QKV_N, 0);
        attn_kernel<<<dim3(S_ / 128, H_, B_), 128>>>(qkv, y, tsl);

        gemm_tc<<<gD, 256, GEMM_SMEM>>>(y, oTh + ooff, oTl + ooff,
                                        bo + l * D_, t, D_, D_, 0);
        add_ln_kernel<<<M_TOK, D_>>>(x, t, g1 + l * D_, be1 + l * D_);

        gemm_tc<<<gF, 256, GEMM_SMEM>>>(x, w1h + w1off, w1l + w1off,
                                        b1 + l * DFF_, ff, D_, DFF_, 1);
        gemm_tc<<<gD, 256, GEMM_SMEM>>>(ff, w2h + w1off, w2l + w1off,
                                        b2 + l * D_, t, DFF_, D_, 0);
        add_ln_kernel<<<M_TOK, D_>>>(x, t, g2 + l * D_, be2 + l * D_);
    }

    gemm_tc<<<gC, 256, GEMM_SMEM>>>(x, wch, wcl, bc, out, D_, V_, 0);
}

// round 4
// speedup vs baseline: 1.4795x; 1.0262x over previous
#include <cuda_runtime.h>
#include <cuda_bf16.h>
#include <math.h>
#include <stdint.h>

// Problem constants
#define B_  8
#define S_  1024
#define D_  256
#define H_  8
#define DH_ 32
#define L_  4
#define V_  100
#define DFF_ 1024
#define M_TOK (B_ * S_)   // 8192
#define QKV_N 768

// -------- scratch (static device globals; no runtime allocation) --------
__device__ float g_x  [M_TOK * D_];
__device__ float g_qkv[M_TOK * QKV_N];
__device__ float g_t  [M_TOK * D_];

// activation bf16 hi/lo planes ([M,K] row-major)
__device__ __nv_bfloat16 g_xh [M_TOK * D_],   g_xl [M_TOK * D_];
__device__ __nv_bfloat16 g_yh [M_TOK * D_],   g_yl [M_TOK * D_];
__device__ __nv_bfloat16 g_ffh[M_TOK * DFF_], g_ffl[M_TOK * DFF_];

// K-major ([N,K]) bf16 hi/lo weight planes
__device__ __nv_bfloat16 g_qkvT_hi[L_*QKV_N*D_], g_qkvT_lo[L_*QKV_N*D_];
__device__ __nv_bfloat16 g_oT_hi [L_*D_*D_],     g_oT_lo [L_*D_*D_];
__device__ __nv_bfloat16 g_1T_hi [L_*DFF_*D_],   g_1T_lo [L_*DFF_*D_];
__device__ __nv_bfloat16 g_2T_hi [L_*D_*DFF_],   g_2T_lo [L_*D_*DFF_];
__device__ __nv_bfloat16 g_cT_hi [128*D_],       g_cT_lo [128*D_];
__device__ float g_bqkv[L_ * QKV_N];

// =========================== PTX helpers ==================================
__device__ __forceinline__ uint32_t smem_u32(const void* p) {
    uint32_t r;
    asm("{ .reg .u64 t; cvta.to.shared.u64 t, %1; cvt.u32.u64 %0, t; }"
        : "=r"(r) : "l"(p));
    return r;
}
__device__ __forceinline__ void cp_async16(uint32_t dst, const void* src) {
    asm volatile("cp.async.cg.shared.global [%0], [%1], 16;"
                 :: "r"(dst), "l"(src));
}
__device__ __forceinline__ void cp_commit() {
    asm volatile("cp.async.commit_group;" ::: "memory");
}
__device__ __forceinline__ void cp_wait1() {
    asm volatile("cp.async.wait_group 1;" ::: "memory");
}
__device__ __forceinline__ void cp_wait0() {
    asm volatile("cp.async.wait_group 0;" ::: "memory");
}
__device__ __forceinline__ void ldsm_x4(uint32_t* r, uint32_t addr) {
    asm volatile("ldmatrix.sync.aligned.m8n8.x4.shared.b16 {%0,%1,%2,%3}, [%4];"
                 : "=r"(r[0]), "=r"(r[1]), "=r"(r[2]), "=r"(r[3]) : "r"(addr));
}
__device__ __forceinline__ void mma_bf16(float* d, const uint32_t* a,
                                         uint32_t b0, uint32_t b1) {
    asm volatile(
        "mma.sync.aligned.m16n8k16.row.col.f32.bf16.bf16.f32 "
        "{%0,%1,%2,%3}, {%4,%5,%6,%7}, {%8,%9}, {%0,%1,%2,%3};"
        : "+f"(d[0]), "+f"(d[1]), "+f"(d[2]), "+f"(d[3])
        : "r"(a[0]), "r"(a[1]), "r"(a[2]), "r"(a[3]), "r"(b0), "r"(b1));
}
__device__ __forceinline__ uint32_t swz128(uint32_t x) {
    return x ^ ((x >> 3) & 0x70u);
}
__device__ __forceinline__ uint32_t pack_bf2(__nv_bfloat16 a, __nv_bfloat16 b) {
    __nv_bfloat162 t(a, b);
    return *reinterpret_cast<uint32_t*>(&t);
}
__device__ __forceinline__ void split2(float a, float b, uint32_t& hi, uint32_t& lo) {
    __nv_bfloat16 h0 = __float2bfloat16(a);
    __nv_bfloat16 h1 = __float2bfloat16(b);
    __nv_bfloat16 l0 = __float2bfloat16(a - __bfloat162float(h0));
    __nv_bfloat16 l1 = __float2bfloat16(b - __bfloat162float(h1));
    hi = pack_bf2(h0, h1);
    lo = pack_bf2(l0, l1);
}

// ===================== GEMM tiling constants ==============================
#define GBM 128
#define GBN 64
#define GKB 64
#define APLANE 16384            // 128 rows x 128B
#define BPLANE 8192             // 64 rows x 128B
#define BUFB (2*APLANE + 2*BPLANE)  // 49152
#define GEMM_SMEM (2*BUFB + 1024)

// ============ weight transpose + bf16 hi/lo split:  W[K,N] -> WT[N,K] =====
__global__ void convert_w_kernel(const float* __restrict__ W,
                                 __nv_bfloat16* __restrict__ Hi,
                                 __nv_bfloat16* __restrict__ Lo,
                                 int K, int N, int Npad)
{
    __shared__ float t[32][33];
    const float* Wz = W + (size_t)blockIdx.z * K * N;
    __nv_bfloat16* Hz = Hi + (size_t)blockIdx.z * Npad * K;
    __nv_bfloat16* Lz = Lo + (size_t)blockIdx.z * Npad * K;
    int k0 = blockIdx.x * 32, n0 = blockIdx.y * 32;
    int tx = threadIdx.x, ty = threadIdx.y;
#pragma unroll
    for (int r = 0; r < 4; r++) {
        int k = k0 + ty + 8 * r;
        int n = n0 + tx;
        t[ty + 8 * r][tx] = (n < N) ? Wz[(size_t)k * N + n] : 0.0f;
    }
    __syncthreads();
#pragma unroll
    for (int r = 0; r < 4; r++) {
        int n = n0 + ty + 8 * r;
        int k = k0 + tx;
        float v = t[tx][ty + 8 * r];
        __nv_bfloat16 h = __float2bfloat16(v);
        __nv_bfloat16 l = __float2bfloat16(v - __bfloat162float(h));
        Hz[(size_t)n * K + k] = h;
        Lz[(size_t)n * K + k] = l;
    }
}

__global__ void pack_bias_kernel(const float* __restrict__ bq,
                                 const float* __restrict__ bk,
                                 const float* __restrict__ bv,
                                 float* __restrict__ o)
{
    int l = blockIdx.x, j = threadIdx.x;
    float v;
    if (j < 256)      v = bq[l * 256 + j];
    else if (j < 512) v = bk[l * 256 + j - 256];
    else              v = bv[l * 256 + j - 512];
    o[l * QKV_N + j] = v;
}

// ====================== HMMA bf16 split-precision GEMM ====================
// C[M,N] = A * B^T + bias.  A: [M,K] bf16 hi/lo planes. B: [Npad,K] planes.
// Output: float C, or bf16 hi/lo planes (for FF1), with optional ReLU.
__device__ __forceinline__ void gemm_fill(
    uint32_t smU, int b, int kb,
    const __nv_bfloat16* __restrict__ AHi, const __nv_bfloat16* __restrict__ ALo,
    const __nv_bfloat16* __restrict__ BHi, const __nv_bfloat16* __restrict__ BLo,
    int K, int bm, int bn, int tid)
{
    const int k0 = kb * GKB;
    uint32_t aHiU = smU + b * BUFB;
    uint32_t aLoU = aHiU + APLANE;
    uint32_t bHiU = aHiU + 2 * APLANE;
    uint32_t bLoU = bHiU + BPLANE;

#pragma unroll
    for (int i = 0; i < 4; i++) {
        int j   = tid + 256 * i;          // 0..1023
        int row = j >> 3;                 // 0..127
        int ch  = (j & 7) << 4;           // byte 0..112
        uint32_t off = swz128((uint32_t)(row * 128 + ch));
        size_t srcb = ((size_t)(bm + row) * K + k0) * 2 + ch;
        cp_async16(aHiU + off, (const char*)AHi + srcb);
        cp_async16(aLoU + off, (const char*)ALo + srcb);
    }
#pragma unroll
    for (int i = 0; i < 2; i++) {
        int j   = tid + 256 * i;          // 0..511
        int row = j >> 3;                 // 0..63
        int ch  = (j & 7) << 4;
        uint32_t off = swz128((uint32_t)(row * 128 + ch));
        size_t srcb = ((size_t)(bn + row) * K + k0) * 2 + ch;
        cp_async16(bHiU + off, (const char*)BHi + srcb);
        cp_async16(bLoU + off, (const char*)BLo + srcb);
    }
}

__device__ __forceinline__ void gemm_compute(
    uint32_t smU, int b, int m0, int n0, int lane, float (*acc)[4][4])
{
    const uint32_t aU = smU + b * BUFB;
    const uint32_t bU = aU + 2 * APLANE;

    const int a_row = m0 + (lane & 15);
    const int a_kb  = (lane >> 4) * 16;
    const int b_row = n0 + ((lane >> 4) << 3) + (lane & 7);
    const int b_kb  = ((lane >> 3) & 1) * 16;

#pragma unroll
    for (int ks = 0; ks < 4; ks++) {
        const int kbase = ks * 32;
        uint32_t ah[2][4], al[2][4], bh[2][4], bl[2][4];
#pragma unroll
        for (int mi = 0; mi < 2; mi++) {
            uint32_t off = swz128((uint32_t)((a_row + mi * 16) * 128 + kbase + a_kb));
            ldsm_x4(ah[mi], aU + off);
            ldsm_x4(al[mi], aU + APLANE + off);
        }
#pragma unroll
        for (int bi = 0; bi < 2; bi++) {
            uint32_t off = swz128((uint32_t)((b_row + bi * 16) * 128 + kbase + b_kb));
            ldsm_x4(bh[bi], bU + off);
            ldsm_x4(bl[bi], bU + BPLANE + off);
        }
#pragma unroll
        for (int mi = 0; mi < 2; mi++)
#pragma unroll
            for (int ni = 0; ni < 4; ni++) {
                uint32_t h0 = bh[ni >> 1][(ni & 1) * 2];
                uint32_t h1 = bh[ni >> 1][(ni & 1) * 2 + 1];
                uint32_t l0 = bl[ni >> 1][(ni & 1) * 2];
                uint32_t l1 = bl[ni >> 1][(ni & 1) * 2 + 1];
                mma_bf16(acc[mi][ni], ah[mi], h0, h1);
                mma_bf16(acc[mi][ni], ah[mi], l0, l1);
                mma_bf16(acc[mi][ni], al[mi], h0, h1);
            }
    }
}

__global__ __launch_bounds__(256)
void gemm_tc(const __nv_bfloat16* __restrict__ AHi,
             const __nv_bfloat16* __restrict__ ALo,
             const __nv_bfloat16* __restrict__ BHi,
             const __nv_bfloat16* __restrict__ BLo,
             const float* __restrict__ bias,
             float* __restrict__ C,
             __nv_bfloat16* __restrict__ CHi,
             __nv_bfloat16* __restrict__ CLo,
             int K, int N, int relu)
{
    extern __shared__ char dsm_raw[];
    const int tid  = threadIdx.x;
    const int lane = tid & 31;
    const int wid  = tid >> 5;
    const int m0   = (wid >> 1) * 32;
    const int n0   = (wid & 1) * 32;
    const int bm   = blockIdx.y * GBM;
    const int bn   = blockIdx.x * GBN;
    const int nk   = K / GKB;

    uint32_t rawU = smem_u32(dsm_raw);
    uint32_t smU  = (rawU + 1023u) & ~1023u;

    float acc[2][4][4];
#pragma unroll
    for (int mi = 0; mi < 2; mi++)
#pragma unroll
        for (int ni = 0; ni < 4; ni++)
#pragma unroll
            for (int e = 0; e < 4; e++) acc[mi][ni][e] = 0.0f;

    gemm_fill(smU, 0, 0, AHi, ALo, BHi, BLo, K, bm, bn, tid);
    cp_commit();

    for (int kb = 0; kb < nk; kb++) {
        const int b = kb & 1;
        if (kb + 1 < nk) {
            gemm_fill(smU, b ^ 1, kb + 1, AHi, ALo, BHi, BLo, K, bm, bn, tid);
            cp_commit();
            cp_wait1();
        } else {
            cp_wait0();
        }
        __syncthreads();
        gemm_compute(smU, b, m0, n0, lane, acc);
        __syncthreads();
    }

    // epilogue
    const int gr = lane >> 2;
    const int gc = (lane & 3) * 2;
#pragma unroll
    for (int mi = 0; mi < 2; mi++) {
        int r0 = bm + m0 + mi * 16 + gr;
#pragma unroll
        for (int ni = 0; ni < 4; ni++) {
            int c = bn + n0 + ni * 8 + gc;
            float v00 = acc[mi][ni][0] + bias[c];
            float v01 = acc[mi][ni][1] + bias[(c + 1 < N) ? c + 1 : c];
            float v10 = acc[mi][ni][2] + bias[c];
            float v11 = acc[mi][ni][3] + bias[(c + 1 < N) ? c + 1 : c];
            if (relu) {
                v00 = fmaxf(v00, 0.f); v01 = fmaxf(v01, 0.f);
                v10 = fmaxf(v10, 0.f); v11 = fmaxf(v11, 0.f);
            }
            if (CHi) {
                // split-plane output (N multiple of 64; always in-bounds)
                uint32_t h0, l0, h1, l1;
                split2(v00, v01, h0, l0);
                split2(v10, v11, h1, l1);
                *(uint32_t*)(CHi + (size_t)r0 * N + c) = h0;
                *(uint32_t*)(CLo + (size_t)r0 * N + c) = l0;
                *(uint32_t*)(CHi + (size_t)(r0 + 8) * N + c) = h1;
                *(uint32_t*)(CLo + (size_t)(r0 + 8) * N + c) = l1;
            } else if (c + 1 < N) {
                *(float2*)(C + (size_t)r0 * N + c) = make_float2(v00, v01);
                *(float2*)(C + (size_t)(r0 + 8) * N + c) = make_float2(v10, v11);
            } else if (c < N) {
                C[(size_t)r0 * N + c] = v00;
                C[(size_t)(r0 + 8) * N + c] = v10;
            }
        }
    }
}

// ============ embedding + positions; also emits bf16 hi/lo planes =========
__global__ void embed_kernel(const int* __restrict__ ids,
                             const float* __restrict__ emb,
                             float* __restrict__ X,
                             __nv_bfloat16* __restrict__ XH,
                             __nv_bfloat16* __restrict__ XL)
{
    int t = blockIdx.x;
    int d = threadIdx.x;
    int s = t & (S_ - 1);
    int id = ids[t];
    float f = (d < D_ / 2) ? (2.0f * d) : (2.0f * (d - D_ / 2) + 1.0f);
    float inv = exp2f(-f * 13.287712379549449f / (float)D_);
    float v = emb[(size_t)id * D_ + d] + sinf((float)s * inv);
    size_t idx = (size_t)t * D_ + d;
    X[idx] = v;
    __nv_bfloat16 h = __float2bfloat16(v);
    XH[idx] = h;
    XL[idx] = __float2bfloat16(v - __bfloat162float(h));
}

// ===================== causal flash-style attention =======================
// Writes output as bf16 hi/lo planes (consumed by the O-projection GEMM).
__global__ __launch_bounds__(128)
void attn_kernel(const float* __restrict__ QKV,
                 __nv_bfloat16* __restrict__ YH, __nv_bfloat16* __restrict__ YL,
                 const int* __restrict__ tsl)
{
    __shared__ float Ks[64][32];
    __shared__ float Vs[64][32];

    int tid = threadIdx.x;
    int b = blockIdx.z, h = blockIdx.y;
    int q = blockIdx.x * 128 + tid;
    int len = tsl[b];

    float4 qv[8];
    {
        const float* qp = QKV + (size_t)(b * S_ + q) * QKV_N + h * DH_;
        float sc = rsqrtf((float)DH_);
#pragma unroll
        for (int i = 0; i < 8; i++) {
            qv[i] = *(const float4*)(qp + 4 * i);
            qv[i].x *= sc; qv[i].y *= sc; qv[i].z *= sc; qv[i].w *= sc;
        }
    }

    float m = -1e30f, l = 0.0f;
    float y[32];
#pragma unroll
    for (int d = 0; d < 32; d++) y[d] = 0.0f;

    int qmax = blockIdx.x * 128 + 127;
    for (int kt = 0; kt <= qmax; kt += 64) {
#pragma unroll
        for (int i = 0; i < 4; i++) {
            int j = tid + 128 * i;
            int row = j >> 3;
            int c = (j & 7) * 4;
            size_t g = (size_t)(b * S_ + kt + row) * QKV_N + h * DH_ + c;
            *(float4*)(&Ks[row][c]) = *(const float4*)(QKV + g + 256);
            *(float4*)(&Vs[row][c]) = *(const float4*)(QKV + g + 512);
        }
        __syncthreads();

#pragma unroll 1
        for (int c0 = 0; c0 < 64; c0 += 16) {
            float s[16];
            float tmax = -1e30f;
#pragma unroll
            for (int i = 0; i < 16; i++) {
                int kk = c0 + i;
                int kg = kt + kk;
                const float4* kp = (const float4*)(&Ks[kk][0]);
                float acc = 0.0f;
#pragma unroll
                for (int t = 0; t < 8; t++) {
                    float4 kv = kp[t];
                    acc += qv[t].x * kv.x + qv[t].y * kv.y
                         + qv[t].z * kv.z + qv[t].w * kv.w;
                }
                bool valid = (kg <= q) && (kg < len) && (q < len);
                s[i] = valid ? acc : -1e30f;
                tmax = fmaxf(tmax, s[i]);
            }
            if (tmax > -1e29f) {
                float mnew = fmaxf(m, tmax);
                float corr = __expf(m - mnew);
                m = mnew;
                l *= corr;
#pragma unroll
                for (int d = 0; d < 32; d++) y[d] *= corr;
#pragma unroll
                for (int i = 0; i < 16; i++) {
                    float p = __expf(s[i] - m);
                    l += p;
                    const float4* vp = (const float4*)(&Vs[c0 + i][0]);
#pragma unroll
                    for (int t = 0; t < 8; t++) {
                        float4 vv = vp[t];
                        y[4 * t + 0] += p * vv.x;
                        y[4 * t + 1] += p * vv.y;
                        y[4 * t + 2] += p * vv.z;
                        y[4 * t + 3] += p * vv.w;
                    }
                }
            }
        }
        __syncthreads();
    }

    float inv = (l > 0.0f) ? (1.0f / l) : 0.0f;
    size_t base = (size_t)(b * S_ + q) * D_ + h * DH_;
#pragma unroll
    for (int d = 0; d < 32; d += 2) {
        uint32_t hp, lp;
        split2(y[d] * inv, y[d + 1] * inv, hp, lp);
        *(uint32_t*)(YH + base + d) = hp;
        *(uint32_t*)(YL + base + d) = lp;
    }
}

// ==== residual add + LayerNorm (in place) + bf16 hi/lo plane output =======
__global__ __launch_bounds__(256)
void add_ln_kernel(float* X, const float* __restrict__ Yb,
                   const float* __restrict__ g, const float* __restrict__ be,
                   __nv_bfloat16* __restrict__ XH, __nv_bfloat16* __restrict__ XL)
{
    int row = blockIdx.x;
    int d = threadIdx.x;
    size_t idx = (size_t)row * D_ + d;
    float h = X[idx] + Yb[idx];

    float s = h, s2 = h * h;
#pragma unroll
    for (int o = 16; o; o >>= 1) {
        s  += __shfl_xor_sync(0xFFFFFFFFu, s,  o);
        s2 += __shfl_xor_sync(0xFFFFFFFFu, s2, o);
    }
    __shared__ float ws[8], ws2[8];
    int w = d >> 5;
    if ((d & 31) == 0) { ws[w] = s; ws2[w] = s2; }
    __syncthreads();
    float tot = 0.f, tot2 = 0.f;
#pragma unroll
    for (int i = 0; i < 8; i++) { tot += ws[i]; tot2 += ws2[i]; }

    float mean = tot * (1.0f / D_);
    float var  = tot2 * (1.0f / D_) - mean * mean;
    float r = rsqrtf(var + 1e-5f);
    float v = (h - mean) * r * g[d] + be[d];
    X[idx] = v;
    __nv_bfloat16 hb = __float2bfloat16(v);
    XH[idx] = hb;
    XL[idx] = __float2bfloat16(v - __bfloat162float(hb));
}

// =========================== launcher ====================================
extern "C" void kernel_launch(void* const* d_in, const int* in_sizes, int n_in,
                              void* d_out, int out_size)
{
    const int*   ids = (const int*)  d_in[0];
    const int*   tsl = (const int*)  d_in[1];
    const float* emb = (const float*)d_in[2];
    const float* Wq  = (const float*)d_in[3];
    const float* bq  = (const float*)d_in[4];
    const float* Wk  = (const float*)d_in[5];
    const float* bk  = (const float*)d_in[6];
    const float* Wv  = (const float*)d_in[7];
    const float* bv  = (const float*)d_in[8];
    const float* Wo  = (const float*)d_in[9];
    const float* bo  = (const float*)d_in[10];
    const float* W1  = (const float*)d_in[11];
    const float* b1  = (const float*)d_in[12];
    const float* W2  = (const float*)d_in[13];
    const float* b2  = (const float*)d_in[14];
    const float* g1  = (const float*)d_in[15];
    const float* be1 = (const float*)d_in[16];
    const float* g2  = (const float*)d_in[17];
    const float* be2 = (const float*)d_in[18];
    const float* Wc  = (const float*)d_in[19];
    const float* bc  = (const float*)d_in[20];
    float* out = (float*)d_out;

    float *x, *qkv, *t, *bqkv;
    cudaGetSymbolAddress((void**)&x,   g_x);
    cudaGetSymbolAddress((void**)&qkv, g_qkv);
    cudaGetSymbolAddress((void**)&t,   g_t);
    cudaGetSymbolAddress((void**)&bqkv, g_bqkv);

    __nv_bfloat16 *xh, *xl, *yh, *yl, *ffh, *ffl;
    cudaGetSymbolAddress((void**)&xh,  g_xh);  cudaGetSymbolAddress((void**)&xl,  g_xl);
    cudaGetSymbolAddress((void**)&yh,  g_yh);  cudaGetSymbolAddress((void**)&yl,  g_yl);
    cudaGetSymbolAddress((void**)&ffh, g_ffh); cudaGetSymbolAddress((void**)&ffl, g_ffl);

    __nv_bfloat16 *qkvTh, *qkvTl, *oTh, *oTl, *w1h, *w1l, *w2h, *w2l, *wch, *wcl;
    cudaGetSymbolAddress((void**)&qkvTh, g_qkvT_hi); cudaGetSymbolAddress((void**)&qkvTl, g_qkvT_lo);
    cudaGetSymbolAddress((void**)&oTh,  g_oT_hi);    cudaGetSymbolAddress((void**)&oTl,  g_oT_lo);
    cudaGetSymbolAddress((void**)&w1h,  g_1T_hi);    cudaGetSymbolAddress((void**)&w1l,  g_1T_lo);
    cudaGetSymbolAddress((void**)&w2h,  g_2T_hi);    cudaGetSymbolAddress((void**)&w2l,  g_2T_lo);
    cudaGetSymbolAddress((void**)&wch,  g_cT_hi);    cudaGetSymbolAddress((void**)&wcl,  g_cT_lo);

    cudaFuncSetAttribute((const void*)gemm_tc,
                         cudaFuncAttributeMaxDynamicSharedMemorySize, GEMM_SMEM);

    dim3 tb(32, 8);
    convert_w_kernel<<<dim3(8, 8, L_),  tb>>>(Wq, qkvTh,            qkvTl,            256, 256, QKV_N);
    convert_w_kernel<<<dim3(8, 8, L_),  tb>>>(Wk, qkvTh + 256 * D_, qkvTl + 256 * D_, 256, 256, QKV_N);
    convert_w_kernel<<<dim3(8, 8, L_),  tb>>>(Wv, qkvTh + 512 * D_, qkvTl + 512 * D_, 256, 256, QKV_N);
    convert_w_kernel<<<dim3(8, 8, L_),  tb>>>(Wo, oTh, oTl, 256, 256, 256);
    convert_w_kernel<<<dim3(8, 32, L_), tb>>>(W1, w1h, w1l, 256, 1024, 1024);
    convert_w_kernel<<<dim3(32, 8, L_), tb>>>(W2, w2h, w2l, 1024, 256, 256);
    convert_w_kernel<<<dim3(8, 4, 1),   tb>>>(Wc, wch, wcl, 256, 100, 128);
    pack_bias_kernel<<<L_, QKV_N>>>(bq, bk, bv, bqkv);

    embed_kernel<<<M_TOK, D_>>>(ids, emb, x, xh, xl);

    dim3 gQKV(QKV_N / GBN, M_TOK / GBM);  // 12 x 64
    dim3 gD  (D_ / GBN,    M_TOK / GBM);  // 4 x 64
    dim3 gF  (DFF_ / GBN,  M_TOK / GBM);  // 16 x 64
    dim3 gC  (2,           M_TOK / GBM);  // 100 -> 2 tiles

    for (int l = 0; l < L_; l++) {
        size_t qoff  = (size_t)l * QKV_N * D_;
        size_t ooff  = (size_t)l * D_ * D_;
        size_t w1off = (size_t)l * DFF_ * D_;

        gemm_tc<<<gQKV, 256, GEMM_SMEM>>>(xh, xl, qkvTh + qoff, qkvTl + qoff,
                                          bqkv + l * QKV_N, qkv, 0, 0, D_, QKV_N, 0);
        attn_kernel<<<dim3(S_ / 128, H_, B_), 128>>>(qkv, yh, yl, tsl);

        gemm_tc<<<gD, 256, GEMM_SMEM>>>(yh, yl, oTh + ooff, oTl + ooff,
                                        bo + l * D_, t, 0, 0, D_, D_, 0);
        add_ln_kernel<<<M_TOK, D_>>>(x, t, g1 + l * D_, be1 + l * D_, xh, xl);

        gemm_tc<<<gF, 256, GEMM_SMEM>>>(xh, xl, w1h + w1off, w1l + w1off,
                                        b1 + l * DFF_, 0, ffh, ffl, D_, DFF_, 1);
        gemm_tc<<<gD, 256, GEMM_SMEM>>>(ffh, ffl, w2h + w1off, w2l + w1off,
                                        b2 + l * D_, t, 0, 0, DFF_, D_, 0);
        add_ln_kernel<<<M_TOK, D_>>>(x, t, g2 + l * D_, be2 + l * D_, xh, xl);
    }

    gemm_tc<<<gC, 256, GEMM_SMEM>>>(xh, xl, wch, wcl, bc, out, 0, 0, D_, V_, 0);
}

// round 5
// speedup vs baseline: 3.0511x; 2.0623x over previous
#include <cuda_runtime.h>
#include <cuda_bf16.h>
#include <math.h>
#include <stdint.h>

// Problem constants
#define B_  8
#define S_  1024
#define D_  256
#define H_  8
#define DH_ 32
#define L_  4
#define V_  100
#define DFF_ 1024
#define M_TOK (B_ * S_)   // 8192
#define QKV_N 768

// -------- scratch (static device globals; no runtime allocation) --------
__device__ float g_x [M_TOK * D_];
__device__ float g_t [M_TOK * D_];

// activation bf16 hi/lo planes ([M,K] row-major)
__device__ __nv_bfloat16 g_xh  [M_TOK * D_],    g_xl  [M_TOK * D_];
__device__ __nv_bfloat16 g_yh  [M_TOK * D_],    g_yl  [M_TOK * D_];
__device__ __nv_bfloat16 g_ffh [M_TOK * DFF_],  g_ffl [M_TOK * DFF_];
__device__ __nv_bfloat16 g_qkvh[M_TOK * QKV_N], g_qkvl[M_TOK * QKV_N];

// K-major ([N,K]) bf16 hi/lo weight planes
__device__ __nv_bfloat16 g_qkvT_hi[L_*QKV_N*D_], g_qkvT_lo[L_*QKV_N*D_];
__device__ __nv_bfloat16 g_oT_hi [L_*D_*D_],     g_oT_lo [L_*D_*D_];
__device__ __nv_bfloat16 g_1T_hi [L_*DFF_*D_],   g_1T_lo [L_*DFF_*D_];
__device__ __nv_bfloat16 g_2T_hi [L_*D_*DFF_],   g_2T_lo [L_*D_*DFF_];
__device__ __nv_bfloat16 g_cT_hi [128*D_],       g_cT_lo [128*D_];
__device__ float g_bqkv[L_ * QKV_N];

// =========================== PTX helpers ==================================
__device__ __forceinline__ uint32_t smem_u32(const void* p) {
    uint32_t r;
    asm("{ .reg .u64 t; cvta.to.shared.u64 t, %1; cvt.u32.u64 %0, t; }"
        : "=r"(r) : "l"(p));
    return r;
}
__device__ __forceinline__ void cp_async16(uint32_t dst, const void* src) {
    asm volatile("cp.async.cg.shared.global [%0], [%1], 16;"
                 :: "r"(dst), "l"(src));
}
__device__ __forceinline__ void cp_commit() {
    asm volatile("cp.async.commit_group;" ::: "memory");
}
__device__ __forceinline__ void cp_wait1() {
    asm volatile("cp.async.wait_group 1;" ::: "memory");
}
__device__ __forceinline__ void cp_wait0() {
    asm volatile("cp.async.wait_group 0;" ::: "memory");
}
__device__ __forceinline__ void ldsm_x4(uint32_t* r, uint32_t addr) {
    asm volatile("ldmatrix.sync.aligned.m8n8.x4.shared.b16 {%0,%1,%2,%3}, [%4];"
                 : "=r"(r[0]), "=r"(r[1]), "=r"(r[2]), "=r"(r[3]) : "r"(addr));
}
__device__ __forceinline__ void ldsm_x2(uint32_t* r, uint32_t addr) {
    asm volatile("ldmatrix.sync.aligned.m8n8.x2.shared.b16 {%0,%1}, [%2];"
                 : "=r"(r[0]), "=r"(r[1]) : "r"(addr));
}
__device__ __forceinline__ void ldsm_x2t(uint32_t* r, uint32_t addr) {
    asm volatile("ldmatrix.sync.aligned.m8n8.x2.trans.shared.b16 {%0,%1}, [%2];"
                 : "=r"(r[0]), "=r"(r[1]) : "r"(addr));
}
__device__ __forceinline__ void mma_bf16(float* d, const uint32_t* a,
                                         uint32_t b0, uint32_t b1) {
    asm volatile(
        "mma.sync.aligned.m16n8k16.row.col.f32.bf16.bf16.f32 "
        "{%0,%1,%2,%3}, {%4,%5,%6,%7}, {%8,%9}, {%0,%1,%2,%3};"
        : "+f"(d[0]), "+f"(d[1]), "+f"(d[2]), "+f"(d[3])
        : "r"(a[0]), "r"(a[1]), "r"(a[2]), "r"(a[3]), "r"(b0), "r"(b1));
}
__device__ __forceinline__ uint32_t swz128(uint32_t x) {
    return x ^ ((x >> 3) & 0x70u);
}
__device__ __forceinline__ uint32_t pack_bf2(__nv_bfloat16 a, __nv_bfloat16 b) {
    __nv_bfloat162 t(a, b);
    return *reinterpret_cast<uint32_t*>(&t);
}
__device__ __forceinline__ void split2(float a, float b, uint32_t& hi, uint32_t& lo) {
    __nv_bfloat16 h0 = __float2bfloat16(a);
    __nv_bfloat16 h1 = __float2bfloat16(b);
    __nv_bfloat16 l0 = __float2bfloat16(a - __bfloat162float(h0));
    __nv_bfloat16 l1 = __float2bfloat16(b - __bfloat162float(h1));
    hi = pack_bf2(h0, h1);
    lo = pack_bf2(l0, l1);
}

// ===================== GEMM tiling constants ==============================
#define GBM 128
#define GBN 64
#define GKB 64
#define APLANE 16384
#define BPLANE 8192
#define BUFB (2*APLANE + 2*BPLANE)
#define GEMM_SMEM (2*BUFB + 1024)

// ============ weight transpose + bf16 hi/lo split:  W[K,N] -> WT[N,K] =====
__global__ void convert_w_kernel(const float* __restrict__ W,
                                 __nv_bfloat16* __restrict__ Hi,
                                 __nv_bfloat16* __restrict__ Lo,
                                 int K, int N, int Npad)
{
    __shared__ float t[32][33];
    const float* Wz = W + (size_t)blockIdx.z * K * N;
    __nv_bfloat16* Hz = Hi + (size_t)blockIdx.z * Npad * K;
    __nv_bfloat16* Lz = Lo + (size_t)blockIdx.z * Npad * K;
    int k0 = blockIdx.x * 32, n0 = blockIdx.y * 32;
    int tx = threadIdx.x, ty = threadIdx.y;
#pragma unroll
    for (int r = 0; r < 4; r++) {
        int k = k0 + ty + 8 * r;
        int n = n0 + tx;
        t[ty + 8 * r][tx] = (n < N) ? Wz[(size_t)k * N + n] : 0.0f;
    }
    __syncthreads();
#pragma unroll
    for (int r = 0; r < 4; r++) {
        int n = n0 + ty + 8 * r;
        int k = k0 + tx;
        float v = t[tx][ty + 8 * r];
        __nv_bfloat16 h = __float2bfloat16(v);
        __nv_bfloat16 l = __float2bfloat16(v - __bfloat162float(h));
        Hz[(size_t)n * K + k] = h;
        Lz[(size_t)n * K + k] = l;
    }
}

__global__ void pack_bias_kernel(const float* __restrict__ bq,
                                 const float* __restrict__ bk,
                                 const float* __restrict__ bv,
                                 float* __restrict__ o)
{
    int l = blockIdx.x, j = threadIdx.x;
    float v;
    if (j < 256)      v = bq[l * 256 + j];
    else if (j < 512) v = bk[l * 256 + j - 256];
    else              v = bv[l * 256 + j - 512];
    o[l * QKV_N + j] = v;
}

// ====================== HMMA bf16 split-precision GEMM ====================
__device__ __forceinline__ void gemm_fill(
    uint32_t smU, int b, int kb,
    const __nv_bfloat16* __restrict__ AHi, const __nv_bfloat16* __restrict__ ALo,
    const __nv_bfloat16* __restrict__ BHi, const __nv_bfloat16* __restrict__ BLo,
    int K, int bm, int bn, int tid)
{
    const int k0 = kb * GKB;
    uint32_t aHiU = smU + b * BUFB;
    uint32_t aLoU = aHiU + APLANE;
    uint32_t bHiU = aHiU + 2 * APLANE;
    uint32_t bLoU = bHiU + BPLANE;

#pragma unroll
    for (int i = 0; i < 4; i++) {
        int j   = tid + 256 * i;
        int row = j >> 3;
        int ch  = (j & 7) << 4;
        uint32_t off = swz128((uint32_t)(row * 128 + ch));
        size_t srcb = ((size_t)(bm + row) * K + k0) * 2 + ch;
        cp_async16(aHiU + off, (const char*)AHi + srcb);
        cp_async16(aLoU + off, (const char*)ALo + srcb);
    }
#pragma unroll
    for (int i = 0; i < 2; i++) {
        int j   = tid + 256 * i;
        int row = j >> 3;
        int ch  = (j & 7) << 4;
        uint32_t off = swz128((uint32_t)(row * 128 + ch));
        size_t srcb = ((size_t)(bn + row) * K + k0) * 2 + ch;
        cp_async16(bHiU + off, (const char*)BHi + srcb);
        cp_async16(bLoU + off, (const char*)BLo + srcb);
    }
}

__device__ __forceinline__ void gemm_compute(
    uint32_t smU, int b, int m0, int n0, int lane, float (*acc)[4][4])
{
    const uint32_t aU = smU + b * BUFB;
    const uint32_t bU = aU + 2 * APLANE;

    const int a_row = m0 + (lane & 15);
    const int a_kb  = (lane >> 4) * 16;
    const int b_row = n0 + ((lane >> 4) << 3) + (lane & 7);
    const int b_kb  = ((lane >> 3) & 1) * 16;

#pragma unroll
    for (int ks = 0; ks < 4; ks++) {
        const int kbase = ks * 32;
        uint32_t ah[2][4], al[2][4], bh[2][4], bl[2][4];
#pragma unroll
        for (int mi = 0; mi < 2; mi++) {
            uint32_t off = swz128((uint32_t)((a_row + mi * 16) * 128 + kbase + a_kb));
            ldsm_x4(ah[mi], aU + off);
            ldsm_x4(al[mi], aU + APLANE + off);
        }
#pragma unroll
        for (int bi = 0; bi < 2; bi++) {
            uint32_t off = swz128((uint32_t)((b_row + bi * 16) * 128 + kbase + b_kb));
            ldsm_x4(bh[bi], bU + off);
            ldsm_x4(bl[bi], bU + BPLANE + off);
        }
#pragma unroll
        for (int mi = 0; mi < 2; mi++)
#pragma unroll
            for (int ni = 0; ni < 4; ni++) {
                uint32_t h0 = bh[ni >> 1][(ni & 1) * 2];
                uint32_t h1 = bh[ni >> 1][(ni & 1) * 2 + 1];
                uint32_t l0 = bl[ni >> 1][(ni & 1) * 2];
                uint32_t l1 = bl[ni >> 1][(ni & 1) * 2 + 1];
                mma_bf16(acc[mi][ni], ah[mi], h0, h1);
                mma_bf16(acc[mi][ni], ah[mi], l0, l1);
                mma_bf16(acc[mi][ni], al[mi], h0, h1);
            }
    }
}

__global__ __launch_bounds__(256)
void gemm_tc(const __nv_bfloat16* __restrict__ AHi,
             const __nv_bfloat16* __restrict__ ALo,
             const __nv_bfloat16* __restrict__ BHi,
             const __nv_bfloat16* __restrict__ BLo,
             const float* __restrict__ bias,
             float* __restrict__ C,
             __nv_bfloat16* __restrict__ CHi,
             __nv_bfloat16* __restrict__ CLo,
             int K, int N, int relu)
{
    extern __shared__ char dsm_raw[];
    const int tid  = threadIdx.x;
    const int lane = tid & 31;
    const int wid  = tid >> 5;
    const int m0   = (wid >> 1) * 32;
    const int n0   = (wid & 1) * 32;
    const int bm   = blockIdx.y * GBM;
    const int bn   = blockIdx.x * GBN;
    const int nk   = K / GKB;

    uint32_t rawU = smem_u32(dsm_raw);
    uint32_t smU  = (rawU + 1023u) & ~1023u;

    float acc[2][4][4];
#pragma unroll
    for (int mi = 0; mi < 2; mi++)
#pragma unroll
        for (int ni = 0; ni < 4; ni++)
#pragma unroll
            for (int e = 0; e < 4; e++) acc[mi][ni][e] = 0.0f;

    gemm_fill(smU, 0, 0, AHi, ALo, BHi, BLo, K, bm, bn, tid);
    cp_commit();

    for (int kb = 0; kb < nk; kb++) {
        const int b = kb & 1;
        if (kb + 1 < nk) {
            gemm_fill(smU, b ^ 1, kb + 1, AHi, ALo, BHi, BLo, K, bm, bn, tid);
            cp_commit();
            cp_wait1();
        } else {
            cp_wait0();
        }
        __syncthreads();
        gemm_compute(smU, b, m0, n0, lane, acc);
        __syncthreads();
    }

    const int gr = lane >> 2;
    const int gc = (lane & 3) * 2;
#pragma unroll
    for (int mi = 0; mi < 2; mi++) {
        int r0 = bm + m0 + mi * 16 + gr;
#pragma unroll
        for (int ni = 0; ni < 4; ni++) {
            int c = bn + n0 + ni * 8 + gc;
            float v00 = acc[mi][ni][0] + bias[c];
            float v01 = acc[mi][ni][1] + bias[(c + 1 < N) ? c + 1 : c];
            float v10 = acc[mi][ni][2] + bias[c];
            float v11 = acc[mi][ni][3] + bias[(c + 1 < N) ? c + 1 : c];
            if (relu) {
                v00 = fmaxf(v00, 0.f); v01 = fmaxf(v01, 0.f);
                v10 = fmaxf(v10, 0.f); v11 = fmaxf(v11, 0.f);
            }
            if (CHi) {
                uint32_t h0, l0, h1, l1;
                split2(v00, v01, h0, l0);
                split2(v10, v11, h1, l1);
                *(uint32_t*)(CHi + (size_t)r0 * N + c) = h0;
                *(uint32_t*)(CLo + (size_t)r0 * N + c) = l0;
                *(uint32_t*)(CHi + (size_t)(r0 + 8) * N + c) = h1;
                *(uint32_t*)(CLo + (size_t)(r0 + 8) * N + c) = l1;
            } else if (c + 1 < N) {
                *(float2*)(C + (size_t)r0 * N + c) = make_float2(v00, v01);
                *(float2*)(C + (size_t)(r0 + 8) * N + c) = make_float2(v10, v11);
            } else if (c < N) {
                C[(size_t)r0 * N + c] = v00;
                C[(size_t)(r0 + 8) * N + c] = v10;
            }
        }
    }
}

// ============ embedding + positions; also emits bf16 hi/lo planes =========
__global__ void embed_kernel(const int* __restrict__ ids,
                             const float* __restrict__ emb,
                             float* __restrict__ X,
                             __nv_bfloat16* __restrict__ XH,
                             __nv_bfloat16* __restrict__ XL)
{
    int t = blockIdx.x;
    int d = threadIdx.x;
    int s = t & (S_ - 1);
    int id = ids[t];
    float f = (d < D_ / 2) ? (2.0f * d) : (2.0f * (d - D_ / 2) + 1.0f);
    float inv = exp2f(-f * 13.287712379549449f / (float)D_);
    float v = emb[(size_t)id * D_ + d] + sinf((float)s * inv);
    size_t idx = (size_t)t * D_ + d;
    X[idx] = v;
    __nv_bfloat16 h = __float2bfloat16(v);
    XH[idx] = h;
    XL[idx] = __float2bfloat16(v - __bfloat162float(h));
}

// ================= tensor-core causal flash attention ====================
// Q/K/V from qkv bf16 hi/lo planes [M,768]; output y hi/lo planes [M,256].
#define AT_PITCH 80
#define AT_QH 0
#define AT_QL 10240
#define AT_KV 20480
#define AT_BUF 20480
#define AT_SMEM 61440
#define SCL2E 0.2550348243f   // log2(e)/sqrt(32)

__device__ __forceinline__ void attn_fill_kv(
    uint32_t smU, int buf,
    const __nv_bfloat16* __restrict__ Ph, const __nv_bfloat16* __restrict__ Pl,
    size_t rowbase, int kt, int h, int tid)
{
    uint32_t base = smU + AT_KV + buf * AT_BUF;
#pragma unroll
    for (int i = 0; i < 2; i++) {
        int j = tid + 128 * i;
        int row = j >> 2, ch = (j & 3) * 16;
        size_t gk = ((rowbase + kt + row) * QKV_N + 256 + h * DH_) * 2 + ch;
        size_t gv = gk + 512;   // (+256 cols)*2 bytes
        uint32_t d = row * AT_PITCH + ch;
        cp_async16(base + d,         (const char*)Ph + gk);
        cp_async16(base + 5120 + d,  (const char*)Pl + gk);
        cp_async16(base + 10240 + d, (const char*)Ph + gv);
        cp_async16(base + 15360 + d, (const char*)Pl + gv);
    }
}

__global__ __launch_bounds__(128)
void attn_tc(const __nv_bfloat16* __restrict__ Ph,
             const __nv_bfloat16* __restrict__ Pl,
             __nv_bfloat16* __restrict__ YH, __nv_bfloat16* __restrict__ YL,
             const int* __restrict__ tsl)
{
    extern __shared__ char asmem[];
    const int tid = threadIdx.x, lane = tid & 31, w = tid >> 5;
    const int qblk = blockIdx.x, h = blockIdx.y, b = blockIdx.z;
    const int q0 = qblk * 128;
    const int len = tsl[b];
    const int gr = lane >> 2, tg = lane & 3;
    const uint32_t smU = smem_u32(asmem);
    const size_t rowbase = (size_t)b * S_;

    // stage Q hi/lo
#pragma unroll
    for (int i = 0; i < 4; i++) {
        int j = tid + 128 * i;
        int row = j >> 2, ch = (j & 3) * 16;
        size_t src = ((rowbase + q0 + row) * QKV_N + h * DH_) * 2 + ch;
        cp_async16(smU + AT_QH + row * AT_PITCH + ch, (const char*)Ph + src);
        cp_async16(smU + AT_QL + row * AT_PITCH + ch, (const char*)Pl + src);
    }
    attn_fill_kv(smU, 0, Ph, Pl, rowbase, 0, h, tid);
    cp_commit();
    cp_wait0();
    __syncthreads();

    // Q fragments (held in registers for whole kernel)
    uint32_t qfh[2][2][4], qfl[2][2][4];
    {
        int r8 = (lane & 7) + ((lane >> 3) & 1) * 8;
        int cb = ((lane >> 4) & 1) * 16;
#pragma unroll
        for (int mi = 0; mi < 2; mi++)
#pragma unroll
            for (int kk = 0; kk < 2; kk++) {
                uint32_t off = (uint32_t)(w * 32 + mi * 16 + r8) * AT_PITCH + kk * 32 + cb;
                ldsm_x4(qfh[mi][kk], smU + AT_QH + off);
                ldsm_x4(qfl[mi][kk], smU + AT_QL + off);
            }
    }

    float o[2][4][4];
    float mrow[2][2], lrow[2][2];
#pragma unroll
    for (int mi = 0; mi < 2; mi++) {
#pragma unroll
        for (int nd = 0; nd < 4; nd++)
#pragma unroll
            for (int e = 0; e < 4; e++) o[mi][nd][e] = 0.f;
        mrow[mi][0] = mrow[mi][1] = -1e30f;
        lrow[mi][0] = lrow[mi][1] = 0.f;
    }

    const int qw0 = q0 + w * 32;
    const int qwmax = qw0 + 31;
    const int nt = (q0 + 128) / 64;

    for (int t = 0; t < nt; t++) {
        const int kt = t * 64;
        if (t + 1 < nt) {
            attn_fill_kv(smU, (t + 1) & 1, Ph, Pl, rowbase, kt + 64, h, tid);
            cp_commit();
            cp_wait1();
        } else {
            cp_wait0();
        }
        __syncthreads();

        if (kt <= qwmax) {
            const uint32_t kb = smU + AT_KV + (t & 1) * AT_BUF;
            const uint32_t vb = kb + 10240;

            // ---- scores: S = Qh*Kh + Qh*Kl + Ql*Kh ----
            float s[2][8][4];
#pragma unroll
            for (int mi = 0; mi < 2; mi++)
#pragma unroll
                for (int ni = 0; ni < 8; ni++)
#pragma unroll
                    for (int e = 0; e < 4; e++) s[mi][ni][e] = 0.f;
            {
                int l7 = lane & 7;
                int hb = ((lane >> 3) & 1) * 16;
#pragma unroll
                for (int kk = 0; kk < 2; kk++)
#pragma unroll
                    for (int ni = 0; ni < 8; ni++) {
                        uint32_t off = (uint32_t)(ni * 8 + l7) * AT_PITCH + kk * 32 + hb;
                        uint32_t khf[2], klf[2];
                        ldsm_x2(khf, kb + off);
                        ldsm_x2(klf, kb + 5120 + off);
#pragma unroll
                        for (int mi = 0; mi < 2; mi++) {
                            mma_bf16(s[mi][ni], qfh[mi][kk], khf[0], khf[1]);
                            mma_bf16(s[mi][ni], qfh[mi][kk], klf[0], klf[1]);
                            mma_bf16(s[mi][ni], qfl[mi][kk], khf[0], khf[1]);
                        }
                    }
            }

            // ---- causal/length mask ----
            if (kt + 63 > qw0 || kt + 64 > len) {
#pragma unroll
                for (int mi = 0; mi < 2; mi++) {
                    int r0 = qw0 + mi * 16 + gr, r1 = r0 + 8;
#pragma unroll
                    for (int ni = 0; ni < 8; ni++) {
                        int c0 = kt + ni * 8 + tg * 2, c1 = c0 + 1;
                        if (c0 > r0 || c0 >= len) s[mi][ni][0] = -1e30f;
                        if (c1 > r0 || c1 >= len) s[mi][ni][1] = -1e30f;
                        if (c0 > r1 || c0 >= len) s[mi][ni][2] = -1e30f;
                        if (c1 > r1 || c1 >= len) s[mi][ni][3] = -1e30f;
                    }
                }
            }

            // ---- row max (quad-shuffle reduce) ----
            float mx[2][2] = {{-1e30f, -1e30f}, {-1e30f, -1e30f}};
#pragma unroll
            for (int mi = 0; mi < 2; mi++)
#pragma unroll
                for (int ni = 0; ni < 8; ni++) {
                    mx[mi][0] = fmaxf(mx[mi][0], fmaxf(s[mi][ni][0], s[mi][ni][1]));
                    mx[mi][1] = fmaxf(mx[mi][1], fmaxf(s[mi][ni][2], s[mi][ni][3]));
                }
#pragma unroll
            for (int mi = 0; mi < 2; mi++)
#pragma unroll
                for (int hh = 0; hh < 2; hh++) {
                    float v = mx[mi][hh];
                    v = fmaxf(v, __shfl_xor_sync(0xFFFFFFFFu, v, 1));
                    v = fmaxf(v, __shfl_xor_sync(0xFFFFFFFFu, v, 2));
                    mx[mi][hh] = v;
                }

            // ---- online softmax update ----
            float corr[2][2];
#pragma unroll
            for (int mi = 0; mi < 2; mi++)
#pragma unroll
                for (int hh = 0; hh < 2; hh++) {
                    float mn = fmaxf(mrow[mi][hh], mx[mi][hh]);
                    corr[mi][hh] = exp2f((mrow[mi][hh] - mn) * SCL2E);
                    mrow[mi][hh] = mn;
                    lrow[mi][hh] *= corr[mi][hh];
                }
#pragma unroll
            for (int mi = 0; mi < 2; mi++)
#pragma unroll
                for (int nd = 0; nd < 4; nd++) {
                    o[mi][nd][0] *= corr[mi][0];
                    o[mi][nd][1] *= corr[mi][0];
                    o[mi][nd][2] *= corr[mi][1];
                    o[mi][nd][3] *= corr[mi][1];
                }
            float ls[2][2] = {{0.f, 0.f}, {0.f, 0.f}};
#pragma unroll
            for (int mi = 0; mi < 2; mi++)
#pragma unroll
                for (int ni = 0; ni < 8; ni++) {
                    float p0 = exp2f((s[mi][ni][0] - mrow[mi][0]) * SCL2E);
                    float p1 = exp2f((s[mi][ni][1] - mrow[mi][0]) * SCL2E);
                    float p2 = exp2f((s[mi][ni][2] - mrow[mi][1]) * SCL2E);
                    float p3 = exp2f((s[mi][ni][3] - mrow[mi][1]) * SCL2E);
                    s[mi][ni][0] = p0; s[mi][ni][1] = p1;
                    s[mi][ni][2] = p2; s[mi][ni][3] = p3;
                    ls[mi][0] += p0 + p1;
                    ls[mi][1] += p2 + p3;
                }
#pragma unroll
            for (int mi = 0; mi < 2; mi++)
#pragma unroll
                for (int hh = 0; hh < 2; hh++) {
                    float v = ls[mi][hh];
                    v += __shfl_xor_sync(0xFFFFFFFFu, v, 1);
                    v += __shfl_xor_sync(0xFFFFFFFFu, v, 2);
                    lrow[mi][hh] += v;
                }

            // ---- O += Ph*Vh + Ph*Vl + Pl*Vh ----
            int l15 = lane & 15;
#pragma unroll
            for (int j = 0; j < 4; j++) {
                uint32_t pah[2][4], pal[2][4];
#pragma unroll
                for (int mi = 0; mi < 2; mi++) {
                    split2(s[mi][2*j][0],   s[mi][2*j][1],   pah[mi][0], pal[mi][0]);
                    split2(s[mi][2*j][2],   s[mi][2*j][3],   pah[mi][1], pal[mi][1]);
                    split2(s[mi][2*j+1][0], s[mi][2*j+1][1], pah[mi][2], pal[mi][2]);
                    split2(s[mi][2*j+1][2], s[mi][2*j+1][3], pah[mi][3], pal[mi][3]);
                }
#pragma unroll
                for (int nd = 0; nd < 4; nd++) {
                    uint32_t off = (uint32_t)(16 * j + l15) * AT_PITCH + nd * 16;
                    uint32_t vhf[2], vlf[2];
                    ldsm_x2t(vhf, vb + off);
                    ldsm_x2t(vlf, vb + 5120 + off);
#pragma unroll
                    for (int mi = 0; mi < 2; mi++) {
                        mma_bf16(o[mi][nd], pah[mi], vhf[0], vhf[1]);
                        mma_bf16(o[mi][nd], pah[mi], vlf[0], vlf[1]);
                        mma_bf16(o[mi][nd], pal[mi], vhf[0], vhf[1]);
                    }
                }
            }
        }
        __syncthreads();
    }

    // ---- normalize + write hi/lo planes ----
#pragma unroll
    for (int mi = 0; mi < 2; mi++) {
        int r0 = qw0 + mi * 16 + gr;
        int r1 = r0 + 8;
        float inv0 = (r0 < len && lrow[mi][0] > 0.f) ? 1.0f / lrow[mi][0] : 0.f;
        float inv1 = (r1 < len && lrow[mi][1] > 0.f) ? 1.0f / lrow[mi][1] : 0.f;
#pragma unroll
        for (int nd = 0; nd < 4; nd++) {
            int col = h * DH_ + nd * 8 + tg * 2;
            uint32_t hp, lp;
            split2(o[mi][nd][0] * inv0, o[mi][nd][1] * inv0, hp, lp);
            *(uint32_t*)(YH + (rowbase + r0) * D_ + col) = hp;
            *(uint32_t*)(YL + (rowbase + r0) * D_ + col) = lp;
            split2(o[mi][nd][2] * inv1, o[mi][nd][3] * inv1, hp, lp);
            *(uint32_t*)(YH + (rowbase + r1) * D_ + col) = hp;
            *(uint32_t*)(YL + (rowbase + r1) * D_ + col) = lp;
        }
    }
}

// ==== residual add + LayerNorm (in place) + bf16 hi/lo plane output =======
__global__ __launch_bounds__(256)
void add_ln_kernel(float* X, const float* __restrict__ Yb,
                   const float* __restrict__ g, const float* __restrict__ be,
                   __nv_bfloat16* __restrict__ XH, __nv_bfloat16* __restrict__ XL)
{
    int row = blockIdx.x;
    int d = threadIdx.x;
    size_t idx = (size_t)row * D_ + d;
    float h = X[idx] + Yb[idx];

    float s = h, s2 = h * h;
#pragma unroll
    for (int o = 16; o; o >>= 1) {
        s  += __shfl_xor_sync(0xFFFFFFFFu, s,  o);
        s2 += __shfl_xor_sync(0xFFFFFFFFu, s2, o);
    }
    __shared__ float ws[8], ws2[8];
    int w = d >> 5;
    if ((d & 31) == 0) { ws[w] = s; ws2[w] = s2; }
    __syncthreads();
    float tot = 0.f, tot2 = 0.f;
#pragma unroll
    for (int i = 0; i < 8; i++) { tot += ws[i]; tot2 += ws2[i]; }

    float mean = tot * (1.0f / D_);
    float var  = tot2 * (1.0f / D_) - mean * mean;
    float r = rsqrtf(var + 1e-5f);
    float v = (h - mean) * r * g[d] + be[d];
    X[idx] = v;
    __nv_bfloat16 hb = __float2bfloat16(v);
    XH[idx] = hb;
    XL[idx] = __float2bfloat16(v - __bfloat162float(hb));
}

// =========================== launcher ====================================
extern "C" void kernel_launch(void* const* d_in, const int* in_sizes, int n_in,
                              void* d_out, int out_size)
{
    const int*   ids = (const int*)  d_in[0];
    const int*   tsl = (const int*)  d_in[1];
    const float* emb = (const float*)d_in[2];
    const float* Wq  = (const float*)d_in[3];
    const float* bq  = (const float*)d_in[4];
    const float* Wk  = (const float*)d_in[5];
    const float* bk  = (const float*)d_in[6];
    const float* Wv  = (const float*)d_in[7];
    const float* bv  = (const float*)d_in[8];
    const float* Wo  = (const float*)d_in[9];
    const float* bo  = (const float*)d_in[10];
    const float* W1  = (const float*)d_in[11];
    const float* b1  = (const float*)d_in[12];
    const float* W2  = (const float*)d_in[13];
    const float* b2  = (const float*)d_in[14];
    const float* g1  = (const float*)d_in[15];
    const float* be1 = (const float*)d_in[16];
    const float* g2  = (const float*)d_in[17];
    const float* be2 = (const float*)d_in[18];
    const float* Wc  = (const float*)d_in[19];
    const float* bc  = (const float*)d_in[20];
    float* out = (float*)d_out;

    float *x, *t, *bqkv;
    cudaGetSymbolAddress((void**)&x,   g_x);
    cudaGetSymbolAddress((void**)&t,   g_t);
    cudaGetSymbolAddress((void**)&bqkv, g_bqkv);

    __nv_bfloat16 *xh, *xl, *yh, *yl, *ffh, *ffl, *qkvh, *qkvl;
    cudaGetSymbolAddress((void**)&xh,  g_xh);   cudaGetSymbolAddress((void**)&xl,  g_xl);
    cudaGetSymbolAddress((void**)&yh,  g_yh);   cudaGetSymbolAddress((void**)&yl,  g_yl);
    cudaGetSymbolAddress((void**)&ffh, g_ffh);  cudaGetSymbolAddress((void**)&ffl, g_ffl);
    cudaGetSymbolAddress((void**)&qkvh, g_qkvh); cudaGetSymbolAddress((void**)&qkvl, g_qkvl);

    __nv_bfloat16 *qkvTh, *qkvTl, *oTh, *oTl, *w1h, *w1l, *w2h, *w2l, *wch, *wcl;
    cudaGetSymbolAddress((void**)&qkvTh, g_qkvT_hi); cudaGetSymbolAddress((void**)&qkvTl, g_qkvT_lo);
    cudaGetSymbolAddress((void**)&oTh,  g_oT_hi);    cudaGetSymbolAddress((void**)&oTl,  g_oT_lo);
    cudaGetSymbolAddress((void**)&w1h,  g_1T_hi);    cudaGetSymbolAddress((void**)&w1l,  g_1T_lo);
    cudaGetSymbolAddress((void**)&w2h,  g_2T_hi);    cudaGetSymbolAddress((void**)&w2l,  g_2T_lo);
    cudaGetSymbolAddress((void**)&wch,  g_cT_hi);    cudaGetSymbolAddress((void**)&wcl,  g_cT_lo);

    cudaFuncSetAttribute((const void*)gemm_tc,
                         cudaFuncAttributeMaxDynamicSharedMemorySize, GEMM_SMEM);
    cudaFuncSetAttribute((const void*)attn_tc,
                         cudaFuncAttributeMaxDynamicSharedMemorySize, AT_SMEM);

    dim3 tb(32, 8);
    convert_w_kernel<<<dim3(8, 8, L_),  tb>>>(Wq, qkvTh,            qkvTl,            256, 256, QKV_N);
    convert_w_kernel<<<dim3(8, 8, L_),  tb>>>(Wk, qkvTh + 256 * D_, qkvTl + 256 * D_, 256, 256, QKV_N);
    convert_w_kernel<<<dim3(8, 8, L_),  tb>>>(Wv, qkvTh + 512 * D_, qkvTl + 512 * D_, 256, 256, QKV_N);
    convert_w_kernel<<<dim3(8, 8, L_),  tb>>>(Wo, oTh, oTl, 256, 256, 256);
    convert_w_kernel<<<dim3(8, 32, L_), tb>>>(W1, w1h, w1l, 256, 1024, 1024);
    convert_w_kernel<<<dim3(32, 8, L_), tb>>>(W2, w2h, w2l, 1024, 256, 256);
    convert_w_kernel<<<dim3(8, 4, 1),   tb>>>(Wc, wch, wcl, 256, 100, 128);
    pack_bias_kernel<<<L_, QKV_N>>>(bq, bk, bv, bqkv);

    embed_kernel<<<M_TOK, D_>>>(ids, emb, x, xh, xl);

    dim3 gQKV(QKV_N / GBN, M_TOK / GBM);
    dim3 gD  (D_ / GBN,    M_TOK / GBM);
    dim3 gF  (DFF_ / GBN,  M_TOK / GBM);
    dim3 gC  (2,           M_TOK / GBM);

    for (int l = 0; l < L_; l++) {
        size_t qoff  = (size_t)l * QKV_N * D_;
        size_t ooff  = (size_t)l * D_ * D_;
        size_t w1off = (size_t)l * DFF_ * D_;

        gemm_tc<<<gQKV, 256, GEMM_SMEM>>>(xh, xl, qkvTh + qoff, qkvTl + qoff,
                                          bqkv + l * QKV_N, 0, qkvh, qkvl, D_, QKV_N, 0);
        attn_tc<<<dim3(S_ / 128, H_, B_), 128, AT_SMEM>>>(qkvh, qkvl, yh, yl, tsl);

        gemm_tc<<<gD, 256, GEMM_SMEM>>>(yh, yl, oTh + ooff, oTl + ooff,
                                        bo + l * D_, t, 0, 0, D_, D_, 0);
        add_ln_kernel<<<M_TOK, D_>>>(x, t, g1 + l * D_, be1 + l * D_, xh, xl);

        gemm_tc<<<gF, 256, GEMM_SMEM>>>(xh, xl, w1h + w1off, w1l + w1off,
                                        b1 + l * DFF_, 0, ffh, ffl, D_, DFF_, 1);
        gemm_tc<<<gD, 256, GEMM_SMEM>>>(ffh, ffl, w2h + w1off, w2l + w1off,
                                        b2 + l * D_, t, 0, 0, DFF_, D_, 0);
        add_ln_kernel<<<M_TOK, D_>>>(x, t, g2 + l * D_, be2 + l * D_, xh, xl);
    }

    gemm_tc<<<gC, 256, GEMM_SMEM>>>(xh, xl, wch, wcl, bc, out, 0, 0, D_, V_, 0);
}

// round 6
// speedup vs baseline: 3.1389x; 1.0288x over previous
#include <cuda_runtime.h>
#include <cuda_bf16.h>
#include <math.h>
#include <stdint.h>

// Problem constants
#define B_  8
#define S_  1024
#define D_  256
#define H_  8
#define DH_ 32
#define L_  4
#define V_  100
#define DFF_ 1024
#define M_TOK (B_ * S_)   // 8192
#define QKV_N 768

// -------- scratch (static device globals; no runtime allocation) --------
__device__ float g_x [M_TOK * D_];

// activation bf16 hi/lo planes ([M,K] row-major)
__device__ __nv_bfloat16 g_xh  [M_TOK * D_],    g_xl  [M_TOK * D_];
__device__ __nv_bfloat16 g_yh  [M_TOK * D_],    g_yl  [M_TOK * D_];
__device__ __nv_bfloat16 g_ffh [M_TOK * DFF_],  g_ffl [M_TOK * DFF_];
__device__ __nv_bfloat16 g_qkvh[M_TOK * QKV_N], g_qkvl[M_TOK * QKV_N];

// K-major ([N,K]) bf16 hi/lo weight planes
__device__ __nv_bfloat16 g_qkvT_hi[L_*QKV_N*D_], g_qkvT_lo[L_*QKV_N*D_];
__device__ __nv_bfloat16 g_oT_hi [L_*D_*D_],     g_oT_lo [L_*D_*D_];
__device__ __nv_bfloat16 g_1T_hi [L_*DFF_*D_],   g_1T_lo [L_*DFF_*D_];
__device__ __nv_bfloat16 g_2T_hi [L_*D_*DFF_],   g_2T_lo [L_*D_*DFF_];
__device__ __nv_bfloat16 g_cT_hi [128*D_],       g_cT_lo [128*D_];
__device__ float g_bqkv[L_ * QKV_N];

// =========================== PTX helpers ==================================
__device__ __forceinline__ uint32_t smem_u32(const void* p) {
    uint32_t r;
    asm("{ .reg .u64 t; cvta.to.shared.u64 t, %1; cvt.u32.u64 %0, t; }"
        : "=r"(r) : "l"(p));
    return r;
}
__device__ __forceinline__ void cp_async16(uint32_t dst, const void* src) {
    asm volatile("cp.async.cg.shared.global [%0], [%1], 16;"
                 :: "r"(dst), "l"(src));
}
__device__ __forceinline__ void cp_commit() {
    asm volatile("cp.async.commit_group;" ::: "memory");
}
__device__ __forceinline__ void cp_wait1() {
    asm volatile("cp.async.wait_group 1;" ::: "memory");
}
__device__ __forceinline__ void cp_wait0() {
    asm volatile("cp.async.wait_group 0;" ::: "memory");
}
__device__ __forceinline__ void ldsm_x4(uint32_t* r, uint32_t addr) {
    asm volatile("ldmatrix.sync.aligned.m8n8.x4.shared.b16 {%0,%1,%2,%3}, [%4];"
                 : "=r"(r[0]), "=r"(r[1]), "=r"(r[2]), "=r"(r[3]) : "r"(addr));
}
__device__ __forceinline__ void ldsm_x2(uint32_t* r, uint32_t addr) {
    asm volatile("ldmatrix.sync.aligned.m8n8.x2.shared.b16 {%0,%1}, [%2];"
                 : "=r"(r[0]), "=r"(r[1]) : "r"(addr));
}
__device__ __forceinline__ void ldsm_x2t(uint32_t* r, uint32_t addr) {
    asm volatile("ldmatrix.sync.aligned.m8n8.x2.trans.shared.b16 {%0,%1}, [%2];"
                 : "=r"(r[0]), "=r"(r[1]) : "r"(addr));
}
__device__ __forceinline__ void mma_bf16(float* d, const uint32_t* a,
                                         uint32_t b0, uint32_t b1) {
    asm volatile(
        "mma.sync.aligned.m16n8k16.row.col.f32.bf16.bf16.f32 "
        "{%0,%1,%2,%3}, {%4,%5,%6,%7}, {%8,%9}, {%0,%1,%2,%3};"
        : "+f"(d[0]), "+f"(d[1]), "+f"(d[2]), "+f"(d[3])
        : "r"(a[0]), "r"(a[1]), "r"(a[2]), "r"(a[3]), "r"(b0), "r"(b1));
}
__device__ __forceinline__ uint32_t swz128(uint32_t x) {
    return x ^ ((x >> 3) & 0x70u);
}
__device__ __forceinline__ uint32_t pack_bf2(__nv_bfloat16 a, __nv_bfloat16 b) {
    __nv_bfloat162 t(a, b);
    return *reinterpret_cast<uint32_t*>(&t);
}
__device__ __forceinline__ void split2(float a, float b, uint32_t& hi, uint32_t& lo) {
    __nv_bfloat16 h0 = __float2bfloat16(a);
    __nv_bfloat16 h1 = __float2bfloat16(b);
    __nv_bfloat16 l0 = __float2bfloat16(a - __bfloat162float(h0));
    __nv_bfloat16 l1 = __float2bfloat16(b - __bfloat162float(h1));
    hi = pack_bf2(h0, h1);
    lo = pack_bf2(l0, l1);
}

// ===================== GEMM tiling constants ==============================
#define GBM 128
#define GBN 64
#define GKB 64
#define APLANE 16384
#define BPLANE 8192
#define BUFB (2*APLANE + 2*BPLANE)
#define GEMM_SMEM (2*BUFB + 1024)

// ============ weight transpose + bf16 hi/lo split:  W[K,N] -> WT[N,K] =====
__global__ void convert_w_kernel(const float* __restrict__ W,
                                 __nv_bfloat16* __restrict__ Hi,
                                 __nv_bfloat16* __restrict__ Lo,
                                 int K, int N, int Npad)
{
    __shared__ float t[32][33];
    const float* Wz = W + (size_t)blockIdx.z * K * N;
    __nv_bfloat16* Hz = Hi + (size_t)blockIdx.z * Npad * K;
    __nv_bfloat16* Lz = Lo + (size_t)blockIdx.z * Npad * K;
    int k0 = blockIdx.x * 32, n0 = blockIdx.y * 32;
    int tx = threadIdx.x, ty = threadIdx.y;
#pragma unroll
    for (int r = 0; r < 4; r++) {
        int k = k0 + ty + 8 * r;
        int n = n0 + tx;
        t[ty + 8 * r][tx] = (n < N) ? Wz[(size_t)k * N + n] : 0.0f;
    }
    __syncthreads();
#pragma unroll
    for (int r = 0; r < 4; r++) {
        int n = n0 + ty + 8 * r;
        int k = k0 + tx;
        float v = t[tx][ty + 8 * r];
        __nv_bfloat16 h = __float2bfloat16(v);
        __nv_bfloat16 l = __float2bfloat16(v - __bfloat162float(h));
        Hz[(size_t)n * K + k] = h;
        Lz[(size_t)n * K + k] = l;
    }
}

__global__ void pack_bias_kernel(const float* __restrict__ bq,
                                 const float* __restrict__ bk,
                                 const float* __restrict__ bv,
                                 float* __restrict__ o)
{
    int l = blockIdx.x, j = threadIdx.x;
    float v;
    if (j < 256)      v = bq[l * 256 + j];
    else if (j < 512) v = bk[l * 256 + j - 256];
    else              v = bv[l * 256 + j - 512];
    o[l * QKV_N + j] = v;
}

// ====================== HMMA bf16 split-precision GEMM ====================
__device__ __forceinline__ void gemm_fill(
    uint32_t smU, int b, int kb,
    const __nv_bfloat16* __restrict__ AHi, const __nv_bfloat16* __restrict__ ALo,
    const __nv_bfloat16* __restrict__ BHi, const __nv_bfloat16* __restrict__ BLo,
    int K, int bm, int bn, int tid)
{
    const int k0 = kb * GKB;
    uint32_t aHiU = smU + b * BUFB;
    uint32_t aLoU = aHiU + APLANE;
    uint32_t bHiU = aHiU + 2 * APLANE;
    uint32_t bLoU = bHiU + BPLANE;

#pragma unroll
    for (int i = 0; i < 4; i++) {
        int j   = tid + 256 * i;
        int row = j >> 3;
        int ch  = (j & 7) << 4;
        uint32_t off = swz128((uint32_t)(row * 128 + ch));
        size_t srcb = ((size_t)(bm + row) * K + k0) * 2 + ch;
        cp_async16(aHiU + off, (const char*)AHi + srcb);
        cp_async16(aLoU + off, (const char*)ALo + srcb);
    }
#pragma unroll
    for (int i = 0; i < 2; i++) {
        int j   = tid + 256 * i;
        int row = j >> 3;
        int ch  = (j & 7) << 4;
        uint32_t off = swz128((uint32_t)(row * 128 + ch));
        size_t srcb = ((size_t)(bn + row) * K + k0) * 2 + ch;
        cp_async16(bHiU + off, (const char*)BHi + srcb);
        cp_async16(bLoU + off, (const char*)BLo + srcb);
    }
}

__device__ __forceinline__ void gemm_compute(
    uint32_t smU, int b, int m0, int n0, int lane, float (*acc)[4][4])
{
    const uint32_t aU = smU + b * BUFB;
    const uint32_t bU = aU + 2 * APLANE;

    const int a_row = m0 + (lane & 15);
    const int a_kb  = (lane >> 4) * 16;
    const int b_row = n0 + ((lane >> 4) << 3) + (lane & 7);
    const int b_kb  = ((lane >> 3) & 1) * 16;

#pragma unroll
    for (int ks = 0; ks < 4; ks++) {
        const int kbase = ks * 32;
        uint32_t ah[2][4], al[2][4], bh[2][4], bl[2][4];
#pragma unroll
        for (int mi = 0; mi < 2; mi++) {
            uint32_t off = swz128((uint32_t)((a_row + mi * 16) * 128 + kbase + a_kb));
            ldsm_x4(ah[mi], aU + off);
            ldsm_x4(al[mi], aU + APLANE + off);
        }
#pragma unroll
        for (int bi = 0; bi < 2; bi++) {
            uint32_t off = swz128((uint32_t)((b_row + bi * 16) * 128 + kbase + b_kb));
            ldsm_x4(bh[bi], bU + off);
            ldsm_x4(bl[bi], bU + BPLANE + off);
        }
#pragma unroll
        for (int mi = 0; mi < 2; mi++)
#pragma unroll
            for (int ni = 0; ni < 4; ni++) {
                uint32_t h0 = bh[ni >> 1][(ni & 1) * 2];
                uint32_t h1 = bh[ni >> 1][(ni & 1) * 2 + 1];
                uint32_t l0 = bl[ni >> 1][(ni & 1) * 2];
                uint32_t l1 = bl[ni >> 1][(ni & 1) * 2 + 1];
                mma_bf16(acc[mi][ni], ah[mi], h0, h1);
                mma_bf16(acc[mi][ni], ah[mi], l0, l1);
                mma_bf16(acc[mi][ni], al[mi], h0, h1);
            }
    }
}

__global__ __launch_bounds__(256, 2)
void gemm_tc(const __nv_bfloat16* __restrict__ AHi,
             const __nv_bfloat16* __restrict__ ALo,
             const __nv_bfloat16* __restrict__ BHi,
             const __nv_bfloat16* __restrict__ BLo,
             const float* __restrict__ bias,
             float* __restrict__ C,
             __nv_bfloat16* __restrict__ CHi,
             __nv_bfloat16* __restrict__ CLo,
             int K, int N, int relu)
{
    extern __shared__ char dsm_raw[];
    const int tid  = threadIdx.x;
    const int lane = tid & 31;
    const int wid  = tid >> 5;
    const int m0   = (wid >> 1) * 32;
    const int n0   = (wid & 1) * 32;
    const int bm   = blockIdx.y * GBM;
    const int bn   = blockIdx.x * GBN;
    const int nk   = K / GKB;

    uint32_t rawU = smem_u32(dsm_raw);
    uint32_t smU  = (rawU + 1023u) & ~1023u;

    float acc[2][4][4];
#pragma unroll
    for (int mi = 0; mi < 2; mi++)
#pragma unroll
        for (int ni = 0; ni < 4; ni++)
#pragma unroll
            for (int e = 0; e < 4; e++) acc[mi][ni][e] = 0.0f;

    gemm_fill(smU, 0, 0, AHi, ALo, BHi, BLo, K, bm, bn, tid);
    cp_commit();

    for (int kb = 0; kb < nk; kb++) {
        const int b = kb & 1;
        if (kb + 1 < nk) {
            gemm_fill(smU, b ^ 1, kb + 1, AHi, ALo, BHi, BLo, K, bm, bn, tid);
            cp_commit();
            cp_wait1();
        } else {
            cp_wait0();
        }
        __syncthreads();
        gemm_compute(smU, b, m0, n0, lane, acc);
        __syncthreads();
    }

    const int gr = lane >> 2;
    const int gc = (lane & 3) * 2;
#pragma unroll
    for (int mi = 0; mi < 2; mi++) {
        int r0 = bm + m0 + mi * 16 + gr;
#pragma unroll
        for (int ni = 0; ni < 4; ni++) {
            int c = bn + n0 + ni * 8 + gc;
            int c0s = (c < N) ? c : N - 1;
            int c1s = (c + 1 < N) ? c + 1 : N - 1;
            float v00 = acc[mi][ni][0] + bias[c0s];
            float v01 = acc[mi][ni][1] + bias[c1s];
            float v10 = acc[mi][ni][2] + bias[c0s];
            float v11 = acc[mi][ni][3] + bias[c1s];
            if (relu) {
                v00 = fmaxf(v00, 0.f); v01 = fmaxf(v01, 0.f);
                v10 = fmaxf(v10, 0.f); v11 = fmaxf(v11, 0.f);
            }
            if (CHi) {
                uint32_t h0, l0, h1, l1;
                split2(v00, v01, h0, l0);
                split2(v10, v11, h1, l1);
                *(uint32_t*)(CHi + (size_t)r0 * N + c) = h0;
                *(uint32_t*)(CLo + (size_t)r0 * N + c) = l0;
                *(uint32_t*)(CHi + (size_t)(r0 + 8) * N + c) = h1;
                *(uint32_t*)(CLo + (size_t)(r0 + 8) * N + c) = l1;
            } else if (c + 1 < N) {
                *(float2*)(C + (size_t)r0 * N + c) = make_float2(v00, v01);
                *(float2*)(C + (size_t)(r0 + 8) * N + c) = make_float2(v10, v11);
            } else if (c < N) {
                C[(size_t)r0 * N + c] = v00;
                C[(size_t)(r0 + 8) * N + c] = v10;
            }
        }
    }
}

// ========== fused GEMM (N=256) + bias + residual + LayerNorm ==============
// X <- LN(X + A*B^T + bias); also emits XH/XL bf16 planes.
// Tile 64x256, 256 threads (8 warps: 2 m-groups x 4 n-groups of 64 cols).
#define LN_BM 64
#define LN_AP 8192              // 64 x 128B per plane
#define LN_BP 32768             // 256 x 128B per plane
#define LN_STAGE (2*LN_AP + 2*LN_BP)   // 81920
#define LN_SMEM (2*LN_STAGE)           // 163840

__device__ __forceinline__ void ln_fill(
    uint32_t smU, int b, int kb,
    const __nv_bfloat16* __restrict__ AHi, const __nv_bfloat16* __restrict__ ALo,
    const __nv_bfloat16* __restrict__ BHi, const __nv_bfloat16* __restrict__ BLo,
    int K, int bm, int tid)
{
    const int k0 = kb * GKB;
    uint32_t aHiU = smU + b * LN_STAGE;
    uint32_t aLoU = aHiU + LN_AP;
    uint32_t bHiU = aHiU + 2 * LN_AP;
    uint32_t bLoU = bHiU + LN_BP;

#pragma unroll
    for (int i = 0; i < 2; i++) {
        int j   = tid + 256 * i;          // 0..511
        int row = j >> 3;                 // 0..63
        int ch  = (j & 7) << 4;
        uint32_t off = swz128((uint32_t)(row * 128 + ch));
        size_t srcb = ((size_t)(bm + row) * K + k0) * 2 + ch;
        cp_async16(aHiU + off, (const char*)AHi + srcb);
        cp_async16(aLoU + off, (const char*)ALo + srcb);
    }
#pragma unroll
    for (int i = 0; i < 8; i++) {
        int j   = tid + 256 * i;          // 0..2047
        int row = j >> 3;                 // 0..255
        int ch  = (j & 7) << 4;
        uint32_t off = swz128((uint32_t)(row * 128 + ch));
        size_t srcb = ((size_t)row * K + k0) * 2 + ch;
        cp_async16(bHiU + off, (const char*)BHi + srcb);
        cp_async16(bLoU + off, (const char*)BLo + srcb);
    }
}

__global__ __launch_bounds__(256)
void gemm_ln(const __nv_bfloat16* __restrict__ AHi,
             const __nv_bfloat16* __restrict__ ALo,
             const __nv_bfloat16* __restrict__ BHi,
             const __nv_bfloat16* __restrict__ BLo,
             const float* __restrict__ bias,
             const float* __restrict__ g,
             const float* __restrict__ be,
             float* __restrict__ X,
             __nv_bfloat16* __restrict__ XH,
             __nv_bfloat16* __restrict__ XL,
             int K)
{
    extern __shared__ char dsm_raw[];
    __shared__ float redS[64][4], redQ[64][4];

    const int tid  = threadIdx.x;
    const int lane = tid & 31;
    const int wid  = tid >> 5;
    const int m0   = (wid >> 2) * 32;     // 0 or 32
    const int n0   = (wid & 3) * 64;      // 0,64,128,192
    const int bm   = blockIdx.x * LN_BM;
    const int nk   = K / GKB;

    uint32_t rawU = smem_u32(dsm_raw);
    uint32_t smU  = (rawU + 1023u) & ~1023u;

    float acc[2][8][4];
#pragma unroll
    for (int mi = 0; mi < 2; mi++)
#pragma unroll
        for (int ni = 0; ni < 8; ni++)
#pragma unroll
            for (int e = 0; e < 4; e++) acc[mi][ni][e] = 0.0f;

    ln_fill(smU, 0, 0, AHi, ALo, BHi, BLo, K, bm, tid);
    cp_commit();

    const int a_row = m0 + (lane & 15);
    const int a_kb  = (lane >> 4) * 16;
    const int b_rowL = ((lane >> 4) << 3) + (lane & 7);
    const int b_kb  = ((lane >> 3) & 1) * 16;

    for (int kb = 0; kb < nk; kb++) {
        const int b = kb & 1;
        if (kb + 1 < nk) {
            ln_fill(smU, b ^ 1, kb + 1, AHi, ALo, BHi, BLo, K, bm, tid);
            cp_commit();
            cp_wait1();
        } else {
            cp_wait0();
        }
        __syncthreads();

        const uint32_t aU = smU + b * LN_STAGE;
        const uint32_t bU = aU + 2 * LN_AP;
#pragma unroll
        for (int ks = 0; ks < 4; ks++) {
            const int kbase = ks * 32;
            uint32_t ah[2][4], al[2][4], bh[4][4], bl[4][4];
#pragma unroll
            for (int mi = 0; mi < 2; mi++) {
                uint32_t off = swz128((uint32_t)((a_row + mi * 16) * 128 + kbase + a_kb));
                ldsm_x4(ah[mi], aU + off);
                ldsm_x4(al[mi], aU + LN_AP + off);
            }
#pragma unroll
            for (int bi = 0; bi < 4; bi++) {
                uint32_t off = swz128((uint32_t)((n0 + bi * 16 + b_rowL) * 128 + kbase + b_kb));
                ldsm_x4(bh[bi], bU + off);
                ldsm_x4(bl[bi], bU + LN_BP + off);
            }
#pragma unroll
            for (int mi = 0; mi < 2; mi++)
#pragma unroll
                for (int ni = 0; ni < 8; ni++) {
                    uint32_t h0 = bh[ni >> 1][(ni & 1) * 2];
                    uint32_t h1 = bh[ni >> 1][(ni & 1) * 2 + 1];
                    uint32_t l0 = bl[ni >> 1][(ni & 1) * 2];
                    uint32_t l1 = bl[ni >> 1][(ni & 1) * 2 + 1];
                    mma_bf16(acc[mi][ni], ah[mi], h0, h1);
                    mma_bf16(acc[mi][ni], ah[mi], l0, l1);
                    mma_bf16(acc[mi][ni], al[mi], h0, h1);
                }
        }
        __syncthreads();
    }

    // ---- epilogue: bias + residual, row stats, LN, write ----
    const int gr = lane >> 2;
    const int tg = lane & 3;
    const int nw = wid & 3;

#pragma unroll
    for (int mi = 0; mi < 2; mi++) {
        int rl0 = m0 + mi * 16 + gr;      // local row (half0)
        int rl1 = rl0 + 8;
        size_t gb0 = (size_t)(bm + rl0) * D_;
        size_t gb1 = (size_t)(bm + rl1) * D_;
        float s0 = 0.f, q0 = 0.f, s1 = 0.f, q1 = 0.f;
#pragma unroll
        for (int ni = 0; ni < 8; ni++) {
            int c = n0 + ni * 8 + tg * 2;
            float2 bv = *(const float2*)(bias + c);
            float2 x0 = *(const float2*)(X + gb0 + c);
            float2 x1 = *(const float2*)(X + gb1 + c);
            acc[mi][ni][0] += bv.x + x0.x;
            acc[mi][ni][1] += bv.y + x0.y;
            acc[mi][ni][2] += bv.x + x1.x;
            acc[mi][ni][3] += bv.y + x1.y;
            s0 += acc[mi][ni][0] + acc[mi][ni][1];
            q0 += acc[mi][ni][0] * acc[mi][ni][0] + acc[mi][ni][1] * acc[mi][ni][1];
            s1 += acc[mi][ni][2] + acc[mi][ni][3];
            q1 += acc[mi][ni][2] * acc[mi][ni][2] + acc[mi][ni][3] * acc[mi][ni][3];
        }
#pragma unroll
        for (int o = 1; o <= 2; o <<= 1) {
            s0 += __shfl_xor_sync(0xFFFFFFFFu, s0, o);
            q0 += __shfl_xor_sync(0xFFFFFFFFu, q0, o);
            s1 += __shfl_xor_sync(0xFFFFFFFFu, s1, o);
            q1 += __shfl_xor_sync(0xFFFFFFFFu, q1, o);
        }
        if (tg == 0) {
            redS[rl0][nw] = s0; redQ[rl0][nw] = q0;
            redS[rl1][nw] = s1; redQ[rl1][nw] = q1;
        }
    }
    __syncthreads();

#pragma unroll
    for (int mi = 0; mi < 2; mi++) {
        int rl0 = m0 + mi * 16 + gr;
        int rl1 = rl0 + 8;
        float S0 = redS[rl0][0] + redS[rl0][1] + redS[rl0][2] + redS[rl0][3];
        float Q0 = redQ[rl0][0] + redQ[rl0][1] + redQ[rl0][2] + redQ[rl0][3];
        float S1 = redS[rl1][0] + redS[rl1][1] + redS[rl1][2] + redS[rl1][3];
        float Q1 = redQ[rl1][0] + redQ[rl1][1] + redQ[rl1][2] + redQ[rl1][3];
        float mean0 = S0 * (1.0f / D_);
        float mean1 = S1 * (1.0f / D_);
        float r0 = rsqrtf(Q0 * (1.0f / D_) - mean0 * mean0 + 1e-5f);
        float r1 = rsqrtf(Q1 * (1.0f / D_) - mean1 * mean1 + 1e-5f);
        size_t gb0 = (size_t)(bm + rl0) * D_;
        size_t gb1 = (size_t)(bm + rl1) * D_;
#pragma unroll
        for (int ni = 0; ni < 8; ni++) {
            int c = n0 + ni * 8 + tg * 2;
            float2 gv = *(const float2*)(g + c);
            float2 bev = *(const float2*)(be + c);
            float o00 = (acc[mi][ni][0] - mean0) * r0 * gv.x + bev.x;
            float o01 = (acc[mi][ni][1] - mean0) * r0 * gv.y + bev.y;
            float o10 = (acc[mi][ni][2] - mean1) * r1 * gv.x + bev.x;
            float o11 = (acc[mi][ni][3] - mean1) * r1 * gv.y + bev.y;
            *(float2*)(X + gb0 + c) = make_float2(o00, o01);
            *(float2*)(X + gb1 + c) = make_float2(o10, o11);
            uint32_t hp, lp;
            split2(o00, o01, hp, lp);
            *(uint32_t*)(XH + gb0 + c) = hp;
            *(uint32_t*)(XL + gb0 + c) = lp;
            split2(o10, o11, hp, lp);
            *(uint32_t*)(XH + gb1 + c) = hp;
            *(uint32_t*)(XL + gb1 + c) = lp;
        }
    }
}

// ============ embedding + positions; also emits bf16 hi/lo planes =========
__global__ void embed_kernel(const int* __restrict__ ids,
                             const float* __restrict__ emb,
                             float* __restrict__ X,
                             __nv_bfloat16* __restrict__ XH,
                             __nv_bfloat16* __restrict__ XL)
{
    int t = blockIdx.x;
    int d = threadIdx.x;
    int s = t & (S_ - 1);
    int id = ids[t];
    float f = (d < D_ / 2) ? (2.0f * d) : (2.0f * (d - D_ / 2) + 1.0f);
    float inv = exp2f(-f * 13.287712379549449f / (float)D_);
    float v = emb[(size_t)id * D_ + d] + sinf((float)s * inv);
    size_t idx = (size_t)t * D_ + d;
    X[idx] = v;
    __nv_bfloat16 h = __float2bfloat16(v);
    XH[idx] = h;
    XL[idx] = __float2bfloat16(v - __bfloat162float(h));
}

// ================= tensor-core causal flash attention ====================
#define AT_PITCH 80
#define AT_QH 0
#define AT_QL 10240
#define AT_KV 20480
#define AT_BUF 20480
#define AT_SMEM 61440
#define SCL2E 0.2550348243f   // log2(e)/sqrt(32)

__device__ __forceinline__ void attn_fill_kv(
    uint32_t smU, int buf,
    const __nv_bfloat16* __restrict__ Ph, const __nv_bfloat16* __restrict__ Pl,
    size_t rowbase, int kt, int h, int tid)
{
    uint32_t base = smU + AT_KV + buf * AT_BUF;
#pragma unroll
    for (int i = 0; i < 2; i++) {
        int j = tid + 128 * i;
        int row = j >> 2, ch = (j & 3) * 16;
        size_t gk = ((rowbase + kt + row) * QKV_N + 256 + h * DH_) * 2 + ch;
        size_t gv = gk + 512;
        uint32_t d = row * AT_PITCH + ch;
        cp_async16(base + d,         (const char*)Ph + gk);
        cp_async16(base + 5120 + d,  (const char*)Pl + gk);
        cp_async16(base + 10240 + d, (const char*)Ph + gv);
        cp_async16(base + 15360 + d, (const char*)Pl + gv);
    }
}

__global__ __launch_bounds__(128)
void attn_tc(const __nv_bfloat16* __restrict__ Ph,
             const __nv_bfloat16* __restrict__ Pl,
             __nv_bfloat16* __restrict__ YH, __nv_bfloat16* __restrict__ YL,
             const int* __restrict__ tsl)
{
    extern __shared__ char asmem[];
    const int tid = threadIdx.x, lane = tid & 31, w = tid >> 5;
    const int qblk = blockIdx.x, h = blockIdx.y, b = blockIdx.z;
    const int q0 = qblk * 128;
    const int len = tsl[b];
    const int gr = lane >> 2, tg = lane & 3;
    const uint32_t smU = smem_u32(asmem);
    const size_t rowbase = (size_t)b * S_;

#pragma unroll
    for (int i = 0; i < 4; i++) {
        int j = tid + 128 * i;
        int row = j >> 2, ch = (j & 3) * 16;
        size_t src = ((rowbase + q0 + row) * QKV_N + h * DH_) * 2 + ch;
        cp_async16(smU + AT_QH + row * AT_PITCH + ch, (const char*)Ph + src);
        cp_async16(smU + AT_QL + row * AT_PITCH + ch, (const char*)Pl + src);
    }
    attn_fill_kv(smU, 0, Ph, Pl, rowbase, 0, h, tid);
    cp_commit();
    cp_wait0();
    __syncthreads();

    uint32_t qfh[2][2][4], qfl[2][2][4];
    {
        int r8 = (lane & 7) + ((lane >> 3) & 1) * 8;
        int cb = ((lane >> 4) & 1) * 16;
#pragma unroll
        for (int mi = 0; mi < 2; mi++)
#pragma unroll
            for (int kk = 0; kk < 2; kk++) {
                uint32_t off = (uint32_t)(w * 32 + mi * 16 + r8) * AT_PITCH + kk * 32 + cb;
                ldsm_x4(qfh[mi][kk], smU + AT_QH + off);
                ldsm_x4(qfl[mi][kk], smU + AT_QL + off);
            }
    }

    float o[2][4][4];
    float mrow[2][2], lrow[2][2];
#pragma unroll
    for (int mi = 0; mi < 2; mi++) {
#pragma unroll
        for (int nd = 0; nd < 4; nd++)
#pragma unroll
            for (int e = 0; e < 4; e++) o[mi][nd][e] = 0.f;
        mrow[mi][0] = mrow[mi][1] = -1e30f;
        lrow[mi][0] = lrow[mi][1] = 0.f;
    }

    const int qw0 = q0 + w * 32;
    const int qwmax = qw0 + 31;
    const int nt = (q0 + 128) / 64;

    for (int t = 0; t < nt; t++) {
        const int kt = t * 64;
        if (t + 1 < nt) {
            attn_fill_kv(smU, (t + 1) & 1, Ph, Pl, rowbase, kt + 64, h, tid);
            cp_commit();
            cp_wait1();
        } else {
            cp_wait0();
        }
        __syncthreads();

        if (kt <= qwmax) {
            const uint32_t kb = smU + AT_KV + (t & 1) * AT_BUF;
            const uint32_t vb = kb + 10240;

            float s[2][8][4];
#pragma unroll
            for (int mi = 0; mi < 2; mi++)
#pragma unroll
                for (int ni = 0; ni < 8; ni++)
#pragma unroll
                    for (int e = 0; e < 4; e++) s[mi][ni][e] = 0.f;
            {
                int l7 = lane & 7;
                int hb = ((lane >> 3) & 1) * 16;
#pragma unroll
                for (int kk = 0; kk < 2; kk++)
#pragma unroll
                    for (int ni = 0; ni < 8; ni++) {
                        uint32_t off = (uint32_t)(ni * 8 + l7) * AT_PITCH + kk * 32 + hb;
                        uint32_t khf[2], klf[2];
                        ldsm_x2(khf, kb + off);
                        ldsm_x2(klf, kb + 5120 + off);
#pragma unroll
                        for (int mi = 0; mi < 2; mi++) {
                            mma_bf16(s[mi][ni], qfh[mi][kk], khf[0], khf[1]);
                            mma_bf16(s[mi][ni], qfh[mi][kk], klf[0], klf[1]);
                            mma_bf16(s[mi][ni], qfl[mi][kk], khf[0], khf[1]);
                        }
                    }
            }

            if (kt + 63 > qw0 || kt + 64 > len) {
#pragma unroll
                for (int mi = 0; mi < 2; mi++) {
                    int r0 = qw0 + mi * 16 + gr, r1 = r0 + 8;
#pragma unroll
                    for (int ni = 0; ni < 8; ni++) {
                        int c0 = kt + ni * 8 + tg * 2, c1 = c0 + 1;
                        if (c0 > r0 || c0 >= len) s[mi][ni][0] = -1e30f;
                        if (c1 > r0 || c1 >= len) s[mi][ni][1] = -1e30f;
                        if (c0 > r1 || c0 >= len) s[mi][ni][2] = -1e30f;
                        if (c1 > r1 || c1 >= len) s[mi][ni][3] = -1e30f;
                    }
                }
            }

            float mx[2][2] = {{-1e30f, -1e30f}, {-1e30f, -1e30f}};
#pragma unroll
            for (int mi = 0; mi < 2; mi++)
#pragma unroll
                for (int ni = 0; ni < 8; ni++) {
                    mx[mi][0] = fmaxf(mx[mi][0], fmaxf(s[mi][ni][0], s[mi][ni][1]));
                    mx[mi][1] = fmaxf(mx[mi][1], fmaxf(s[mi][ni][2], s[mi][ni][3]));
                }
#pragma unroll
            for (int mi = 0; mi < 2; mi++)
#pragma unroll
                for (int hh = 0; hh < 2; hh++) {
                    float v = mx[mi][hh];
                    v = fmaxf(v, __shfl_xor_sync(0xFFFFFFFFu, v, 1));
                    v = fmaxf(v, __shfl_xor_sync(0xFFFFFFFFu, v, 2));
                    mx[mi][hh] = v;
                }

            float corr[2][2];
#pragma unroll
            for (int mi = 0; mi < 2; mi++)
#pragma unroll
                for (int hh = 0; hh < 2; hh++) {
                    float mn = fmaxf(mrow[mi][hh], mx[mi][hh]);
                    corr[mi][hh] = exp2f((mrow[mi][hh] - mn) * SCL2E);
                    mrow[mi][hh] = mn;
                    lrow[mi][hh] *= corr[mi][hh];
                }
#pragma unroll
            for (int mi = 0; mi < 2; mi++)
#pragma unroll
                for (int nd = 0; nd < 4; nd++) {
                    o[mi][nd][0] *= corr[mi][0];
                    o[mi][nd][1] *= corr[mi][0];
                    o[mi][nd][2] *= corr[mi][1];
                    o[mi][nd][3] *= corr[mi][1];
                }
            float ls[2][2] = {{0.f, 0.f}, {0.f, 0.f}};
#pragma unroll
            for (int mi = 0; mi < 2; mi++)
#pragma unroll
                for (int ni = 0; ni < 8; ni++) {
                    float p0 = exp2f((s[mi][ni][0] - mrow[mi][0]) * SCL2E);
                    float p1 = exp2f((s[mi][ni][1] - mrow[mi][0]) * SCL2E);
                    float p2 = exp2f((s[mi][ni][2] - mrow[mi][1]) * SCL2E);
                    float p3 = exp2f((s[mi][ni][3] - mrow[mi][1]) * SCL2E);
                    s[mi][ni][0] = p0; s[mi][ni][1] = p1;
                    s[mi][ni][2] = p2; s[mi][ni][3] = p3;
                    ls[mi][0] += p0 + p1;
                    ls[mi][1] += p2 + p3;
                }
#pragma unroll
            for (int mi = 0; mi < 2; mi++)
#pragma unroll
                for (int hh = 0; hh < 2; hh++) {
                    float v = ls[mi][hh];
                    v += __shfl_xor_sync(0xFFFFFFFFu, v, 1);
                    v += __shfl_xor_sync(0xFFFFFFFFu, v, 2);
                    lrow[mi][hh] += v;
                }

            int l15 = lane & 15;
#pragma unroll
            for (int j = 0; j < 4; j++) {
                uint32_t pah[2][4], pal[2][4];
#pragma unroll
                for (int mi = 0; mi < 2; mi++) {
                    split2(s[mi][2*j][0],   s[mi][2*j][1],   pah[mi][0], pal[mi][0]);
                    split2(s[mi][2*j][2],   s[mi][2*j][3],   pah[mi][1], pal[mi][1]);
                    split2(s[mi][2*j+1][0], s[mi][2*j+1][1], pah[mi][2], pal[mi][2]);
                    split2(s[mi][2*j+1][2], s[mi][2*j+1][3], pah[mi][3], pal[mi][3]);
                }
#pragma unroll
                for (int nd = 0; nd < 4; nd++) {
                    uint32_t off = (uint32_t)(16 * j + l15) * AT_PITCH + nd * 16;
                    uint32_t vhf[2], vlf[2];
                    ldsm_x2t(vhf, vb + off);
                    ldsm_x2t(vlf, vb + 5120 + off);
#pragma unroll
                    for (int mi = 0; mi < 2; mi++) {
                        mma_bf16(o[mi][nd], pah[mi], vhf[0], vhf[1]);
                        mma_bf16(o[mi][nd], pah[mi], vlf[0], vlf[1]);
                        mma_bf16(o[mi][nd], pal[mi], vhf[0], vhf[1]);
                    }
                }
            }
        }
        __syncthreads();
    }

#pragma unroll
    for (int mi = 0; mi < 2; mi++) {
        int r0 = qw0 + mi * 16 + gr;
        int r1 = r0 + 8;
        float inv0 = (r0 < len && lrow[mi][0] > 0.f) ? 1.0f / lrow[mi][0] : 0.f;
        float inv1 = (r1 < len && lrow[mi][1] > 0.f) ? 1.0f / lrow[mi][1] : 0.f;
#pragma unroll
        for (int nd = 0; nd < 4; nd++) {
            int col = h * DH_ + nd * 8 + tg * 2;
            uint32_t hp, lp;
            split2(o[mi][nd][0] * inv0, o[mi][nd][1] * inv0, hp, lp);
            *(uint32_t*)(YH + (rowbase + r0) * D_ + col) = hp;
            *(uint32_t*)(YL + (rowbase + r0) * D_ + col) = lp;
            split2(o[mi][nd][2] * inv1, o[mi][nd][3] * inv1, hp, lp);
            *(uint32_t*)(YH + (rowbase + r1) * D_ + col) = hp;
            *(uint32_t*)(YL + (rowbase + r1) * D_ + col) = lp;
        }
    }
}

// =========================== launcher ====================================
extern "C" void kernel_launch(void* const* d_in, const int* in_sizes, int n_in,
                              void* d_out, int out_size)
{
    const int*   ids = (const int*)  d_in[0];
    const int*   tsl = (const int*)  d_in[1];
    const float* emb = (const float*)d_in[2];
    const float* Wq  = (const float*)d_in[3];
    const float* bq  = (const float*)d_in[4];
    const float* Wk  = (const float*)d_in[5];
    const float* bk  = (const float*)d_in[6];
    const float* Wv  = (const float*)d_in[7];
    const float* bv  = (const float*)d_in[8];
    const float* Wo  = (const float*)d_in[9];
    const float* bo  = (const float*)d_in[10];
    const float* W1  = (const float*)d_in[11];
    const float* b1  = (const float*)d_in[12];
    const float* W2  = (const float*)d_in[13];
    const float* b2  = (const float*)d_in[14];
    const float* g1  = (const float*)d_in[15];
    const float* be1 = (const float*)d_in[16];
    const float* g2  = (const float*)d_in[17];
    const float* be2 = (const float*)d_in[18];
    const float* Wc  = (const float*)d_in[19];
    const float* bc  = (const float*)d_in[20];
    float* out = (float*)d_out;

    float *x, *bqkv;
    cudaGetSymbolAddress((void**)&x,   g_x);
    cudaGetSymbolAddress((void**)&bqkv, g_bqkv);

    __nv_bfloat16 *xh, *xl, *yh, *yl, *ffh, *ffl, *qkvh, *qkvl;
    cudaGetSymbolAddress((void**)&xh,  g_xh);   cudaGetSymbolAddress((void**)&xl,  g_xl);
    cudaGetSymbolAddress((void**)&yh,  g_yh);   cudaGetSymbolAddress((void**)&yl,  g_yl);
    cudaGetSymbolAddress((void**)&ffh, g_ffh);  cudaGetSymbolAddress((void**)&ffl, g_ffl);
    cudaGetSymbolAddress((void**)&qkvh, g_qkvh); cudaGetSymbolAddress((void**)&qkvl, g_qkvl);

    __nv_bfloat16 *qkvTh, *qkvTl, *oTh, *oTl, *w1h, *w1l, *w2h, *w2l, *wch, *wcl;
    cudaGetSymbolAddress((void**)&qkvTh, g_qkvT_hi); cudaGetSymbolAddress((void**)&qkvTl, g_qkvT_lo);
    cudaGetSymbolAddress((void**)&oTh,  g_oT_hi);    cudaGetSymbolAddress((void**)&oTl,  g_oT_lo);
    cudaGetSymbolAddress((void**)&w1h,  g_1T_hi);    cudaGetSymbolAddress((void**)&w1l,  g_1T_lo);
    cudaGetSymbolAddress((void**)&w2h,  g_2T_hi);    cudaGetSymbolAddress((void**)&w2l,  g_2T_lo);
    cudaGetSymbolAddress((void**)&wch,  g_cT_hi);    cudaGetSymbolAddress((void**)&wcl,  g_cT_lo);

    cudaFuncSetAttribute((const void*)gemm_tc,
                         cudaFuncAttributeMaxDynamicSharedMemorySize, GEMM_SMEM);
    cudaFuncSetAttribute((const void*)gemm_ln,
                         cudaFuncAttributeMaxDynamicSharedMemorySize, LN_SMEM);
    cudaFuncSetAttribute((const void*)attn_tc,
                         cudaFuncAttributeMaxDynamicSharedMemorySize, AT_SMEM);

    dim3 tb(32, 8);
    convert_w_kernel<<<dim3(8, 8, L_),  tb>>>(Wq, qkvTh,            qkvTl,            256, 256, QKV_N);
    convert_w_kernel<<<dim3(8, 8, L_),  tb>>>(Wk, qkvTh + 256 * D_, qkvTl + 256 * D_, 256, 256, QKV_N);
    convert_w_kernel<<<dim3(8, 8, L_),  tb>>>(Wv, qkvTh + 512 * D_, qkvTl + 512 * D_, 256, 256, QKV_N);
    convert_w_kernel<<<dim3(8, 8, L_),  tb>>>(Wo, oTh, oTl, 256, 256, 256);
    convert_w_kernel<<<dim3(8, 32, L_), tb>>>(W1, w1h, w1l, 256, 1024, 1024);
    convert_w_kernel<<<dim3(32, 8, L_), tb>>>(W2, w2h, w2l, 1024, 256, 256);
    convert_w_kernel<<<dim3(8, 4, 1),   tb>>>(Wc, wch, wcl, 256, 100, 128);
    pack_bias_kernel<<<L_, QKV_N>>>(bq, bk, bv, bqkv);

    embed_kernel<<<M_TOK, D_>>>(ids, emb, x, xh, xl);

    dim3 gQKV(QKV_N / GBN, M_TOK / GBM);
    dim3 gF  (DFF_ / GBN,  M_TOK / GBM);
    dim3 gC  (2,           M_TOK / GBM);
    const int gLN = M_TOK / LN_BM;   // 128

    for (int l = 0; l < L_; l++) {
        size_t qoff  = (size_t)l * QKV_N * D_;
        size_t ooff  = (size_t)l * D_ * D_;
        size_t w1off = (size_t)l * DFF_ * D_;

        gemm_tc<<<gQKV, 256, GEMM_SMEM>>>(xh, xl, qkvTh + qoff, qkvTl + qoff,
                                          bqkv + l * QKV_N, 0, qkvh, qkvl, D_, QKV_N, 0);
        attn_tc<<<dim3(S_ / 128, H_, B_), 128, AT_SMEM>>>(qkvh, qkvl, yh, yl, tsl);

        gemm_ln<<<gLN, 256, LN_SMEM>>>(yh, yl, oTh + ooff, oTl + ooff,
                                       bo + l * D_, g1 + l * D_, be1 + l * D_,
                                       x, xh, xl, D_);

        gemm_tc<<<gF, 256, GEMM_SMEM>>>(xh, xl, w1h + w1off, w1l + w1off,
                                        b1 + l * DFF_, 0, ffh, ffl, D_, DFF_, 1);

        gemm_ln<<<gLN, 256, LN_SMEM>>>(ffh, ffl, w2h + w1off, w2l + w1off,
                                       b2 + l * D_, g2 + l * D_, be2 + l * D_,
                                       x, xh, xl, DFF_);
    }

    gemm_tc<<<gC, 256, GEMM_SMEM>>>(xh, xl, wch, wcl, bc, out, 0, 0, D_, V_, 0);
}

// round 7
// speedup vs baseline: 3.2699x; 1.0417x over previous
#include <cuda_runtime.h>
#include <cuda_bf16.h>
#include <math.h>
#include <stdint.h>

// Problem constants
#define B_  8
#define S_  1024
#define D_  256
#define H_  8
#define DH_ 32
#define L_  4
#define V_  100
#define DFF_ 1024
#define M_TOK (B_ * S_)   // 8192
#define QKV_N 768

// -------- scratch (static device globals; no runtime allocation) --------
__device__ float g_x [M_TOK * D_];

// activation bf16 hi/lo planes ([M,K] row-major)
__device__ __nv_bfloat16 g_xh  [M_TOK * D_],    g_xl  [M_TOK * D_];
__device__ __nv_bfloat16 g_yh  [M_TOK * D_],    g_yl  [M_TOK * D_];
__device__ __nv_bfloat16 g_ffh [M_TOK * DFF_],  g_ffl [M_TOK * DFF_];
__device__ __nv_bfloat16 g_qkvh[M_TOK * QKV_N], g_qkvl[M_TOK * QKV_N];

// K-major ([N,K]) bf16 hi/lo weight planes
__device__ __nv_bfloat16 g_qkvT_hi[L_*QKV_N*D_], g_qkvT_lo[L_*QKV_N*D_];
__device__ __nv_bfloat16 g_oT_hi [L_*D_*D_],     g_oT_lo [L_*D_*D_];
__device__ __nv_bfloat16 g_1T_hi [L_*DFF_*D_],   g_1T_lo [L_*DFF_*D_];
__device__ __nv_bfloat16 g_2T_hi [L_*D_*DFF_],   g_2T_lo [L_*D_*DFF_];
__device__ __nv_bfloat16 g_cT_hi [128*D_],       g_cT_lo [128*D_];
__device__ float g_bqkv[L_ * QKV_N];

// =========================== PTX helpers ==================================
__device__ __forceinline__ uint32_t smem_u32(const void* p) {
    uint32_t r;
    asm("{ .reg .u64 t; cvta.to.shared.u64 t, %1; cvt.u32.u64 %0, t; }"
        : "=r"(r) : "l"(p));
    return r;
}
__device__ __forceinline__ void cp_async16(uint32_t dst, const void* src) {
    asm volatile("cp.async.cg.shared.global [%0], [%1], 16;"
                 :: "r"(dst), "l"(src));
}
__device__ __forceinline__ void cp_commit() {
    asm volatile("cp.async.commit_group;" ::: "memory");
}
__device__ __forceinline__ void cp_wait1() {
    asm volatile("cp.async.wait_group 1;" ::: "memory");
}
__device__ __forceinline__ void cp_wait0() {
    asm volatile("cp.async.wait_group 0;" ::: "memory");
}
__device__ __forceinline__ void ldsm_x4(uint32_t* r, uint32_t addr) {
    asm volatile("ldmatrix.sync.aligned.m8n8.x4.shared.b16 {%0,%1,%2,%3}, [%4];"
                 : "=r"(r[0]), "=r"(r[1]), "=r"(r[2]), "=r"(r[3]) : "r"(addr));
}
__device__ __forceinline__ void ldsm_x2(uint32_t* r, uint32_t addr) {
    asm volatile("ldmatrix.sync.aligned.m8n8.x2.shared.b16 {%0,%1}, [%2];"
                 : "=r"(r[0]), "=r"(r[1]) : "r"(addr));
}
__device__ __forceinline__ void ldsm_x2t(uint32_t* r, uint32_t addr) {
    asm volatile("ldmatrix.sync.aligned.m8n8.x2.trans.shared.b16 {%0,%1}, [%2];"
                 : "=r"(r[0]), "=r"(r[1]) : "r"(addr));
}
__device__ __forceinline__ void mma_bf16(float* d, const uint32_t* a,
                                         uint32_t b0, uint32_t b1) {
    asm volatile(
        "mma.sync.aligned.m16n8k16.row.col.f32.bf16.bf16.f32 "
        "{%0,%1,%2,%3}, {%4,%5,%6,%7}, {%8,%9}, {%0,%1,%2,%3};"
        : "+f"(d[0]), "+f"(d[1]), "+f"(d[2]), "+f"(d[3])
        : "r"(a[0]), "r"(a[1]), "r"(a[2]), "r"(a[3]), "r"(b0), "r"(b1));
}
__device__ __forceinline__ uint32_t swz128(uint32_t x) {
    return x ^ ((x >> 3) & 0x70u);
}
__device__ __forceinline__ uint32_t pack_bf2(__nv_bfloat16 a, __nv_bfloat16 b) {
    __nv_bfloat162 t(a, b);
    return *reinterpret_cast<uint32_t*>(&t);
}
__device__ __forceinline__ void split2(float a, float b, uint32_t& hi, uint32_t& lo) {
    __nv_bfloat16 h0 = __float2bfloat16(a);
    __nv_bfloat16 h1 = __float2bfloat16(b);
    __nv_bfloat16 l0 = __float2bfloat16(a - __bfloat162float(h0));
    __nv_bfloat16 l1 = __float2bfloat16(b - __bfloat162float(h1));
    hi = pack_bf2(h0, h1);
    lo = pack_bf2(l0, l1);
}

// ===================== GEMM tiling constants ==============================
#define GBM 128
#define GBN 64
#define GKB 64
#define APLANE 16384
#define BPLANE 8192
#define BUFB (2*APLANE + 2*BPLANE)
#define GEMM_SMEM (2*BUFB + 1024)

// ======== weight transpose + bf16 hi/lo split kernels =====================
// generic: W[K,N] -> WT[Npad,K] planes
__global__ void convert_w_kernel(const float* __restrict__ W,
                                 __nv_bfloat16* __restrict__ Hi,
                                 __nv_bfloat16* __restrict__ Lo,
                                 int K, int N, int Npad)
{
    __shared__ float t[32][33];
    const float* Wz = W + (size_t)blockIdx.z * K * N;
    __nv_bfloat16* Hz = Hi + (size_t)blockIdx.z * Npad * K;
    __nv_bfloat16* Lz = Lo + (size_t)blockIdx.z * Npad * K;
    int k0 = blockIdx.x * 32, n0 = blockIdx.y * 32;
    int tx = threadIdx.x, ty = threadIdx.y;
#pragma unroll
    for (int r = 0; r < 4; r++) {
        int k = k0 + ty + 8 * r;
        int n = n0 + tx;
        t[ty + 8 * r][tx] = (n < N) ? Wz[(size_t)k * N + n] : 0.0f;
    }
    __syncthreads();
#pragma unroll
    for (int r = 0; r < 4; r++) {
        int n = n0 + ty + 8 * r;
        int k = k0 + tx;
        float v = t[tx][ty + 8 * r];
        __nv_bfloat16 h = __float2bfloat16(v);
        __nv_bfloat16 l = __float2bfloat16(v - __bfloat162float(h));
        Hz[(size_t)n * K + k] = h;
        Lz[(size_t)n * K + k] = l;
    }
}

// merged Q/K/V converts: z = src*L + l, dst section src*256 within QKV_N rows
__global__ void convert_qkv_kernel(const float* __restrict__ Wq,
                                   const float* __restrict__ Wk,
                                   const float* __restrict__ Wv,
                                   __nv_bfloat16* __restrict__ Hi,
                                   __nv_bfloat16* __restrict__ Lo)
{
    __shared__ float t[32][33];
    int z = blockIdx.z;
    int src = z / L_, l = z % L_;
    const float* W = ((src == 0) ? Wq : (src == 1) ? Wk : Wv) + (size_t)l * D_ * D_;
    __nv_bfloat16* Hz = Hi + (size_t)l * QKV_N * D_ + (size_t)src * 256 * D_;
    __nv_bfloat16* Lz = Lo + (size_t)l * QKV_N * D_ + (size_t)src * 256 * D_;
    int k0 = blockIdx.x * 32, n0 = blockIdx.y * 32;
    int tx = threadIdx.x, ty = threadIdx.y;
#pragma unroll
    for (int r = 0; r < 4; r++)
        t[ty + 8 * r][tx] = W[(size_t)(k0 + ty + 8 * r) * D_ + n0 + tx];
    __syncthreads();
#pragma unroll
    for (int r = 0; r < 4; r++) {
        int n = n0 + ty + 8 * r;
        int k = k0 + tx;
        float v = t[tx][ty + 8 * r];
        __nv_bfloat16 h = __float2bfloat16(v);
        __nv_bfloat16 l2 = __float2bfloat16(v - __bfloat162float(h));
        Hz[(size_t)n * D_ + k] = h;
        Lz[(size_t)n * D_ + k] = l2;
    }
}

// merged Wo (z<L) + classifier Wc (z==L) converts; K=256 for both
__global__ void convert_oc_kernel(const float* __restrict__ Wo,
                                  const float* __restrict__ Wc,
                                  __nv_bfloat16* __restrict__ oH,
                                  __nv_bfloat16* __restrict__ oL,
                                  __nv_bfloat16* __restrict__ cH,
                                  __nv_bfloat16* __restrict__ cL)
{
    __shared__ float t[32][33];
    int z = blockIdx.z;
    const float* W;
    __nv_bfloat16 *Hz, *Lz;
    int N;
    if (z < L_) {
        W = Wo + (size_t)z * D_ * D_;
        Hz = oH + (size_t)z * D_ * D_;
        Lz = oL + (size_t)z * D_ * D_;
        N = 256;
    } else {
        if (blockIdx.y >= 4) return;   // Npad=128 -> 4 col-tiles
        W = Wc; Hz = cH; Lz = cL; N = 100;
    }
    int k0 = blockIdx.x * 32, n0 = blockIdx.y * 32;
    int tx = threadIdx.x, ty = threadIdx.y;
#pragma unroll
    for (int r = 0; r < 4; r++) {
        int n = n0 + tx;
        t[ty + 8 * r][tx] = (n < N) ? W[(size_t)(k0 + ty + 8 * r) * N + n] : 0.0f;
    }
    __syncthreads();
#pragma unroll
    for (int r = 0; r < 4; r++) {
        int n = n0 + ty + 8 * r;
        int k = k0 + tx;
        float v = t[tx][ty + 8 * r];
        __nv_bfloat16 h = __float2bfloat16(v);
        __nv_bfloat16 l2 = __float2bfloat16(v - __bfloat162float(h));
        Hz[(size_t)n * D_ + k] = h;
        Lz[(size_t)n * D_ + k] = l2;
    }
}

// ====================== HMMA bf16 split-precision GEMM ====================
__device__ __forceinline__ void gemm_fill(
    uint32_t smU, int b, int kb,
    const __nv_bfloat16* __restrict__ AHi, const __nv_bfloat16* __restrict__ ALo,
    const __nv_bfloat16* __restrict__ BHi, const __nv_bfloat16* __restrict__ BLo,
    int K, int bm, int bn, int tid)
{
    const int k0 = kb * GKB;
    uint32_t aHiU = smU + b * BUFB;
    uint32_t aLoU = aHiU + APLANE;
    uint32_t bHiU = aHiU + 2 * APLANE;
    uint32_t bLoU = bHiU + BPLANE;

#pragma unroll
    for (int i = 0; i < 4; i++) {
        int j   = tid + 256 * i;
        int row = j >> 3;
        int ch  = (j & 7) << 4;
        uint32_t off = swz128((uint32_t)(row * 128 + ch));
        size_t srcb = ((size_t)(bm + row) * K + k0) * 2 + ch;
        cp_async16(aHiU + off, (const char*)AHi + srcb);
        cp_async16(aLoU + off, (const char*)ALo + srcb);
    }
#pragma unroll
    for (int i = 0; i < 2; i++) {
        int j   = tid + 256 * i;
        int row = j >> 3;
        int ch  = (j & 7) << 4;
        uint32_t off = swz128((uint32_t)(row * 128 + ch));
        size_t srcb = ((size_t)(bn + row) * K + k0) * 2 + ch;
        cp_async16(bHiU + off, (const char*)BHi + srcb);
        cp_async16(bLoU + off, (const char*)BLo + srcb);
    }
}

__device__ __forceinline__ void gemm_compute(
    uint32_t smU, int b, int m0, int n0, int lane, float (*acc)[4][4])
{
    const uint32_t aU = smU + b * BUFB;
    const uint32_t bU = aU + 2 * APLANE;

    const int a_row = m0 + (lane & 15);
    const int a_kb  = (lane >> 4) * 16;
    const int b_row = n0 + ((lane >> 4) << 3) + (lane & 7);
    const int b_kb  = ((lane >> 3) & 1) * 16;

#pragma unroll
    for (int ks = 0; ks < 4; ks++) {
        const int kbase = ks * 32;
        uint32_t ah[2][4], al[2][4], bh[2][4], bl[2][4];
#pragma unroll
        for (int mi = 0; mi < 2; mi++) {
            uint32_t off = swz128((uint32_t)((a_row + mi * 16) * 128 + kbase + a_kb));
            ldsm_x4(ah[mi], aU + off);
            ldsm_x4(al[mi], aU + APLANE + off);
        }
#pragma unroll
        for (int bi = 0; bi < 2; bi++) {
            uint32_t off = swz128((uint32_t)((b_row + bi * 16) * 128 + kbase + b_kb));
            ldsm_x4(bh[bi], bU + off);
            ldsm_x4(bl[bi], bU + BPLANE + off);
        }
#pragma unroll
        for (int mi = 0; mi < 2; mi++)
#pragma unroll
            for (int ni = 0; ni < 4; ni++) {
                uint32_t h0 = bh[ni >> 1][(ni & 1) * 2];
                uint32_t h1 = bh[ni >> 1][(ni & 1) * 2 + 1];
                uint32_t l0 = bl[ni >> 1][(ni & 1) * 2];
                uint32_t l1 = bl[ni >> 1][(ni & 1) * 2 + 1];
                mma_bf16(acc[mi][ni], ah[mi], h0, h1);
                mma_bf16(acc[mi][ni], ah[mi], l0, l1);
                mma_bf16(acc[mi][ni], al[mi], h0, h1);
            }
    }
}

__global__ __launch_bounds__(256, 2)
void gemm_tc(const __nv_bfloat16* __restrict__ AHi,
             const __nv_bfloat16* __restrict__ ALo,
             const __nv_bfloat16* __restrict__ BHi,
             const __nv_bfloat16* __restrict__ BLo,
             const float* __restrict__ bias,
             float* __restrict__ C,
             __nv_bfloat16* __restrict__ CHi,
             __nv_bfloat16* __restrict__ CLo,
             int K, int N, int relu)
{
    extern __shared__ char dsm_raw[];
    const int tid  = threadIdx.x;
    const int lane = tid & 31;
    const int wid  = tid >> 5;
    const int m0   = (wid >> 1) * 32;
    const int n0   = (wid & 1) * 32;
    const int bm   = blockIdx.y * GBM;
    const int bn   = blockIdx.x * GBN;
    const int nk   = K / GKB;

    uint32_t rawU = smem_u32(dsm_raw);
    uint32_t smU  = (rawU + 1023u) & ~1023u;

    float acc[2][4][4];
#pragma unroll
    for (int mi = 0; mi < 2; mi++)
#pragma unroll
        for (int ni = 0; ni < 4; ni++)
#pragma unroll
            for (int e = 0; e < 4; e++) acc[mi][ni][e] = 0.0f;

    gemm_fill(smU, 0, 0, AHi, ALo, BHi, BLo, K, bm, bn, tid);
    cp_commit();

    for (int kb = 0; kb < nk; kb++) {
        const int b = kb & 1;
        if (kb + 1 < nk) {
            gemm_fill(smU, b ^ 1, kb + 1, AHi, ALo, BHi, BLo, K, bm, bn, tid);
            cp_commit();
            cp_wait1();
        } else {
            cp_wait0();
        }
        __syncthreads();
        gemm_compute(smU, b, m0, n0, lane, acc);
        __syncthreads();
    }

    const int gr = lane >> 2;
    const int gc = (lane & 3) * 2;
#pragma unroll
    for (int mi = 0; mi < 2; mi++) {
        int r0 = bm + m0 + mi * 16 + gr;
#pragma unroll
        for (int ni = 0; ni < 4; ni++) {
            int c = bn + n0 + ni * 8 + gc;
            int c0s = (c < N) ? c : N - 1;
            int c1s = (c + 1 < N) ? c + 1 : N - 1;
            float v00 = acc[mi][ni][0] + bias[c0s];
            float v01 = acc[mi][ni][1] + bias[c1s];
            float v10 = acc[mi][ni][2] + bias[c0s];
            float v11 = acc[mi][ni][3] + bias[c1s];
            if (relu) {
                v00 = fmaxf(v00, 0.f); v01 = fmaxf(v01, 0.f);
                v10 = fmaxf(v10, 0.f); v11 = fmaxf(v11, 0.f);
            }
            if (CHi) {
                uint32_t h0, l0, h1, l1;
                split2(v00, v01, h0, l0);
                split2(v10, v11, h1, l1);
                *(uint32_t*)(CHi + (size_t)r0 * N + c) = h0;
                *(uint32_t*)(CLo + (size_t)r0 * N + c) = l0;
                *(uint32_t*)(CHi + (size_t)(r0 + 8) * N + c) = h1;
                *(uint32_t*)(CLo + (size_t)(r0 + 8) * N + c) = l1;
            } else if (c + 1 < N) {
                *(float2*)(C + (size_t)r0 * N + c) = make_float2(v00, v01);
                *(float2*)(C + (size_t)(r0 + 8) * N + c) = make_float2(v10, v11);
            } else if (c < N) {
                C[(size_t)r0 * N + c] = v00;
                C[(size_t)(r0 + 8) * N + c] = v10;
            }
        }
    }
}

// ========== fused GEMM (N=256) + bias + residual + LayerNorm ==============
// X <- LN(X + A*B^T + bias); also emits XH/XL bf16 planes.
// Tile 64x256, 512 threads (16 warps: 4 m-groups x 4 n-groups).
#define LN_BM 64
#define LN_AP 8192
#define LN_BP 32768
#define LN_STAGE (2*LN_AP + 2*LN_BP)   // 81920
#define LN_SMEM (2*LN_STAGE)           // 163840

__device__ __forceinline__ void ln_fill(
    uint32_t smU, int b, int kb,
    const __nv_bfloat16* __restrict__ AHi, const __nv_bfloat16* __restrict__ ALo,
    const __nv_bfloat16* __restrict__ BHi, const __nv_bfloat16* __restrict__ BLo,
    int K, int bm, int tid)
{
    const int k0 = kb * GKB;
    uint32_t aHiU = smU + b * LN_STAGE;
    uint32_t aLoU = aHiU + LN_AP;
    uint32_t bHiU = aHiU + 2 * LN_AP;
    uint32_t bLoU = bHiU + LN_BP;

    {
        int j   = tid;                    // 0..511
        int row = j >> 3;                 // 0..63
        int ch  = (j & 7) << 4;
        uint32_t off = swz128((uint32_t)(row * 128 + ch));
        size_t srcb = ((size_t)(bm + row) * K + k0) * 2 + ch;
        cp_async16(aHiU + off, (const char*)AHi + srcb);
        cp_async16(aLoU + off, (const char*)ALo + srcb);
    }
#pragma unroll
    for (int i = 0; i < 4; i++) {
        int j   = tid + 512 * i;          // 0..2047
        int row = j >> 3;                 // 0..255
        int ch  = (j & 7) << 4;
        uint32_t off = swz128((uint32_t)(row * 128 + ch));
        size_t srcb = ((size_t)row * K + k0) * 2 + ch;
        cp_async16(bHiU + off, (const char*)BHi + srcb);
        cp_async16(bLoU + off, (const char*)BLo + srcb);
    }
}

__global__ __launch_bounds__(512)
void gemm_ln(const __nv_bfloat16* __restrict__ AHi,
             const __nv_bfloat16* __restrict__ ALo,
             const __nv_bfloat16* __restrict__ BHi,
             const __nv_bfloat16* __restrict__ BLo,
             const float* __restrict__ bias,
             const float* __restrict__ g,
             const float* __restrict__ be,
             float* __restrict__ X,
             __nv_bfloat16* __restrict__ XH,
             __nv_bfloat16* __restrict__ XL,
             int K)
{
    extern __shared__ char dsm_raw[];
    __shared__ float redS[64][4], redQ[64][4];

    const int tid  = threadIdx.x;
    const int lane = tid & 31;
    const int wid  = tid >> 5;            // 0..15
    const int m0   = (wid >> 2) * 16;     // 0,16,32,48
    const int n0   = (wid & 3) * 64;      // 0,64,128,192
    const int bm   = blockIdx.x * LN_BM;
    const int nk   = K / GKB;

    uint32_t rawU = smem_u32(dsm_raw);
    uint32_t smU  = (rawU + 1023u) & ~1023u;

    float acc[8][4];
#pragma unroll
    for (int ni = 0; ni < 8; ni++)
#pragma unroll
        for (int e = 0; e < 4; e++) acc[ni][e] = 0.0f;

    ln_fill(smU, 0, 0, AHi, ALo, BHi, BLo, K, bm, tid);
    cp_commit();

    const int a_row = m0 + (lane & 15);
    const int a_kb  = (lane >> 4) * 16;
    const int b_rowL = ((lane >> 4) << 3) + (lane & 7);
    const int b_kb  = ((lane >> 3) & 1) * 16;

    for (int kb = 0; kb < nk; kb++) {
        const int b = kb & 1;
        if (kb + 1 < nk) {
            ln_fill(smU, b ^ 1, kb + 1, AHi, ALo, BHi, BLo, K, bm, tid);
            cp_commit();
            cp_wait1();
        } else {
            cp_wait0();
        }
        __syncthreads();

        const uint32_t aU = smU + b * LN_STAGE;
        const uint32_t bU = aU + 2 * LN_AP;
#pragma unroll
        for (int ks = 0; ks < 4; ks++) {
            const int kbase = ks * 32;
            uint32_t ah[4], al[4], bh[4][4], bl[4][4];
            {
                uint32_t off = swz128((uint32_t)(a_row * 128 + kbase + a_kb));
                ldsm_x4(ah, aU + off);
                ldsm_x4(al, aU + LN_AP + off);
            }
#pragma unroll
            for (int bi = 0; bi < 4; bi++) {
                uint32_t off = swz128((uint32_t)((n0 + bi * 16 + b_rowL) * 128 + kbase + b_kb));
                ldsm_x4(bh[bi], bU + off);
                ldsm_x4(bl[bi], bU + LN_BP + off);
            }
#pragma unroll
            for (int ni = 0; ni < 8; ni++) {
                uint32_t h0 = bh[ni >> 1][(ni & 1) * 2];
                uint32_t h1 = bh[ni >> 1][(ni & 1) * 2 + 1];
                uint32_t l0 = bl[ni >> 1][(ni & 1) * 2];
                uint32_t l1 = bl[ni >> 1][(ni & 1) * 2 + 1];
                mma_bf16(acc[ni], ah, h0, h1);
                mma_bf16(acc[ni], ah, l0, l1);
                mma_bf16(acc[ni], al, h0, h1);
            }
        }
        __syncthreads();
    }

    // ---- epilogue: bias + residual, row stats, LN, write ----
    const int gr = lane >> 2;
    const int tg = lane & 3;
    const int nw = wid & 3;

    int rl0 = m0 + gr;
    int rl1 = rl0 + 8;
    size_t gb0 = (size_t)(bm + rl0) * D_;
    size_t gb1 = (size_t)(bm + rl1) * D_;
    {
        float s0 = 0.f, q0 = 0.f, s1 = 0.f, q1 = 0.f;
#pragma unroll
        for (int ni = 0; ni < 8; ni++) {
            int c = n0 + ni * 8 + tg * 2;
            float2 bv = *(const float2*)(bias + c);
            float2 x0 = *(const float2*)(X + gb0 + c);
            float2 x1 = *(const float2*)(X + gb1 + c);
            acc[ni][0] += bv.x + x0.x;
            acc[ni][1] += bv.y + x0.y;
            acc[ni][2] += bv.x + x1.x;
            acc[ni][3] += bv.y + x1.y;
            s0 += acc[ni][0] + acc[ni][1];
            q0 += acc[ni][0] * acc[ni][0] + acc[ni][1] * acc[ni][1];
            s1 += acc[ni][2] + acc[ni][3];
            q1 += acc[ni][2] * acc[ni][2] + acc[ni][3] * acc[ni][3];
        }
#pragma unroll
        for (int o = 1; o <= 2; o <<= 1) {
            s0 += __shfl_xor_sync(0xFFFFFFFFu, s0, o);
            q0 += __shfl_xor_sync(0xFFFFFFFFu, q0, o);
            s1 += __shfl_xor_sync(0xFFFFFFFFu, s1, o);
            q1 += __shfl_xor_sync(0xFFFFFFFFu, q1, o);
        }
        if (tg == 0) {
            redS[rl0][nw] = s0; redQ[rl0][nw] = q0;
            redS[rl1][nw] = s1; redQ[rl1][nw] = q1;
        }
    }
    __syncthreads();

    {
        float S0 = redS[rl0][0] + redS[rl0][1] + redS[rl0][2] + redS[rl0][3];
        float Q0 = redQ[rl0][0] + redQ[rl0][1] + redQ[rl0][2] + redQ[rl0][3];
        float S1 = redS[rl1][0] + redS[rl1][1] + redS[rl1][2] + redS[rl1][3];
        float Q1 = redQ[rl1][0] + redQ[rl1][1] + redQ[rl1][2] + redQ[rl1][3];
        float mean0 = S0 * (1.0f / D_);
        float mean1 = S1 * (1.0f / D_);
        float r0 = rsqrtf(Q0 * (1.0f / D_) - mean0 * mean0 + 1e-5f);
        float r1 = rsqrtf(Q1 * (1.0f / D_) - mean1 * mean1 + 1e-5f);
#pragma unroll
        for (int ni = 0; ni < 8; ni++) {
            int c = n0 + ni * 8 + tg * 2;
            float2 gv = *(const float2*)(g + c);
            float2 bev = *(const float2*)(be + c);
            float o00 = (acc[ni][0] - mean0) * r0 * gv.x + bev.x;
            float o01 = (acc[ni][1] - mean0) * r0 * gv.y + bev.y;
            float o10 = (acc[ni][2] - mean1) * r1 * gv.x + bev.x;
            float o11 = (acc[ni][3] - mean1) * r1 * gv.y + bev.y;
            *(float2*)(X + gb0 + c) = make_float2(o00, o01);
            *(float2*)(X + gb1 + c) = make_float2(o10, o11);
            uint32_t hp, lp;
            split2(o00, o01, hp, lp);
            *(uint32_t*)(XH + gb0 + c) = hp;
            *(uint32_t*)(XL + gb0 + c) = lp;
            split2(o10, o11, hp, lp);
            *(uint32_t*)(XH + gb1 + c) = hp;
            *(uint32_t*)(XL + gb1 + c) = lp;
        }
    }
}

// ====== embedding + positions (+ bias pack) + bf16 hi/lo planes ===========
__global__ void embed_kernel(const int* __restrict__ ids,
                             const float* __restrict__ emb,
                             const float* __restrict__ bq,
                             const float* __restrict__ bk,
                             const float* __restrict__ bv,
                             float* __restrict__ bqkv,
                             float* __restrict__ X,
                             __nv_bfloat16* __restrict__ XH,
                             __nv_bfloat16* __restrict__ XL)
{
    int t = blockIdx.x;
    int d = threadIdx.x;
    if (t >= M_TOK) {
        int idx = t - M_TOK;              // 0..3L-1
        int l = idx / 3, seg = idx % 3;
        const float* src = (seg == 0) ? bq : (seg == 1) ? bk : bv;
        bqkv[l * QKV_N + seg * 256 + d] = src[l * 256 + d];
        return;
    }
    int s = t & (S_ - 1);
    int id = ids[t];
    float f = (d < D_ / 2) ? (2.0f * d) : (2.0f * (d - D_ / 2) + 1.0f);
    float inv = exp2f(-f * 13.287712379549449f / (float)D_);
    float v = emb[(size_t)id * D_ + d] + sinf((float)s * inv);
    size_t idx = (size_t)t * D_ + d;
    X[idx] = v;
    __nv_bfloat16 h = __float2bfloat16(v);
    XH[idx] = h;
    XL[idx] = __float2bfloat16(v - __bfloat162float(h));
}

// ================= tensor-core causal flash attention ====================
// 64 queries per CTA, 4 warps x 16 rows. K/V double-buffered 64-key tiles.
#define AT_PITCH 80
#define AT_QH 0
#define AT_QL 5120
#define AT_KV 10240
#define AT_BUF 20480
#define AT_SMEM (AT_KV + 2*AT_BUF)   // 51200
#define SCL2E 0.2550348243f          // log2(e)/sqrt(32)

__device__ __forceinline__ void attn_fill_kv(
    uint32_t smU, int buf,
    const __nv_bfloat16* __restrict__ Ph, const __nv_bfloat16* __restrict__ Pl,
    size_t rowbase, int kt, int h, int tid)
{
    uint32_t base = smU + AT_KV + buf * AT_BUF;
#pragma unroll
    for (int i = 0; i < 2; i++) {
        int j = tid + 128 * i;
        int row = j >> 2, ch = (j & 3) * 16;
        size_t gk = ((rowbase + kt + row) * QKV_N + 256 + h * DH_) * 2 + ch;
        size_t gv = gk + 512;
        uint32_t d = row * AT_PITCH + ch;
        cp_async16(base + d,         (const char*)Ph + gk);
        cp_async16(base + 5120 + d,  (const char*)Pl + gk);
        cp_async16(base + 10240 + d, (const char*)Ph + gv);
        cp_async16(base + 15360 + d, (const char*)Pl + gv);
    }
}

__global__ __launch_bounds__(128)
void attn_tc(const __nv_bfloat16* __restrict__ Ph,
             const __nv_bfloat16* __restrict__ Pl,
             __nv_bfloat16* __restrict__ YH, __nv_bfloat16* __restrict__ YL,
             const int* __restrict__ tsl)
{
    extern __shared__ char asmem[];
    const int tid = threadIdx.x, lane = tid & 31, w = tid >> 5;
    const int qblk = (gridDim.x - 1) - blockIdx.x;   // longest-first
    const int h = blockIdx.y, b = blockIdx.z;
    const int q0 = qblk * 64;
    const int len = tsl[b];
    const int gr = lane >> 2, tg = lane & 3;
    const uint32_t smU = smem_u32(asmem);
    const size_t rowbase = (size_t)b * S_;

    // stage Q hi/lo (64 rows)
#pragma unroll
    for (int i = 0; i < 2; i++) {
        int j = tid + 128 * i;
        int row = j >> 2, ch = (j & 3) * 16;
        size_t src = ((rowbase + q0 + row) * QKV_N + h * DH_) * 2 + ch;
        cp_async16(smU + AT_QH + row * AT_PITCH + ch, (const char*)Ph + src);
        cp_async16(smU + AT_QL + row * AT_PITCH + ch, (const char*)Pl + src);
    }
    attn_fill_kv(smU, 0, Ph, Pl, rowbase, 0, h, tid);
    cp_commit();
    cp_wait0();
    __syncthreads();

    // Q fragments (registers for whole kernel); warp rows q0 + w*16 ..
    uint32_t qfh[2][4], qfl[2][4];
    {
        int r8 = (lane & 7) + ((lane >> 3) & 1) * 8;
        int cb = ((lane >> 4) & 1) * 16;
#pragma unroll
        for (int kk = 0; kk < 2; kk++) {
            uint32_t off = (uint32_t)(w * 16 + r8) * AT_PITCH + kk * 32 + cb;
            ldsm_x4(qfh[kk], smU + AT_QH + off);
            ldsm_x4(qfl[kk], smU + AT_QL + off);
        }
    }

    float o[4][4];
    float mrow[2] = {-1e30f, -1e30f}, lrow[2] = {0.f, 0.f};
#pragma unroll
    for (int nd = 0; nd < 4; nd++)
#pragma unroll
        for (int e = 0; e < 4; e++) o[nd][e] = 0.f;

    const int qw0 = q0 + w * 16;
    const int nt = qblk + 1;

    for (int t = 0; t < nt; t++) {
        const int kt = t * 64;
        if (t + 1 < nt) {
            attn_fill_kv(smU, (t + 1) & 1, Ph, Pl, rowbase, kt + 64, h, tid);
            cp_commit();
            cp_wait1();
        } else {
            cp_wait0();
        }
        __syncthreads();

        const uint32_t kb = smU + AT_KV + (t & 1) * AT_BUF;
        const uint32_t vb = kb + 10240;

        // scores: S = Qh*Kh + Qh*Kl + Ql*Kh
        float s[8][4];
#pragma unroll
        for (int ni = 0; ni < 8; ni++)
#pragma unroll
            for (int e = 0; e < 4; e++) s[ni][e] = 0.f;
        {
            int l7 = lane & 7;
            int hb = ((lane >> 3) & 1) * 16;
#pragma unroll
            for (int kk = 0; kk < 2; kk++)
#pragma unroll
                for (int ni = 0; ni < 8; ni++) {
                    uint32_t off = (uint32_t)(ni * 8 + l7) * AT_PITCH + kk * 32 + hb;
                    uint32_t khf[2], klf[2];
                    ldsm_x2(khf, kb + off);
                    ldsm_x2(klf, kb + 5120 + off);
                    mma_bf16(s[ni], qfh[kk], khf[0], khf[1]);
                    mma_bf16(s[ni], qfh[kk], klf[0], klf[1]);
                    mma_bf16(s[ni], qfl[kk], khf[0], khf[1]);
                }
        }

        // causal/length mask (only the diagonal tile needs it)
        if (kt + 63 > qw0 || kt + 64 > len) {
            int r0 = qw0 + gr, r1 = r0 + 8;
#pragma unroll
            for (int ni = 0; ni < 8; ni++) {
                int c0 = kt + ni * 8 + tg * 2, c1 = c0 + 1;
                if (c0 > r0 || c0 >= len) s[ni][0] = -1e30f;
                if (c1 > r0 || c1 >= len) s[ni][1] = -1e30f;
                if (c0 > r1 || c0 >= len) s[ni][2] = -1e30f;
                if (c1 > r1 || c1 >= len) s[ni][3] = -1e30f;
            }
        }

        // row max
        float mx[2] = {-1e30f, -1e30f};
#pragma unroll
        for (int ni = 0; ni < 8; ni++) {
            mx[0] = fmaxf(mx[0], fmaxf(s[ni][0], s[ni][1]));
            mx[1] = fmaxf(mx[1], fmaxf(s[ni][2], s[ni][3]));
        }
#pragma unroll
        for (int hh = 0; hh < 2; hh++) {
            float v = mx[hh];
            v = fmaxf(v, __shfl_xor_sync(0xFFFFFFFFu, v, 1));
            v = fmaxf(v, __shfl_xor_sync(0xFFFFFFFFu, v, 2));
            mx[hh] = v;
        }

        // online softmax update
        float corr[2];
#pragma unroll
        for (int hh = 0; hh < 2; hh++) {
            float mn = fmaxf(mrow[hh], mx[hh]);
            corr[hh] = exp2f((mrow[hh] - mn) * SCL2E);
            mrow[hh] = mn;
            lrow[hh] *= corr[hh];
        }
#pragma unroll
        for (int nd = 0; nd < 4; nd++) {
            o[nd][0] *= corr[0];
            o[nd][1] *= corr[0];
            o[nd][2] *= corr[1];
            o[nd][3] *= corr[1];
        }
        float ls[2] = {0.f, 0.f};
#pragma unroll
        for (int ni = 0; ni < 8; ni++) {
            float p0 = exp2f((s[ni][0] - mrow[0]) * SCL2E);
            float p1 = exp2f((s[ni][1] - mrow[0]) * SCL2E);
            float p2 = exp2f((s[ni][2] - mrow[1]) * SCL2E);
            float p3 = exp2f((s[ni][3] - mrow[1]) * SCL2E);
            s[ni][0] = p0; s[ni][1] = p1; s[ni][2] = p2; s[ni][3] = p3;
            ls[0] += p0 + p1;
            ls[1] += p2 + p3;
        }
#pragma unroll
        for (int hh = 0; hh < 2; hh++) {
            float v = ls[hh];
            v += __shfl_xor_sync(0xFFFFFFFFu, v, 1);
            v += __shfl_xor_sync(0xFFFFFFFFu, v, 2);
            lrow[hh] += v;
        }

        // O += Ph*Vh + Ph*Vl + Pl*Vh
        int l15 = lane & 15;
#pragma unroll
        for (int j = 0; j < 4; j++) {
            uint32_t pah[4], pal[4];
            split2(s[2*j][0],   s[2*j][1],   pah[0], pal[0]);
            split2(s[2*j][2],   s[2*j][3],   pah[1], pal[1]);
            split2(s[2*j+1][0], s[2*j+1][1], pah[2], pal[2]);
            split2(s[2*j+1][2], s[2*j+1][3], pah[3], pal[3]);
#pragma unroll
            for (int nd = 0; nd < 4; nd++) {
                uint32_t off = (uint32_t)(16 * j + l15) * AT_PITCH + nd * 16;
                uint32_t vhf[2], vlf[2];
                ldsm_x2t(vhf, vb + off);
                ldsm_x2t(vlf, vb + 5120 + off);
                mma_bf16(o[nd], pah, vhf[0], vhf[1]);
                mma_bf16(o[nd], pah, vlf[0], vlf[1]);
                mma_bf16(o[nd], pal, vhf[0], vhf[1]);
            }
        }
        __syncthreads();
    }

    // normalize + write hi/lo planes
    int r0 = qw0 + gr, r1 = r0 + 8;
    float inv0 = (r0 < len && lrow[0] > 0.f) ? 1.0f / lrow[0] : 0.f;
    float inv1 = (r1 < len && lrow[1] > 0.f) ? 1.0f / lrow[1] : 0.f;
#pragma unroll
    for (int nd = 0; nd < 4; nd++) {
        int col = h * DH_ + nd * 8 + tg * 2;
        uint32_t hp, lp;
        split2(o[nd][0] * inv0, o[nd][1] * inv0, hp, lp);
        *(uint32_t*)(YH + (rowbase + r0) * D_ + col) = hp;
        *(uint32_t*)(YL + (rowbase + r0) * D_ + col) = lp;
        split2(o[nd][2] * inv1, o[nd][3] * inv1, hp, lp);
        *(uint32_t*)(YH + (rowbase + r1) * D_ + col) = hp;
        *(uint32_t*)(YL + (rowbase + r1) * D_ + col) = lp;
    }
}

// =========================== launcher ====================================
extern "C" void kernel_launch(void* const* d_in, const int* in_sizes, int n_in,
                              void* d_out, int out_size)
{
    const int*   ids = (const int*)  d_in[0];
    const int*   tsl = (const int*)  d_in[1];
    const float* emb = (const float*)d_in[2];
    const float* Wq  = (const float*)d_in[3];
    const float* bq  = (const float*)d_in[4];
    const float* Wk  = (const float*)d_in[5];
    const float* bk  = (const float*)d_in[6];
    const float* Wv  = (const float*)d_in[7];
    const float* bv  = (const float*)d_in[8];
    const float* Wo  = (const float*)d_in[9];
    const float* bo  = (const float*)d_in[10];
    const float* W1  = (const float*)d_in[11];
    const float* b1  = (const float*)d_in[12];
    const float* W2  = (const float*)d_in[13];
    const float* b2  = (const float*)d_in[14];
    const float* g1  = (const float*)d_in[15];
    const float* be1 = (const float*)d_in[16];
    const float* g2  = (const float*)d_in[17];
    const float* be2 = (const float*)d_in[18];
    const float* Wc  = (const float*)d_in[19];
    const float* bc  = (const float*)d_in[20];
    float* out = (float*)d_out;

    float *x, *bqkv;
    cudaGetSymbolAddress((void**)&x,   g_x);
    cudaGetSymbolAddress((void**)&bqkv, g_bqkv);

    __nv_bfloat16 *xh, *xl, *yh, *yl, *ffh, *ffl, *qkvh, *qkvl;
    cudaGetSymbolAddress((void**)&xh,  g_xh);   cudaGetSymbolAddress((void**)&xl,  g_xl);
    cudaGetSymbolAddress((void**)&yh,  g_yh);   cudaGetSymbolAddress((void**)&yl,  g_yl);
    cudaGetSymbolAddress((void**)&ffh, g_ffh);  cudaGetSymbolAddress((void**)&ffl, g_ffl);
    cudaGetSymbolAddress((void**)&qkvh, g_qkvh); cudaGetSymbolAddress((void**)&qkvl, g_qkvl);

    __nv_bfloat16 *qkvTh, *qkvTl, *oTh, *oTl, *w1h, *w1l, *w2h, *w2l, *wch, *wcl;
    cudaGetSymbolAddress((void**)&qkvTh, g_qkvT_hi); cudaGetSymbolAddress((void**)&qkvTl, g_qkvT_lo);
    cudaGetSymbolAddress((void**)&oTh,  g_oT_hi);    cudaGetSymbolAddress((void**)&oTl,  g_oT_lo);
    cudaGetSymbolAddress((void**)&w1h,  g_1T_hi);    cudaGetSymbolAddress((void**)&w1l,  g_1T_lo);
    cudaGetSymbolAddress((void**)&w2h,  g_2T_hi);    cudaGetSymbolAddress((void**)&w2l,  g_2T_lo);
    cudaGetSymbolAddress((void**)&wch,  g_cT_hi);    cudaGetSymbolAddress((void**)&wcl,  g_cT_lo);

    cudaFuncSetAttribute((const void*)gemm_tc,
                         cudaFuncAttributeMaxDynamicSharedMemorySize, GEMM_SMEM);
    cudaFuncSetAttribute((const void*)gemm_ln,
                         cudaFuncAttributeMaxDynamicSharedMemorySize, LN_SMEM);
    cudaFuncSetAttribute((const void*)attn_tc,
                         cudaFuncAttributeMaxDynamicSharedMemorySize, AT_SMEM);

    dim3 tb(32, 8);
    // exactly 5 prep launches so launch #6 is the QKV GEMM (ncu -s 5 -c 1)
    embed_kernel<<<M_TOK + 3 * L_, 256>>>(ids, emb, bq, bk, bv, bqkv, x, xh, xl);
    convert_qkv_kernel<<<dim3(8, 8, 3 * L_), tb>>>(Wq, Wk, Wv, qkvTh, qkvTl);
    convert_oc_kernel<<<dim3(8, 8, L_ + 1), tb>>>(Wo, Wc, oTh, oTl, wch, wcl);
    convert_w_kernel<<<dim3(8, 32, L_), tb>>>(W1, w1h, w1l, 256, 1024, 1024);
    convert_w_kernel<<<dim3(32, 8, L_), tb>>>(W2, w2h, w2l, 1024, 256, 256);

    dim3 gQKV(QKV_N / GBN, M_TOK / GBM);
    dim3 gF  (DFF_ / GBN,  M_TOK / GBM);
    dim3 gC  (2,           M_TOK / GBM);
    const int gLN = M_TOK / LN_BM;   // 128

    for (int l = 0; l < L_; l++) {
        size_t qoff  = (size_t)l * QKV_N * D_;
        size_t ooff  = (size_t)l * D_ * D_;
        size_t w1off = (size_t)l * DFF_ * D_;

        gemm_tc<<<gQKV, 256, GEMM_SMEM>>>(xh, xl, qkvTh + qoff, qkvTl + qoff,
                                          bqkv + l * QKV_N, 0, qkvh, qkvl, D_, QKV_N, 0);
        attn_tc<<<dim3(S_ / 64, H_, B_), 128, AT_SMEM>>>(qkvh, qkvl, yh, yl, tsl);

        gemm_ln<<<gLN, 512, LN_SMEM>>>(yh, yl, oTh + ooff, oTl + ooff,
                                       bo + l * D_, g1 + l * D_, be1 + l * D_,
                                       x, xh, xl, D_);

        gemm_tc<<<gF, 256, GEMM_SMEM>>>(xh, xl, w1h + w1off, w1l + w1off,
                                        b1 + l * DFF_, 0, ffh, ffl, D_, DFF_, 1);

        gemm_ln<<<gLN, 512, LN_SMEM>>>(ffh, ffl, w2h + w1off, w2l + w1off,
                                       b2 + l * D_, g2 + l * D_, be2 + l * D_,
                                       x, xh, xl, DFF_);
    }

    gemm_tc<<<gC, 256, GEMM_SMEM>>>(xh, xl, wch, wcl, bc, out, 0, 0, D_, V_, 0);
}

// round 8
// speedup vs baseline: 4.3192x; 1.3209x over previous
#include <cuda_runtime.h>
#include <cuda_fp16.h>
#include <math.h>
#include <stdint.h>

// Problem constants
#define B_  8
#define S_  1024
#define D_  256
#define H_  8
#define DH_ 32
#define L_  4
#define V_  100
#define DFF_ 1024
#define M_TOK (B_ * S_)   // 8192
#define QKV_N 768

// -------- scratch (static device globals; no runtime allocation) --------
__device__ float g_x [M_TOK * D_];

// activation fp16 hi/lo planes ([M,K] row-major)
__device__ __half g_xh  [M_TOK * D_],    g_xl  [M_TOK * D_];
__device__ __half g_yh  [M_TOK * D_],    g_yl  [M_TOK * D_];
__device__ __half g_ffh [M_TOK * DFF_],  g_ffl [M_TOK * DFF_];
__device__ __half g_qkvh[M_TOK * QKV_N], g_qkvl[M_TOK * QKV_N];

// K-major ([N,K]) fp16 weight planes (single-plane except classifier)
__device__ __half g_qkvT[L_*QKV_N*D_];
__device__ __half g_oT  [L_*D_*D_];
__device__ __half g_1T  [L_*DFF_*D_];
__device__ __half g_2T  [L_*D_*DFF_];
__device__ __half g_cT_hi[128*D_], g_cT_lo[128*D_];
__device__ float g_bqkv[L_ * QKV_N];

// =========================== PTX helpers ==================================
__device__ __forceinline__ uint32_t smem_u32(const void* p) {
    uint32_t r;
    asm("{ .reg .u64 t; cvta.to.shared.u64 t, %1; cvt.u32.u64 %0, t; }"
        : "=r"(r) : "l"(p));
    return r;
}
__device__ __forceinline__ void cp_async16(uint32_t dst, const void* src) {
    asm volatile("cp.async.cg.shared.global [%0], [%1], 16;"
                 :: "r"(dst), "l"(src));
}
__device__ __forceinline__ void cp_commit() {
    asm volatile("cp.async.commit_group;" ::: "memory");
}
__device__ __forceinline__ void cp_wait1() {
    asm volatile("cp.async.wait_group 1;" ::: "memory");
}
__device__ __forceinline__ void cp_wait0() {
    asm volatile("cp.async.wait_group 0;" ::: "memory");
}
__device__ __forceinline__ void ldsm_x4(uint32_t* r, uint32_t addr) {
    asm volatile("ldmatrix.sync.aligned.m8n8.x4.shared.b16 {%0,%1,%2,%3}, [%4];"
                 : "=r"(r[0]), "=r"(r[1]), "=r"(r[2]), "=r"(r[3]) : "r"(addr));
}
__device__ __forceinline__ void ldsm_x2(uint32_t* r, uint32_t addr) {
    asm volatile("ldmatrix.sync.aligned.m8n8.x2.shared.b16 {%0,%1}, [%2];"
                 : "=r"(r[0]), "=r"(r[1]) : "r"(addr));
}
__device__ __forceinline__ void ldsm_x2t(uint32_t* r, uint32_t addr) {
    asm volatile("ldmatrix.sync.aligned.m8n8.x2.trans.shared.b16 {%0,%1}, [%2];"
                 : "=r"(r[0]), "=r"(r[1]) : "r"(addr));
}
__device__ __forceinline__ void mma_f16(float* d, const uint32_t* a,
                                        uint32_t b0, uint32_t b1) {
    asm volatile(
        "mma.sync.aligned.m16n8k16.row.col.f32.f16.f16.f32 "
        "{%0,%1,%2,%3}, {%4,%5,%6,%7}, {%8,%9}, {%0,%1,%2,%3};"
        : "+f"(d[0]), "+f"(d[1]), "+f"(d[2]), "+f"(d[3])
        : "r"(a[0]), "r"(a[1]), "r"(a[2]), "r"(a[3]), "r"(b0), "r"(b1));
}
__device__ __forceinline__ uint32_t swz128(uint32_t x) {
    return x ^ ((x >> 3) & 0x70u);
}
__device__ __forceinline__ uint32_t pack_h2(__half a, __half b) {
    __half2 t(a, b);
    return *reinterpret_cast<uint32_t*>(&t);
}
__device__ __forceinline__ void split2h(float a, float b, uint32_t& hi, uint32_t& lo) {
    __half h0 = __float2half_rn(a);
    __half h1 = __float2half_rn(b);
    __half l0 = __float2half_rn(a - __half2float(h0));
    __half l1 = __float2half_rn(b - __half2float(h1));
    hi = pack_h2(h0, h1);
    lo = pack_h2(l0, l1);
}

// ===================== GEMM tiling constants ==============================
#define GBM 128
#define GBN 64
#define GKB 64
#define APLANE 16384     // 128 rows x 128B
#define BPLANE 8192      // 64 rows x 128B
#define BUFB (2*APLANE + 2*BPLANE)   // aHi|aLo|bHi|bLo(optional)
#define GEMM_SMEM (2*BUFB + 1024)

// ======== weight transpose + fp16 convert kernels =========================
// generic: W[K,N] -> WT[Npad,K] single fp16 plane
__global__ void convert_w_kernel(const float* __restrict__ W,
                                 __half* __restrict__ Hi,
                                 int K, int N, int Npad)
{
    __shared__ float t[32][33];
    const float* Wz = W + (size_t)blockIdx.z * K * N;
    __half* Hz = Hi + (size_t)blockIdx.z * Npad * K;
    int k0 = blockIdx.x * 32, n0 = blockIdx.y * 32;
    int tx = threadIdx.x, ty = threadIdx.y;
#pragma unroll
    for (int r = 0; r < 4; r++) {
        int k = k0 + ty + 8 * r;
        int n = n0 + tx;
        t[ty + 8 * r][tx] = (n < N) ? Wz[(size_t)k * N + n] : 0.0f;
    }
    __syncthreads();
#pragma unroll
    for (int r = 0; r < 4; r++) {
        int n = n0 + ty + 8 * r;
        int k = k0 + tx;
        Hz[(size_t)n * K + k] = __float2half_rn(t[tx][ty + 8 * r]);
    }
}

// merged Q/K/V converts
__global__ void convert_qkv_kernel(const float* __restrict__ Wq,
                                   const float* __restrict__ Wk,
                                   const float* __restrict__ Wv,
                                   __half* __restrict__ Hi)
{
    __shared__ float t[32][33];
    int z = blockIdx.z;
    int src = z / L_, l = z % L_;
    const float* W = ((src == 0) ? Wq : (src == 1) ? Wk : Wv) + (size_t)l * D_ * D_;
    __half* Hz = Hi + (size_t)l * QKV_N * D_ + (size_t)src * 256 * D_;
    int k0 = blockIdx.x * 32, n0 = blockIdx.y * 32;
    int tx = threadIdx.x, ty = threadIdx.y;
#pragma unroll
    for (int r = 0; r < 4; r++)
        t[ty + 8 * r][tx] = W[(size_t)(k0 + ty + 8 * r) * D_ + n0 + tx];
    __syncthreads();
#pragma unroll
    for (int r = 0; r < 4; r++) {
        int n = n0 + ty + 8 * r;
        int k = k0 + tx;
        Hz[(size_t)n * D_ + k] = __float2half_rn(t[tx][ty + 8 * r]);
    }
}

// merged Wo (z<L, single plane) + classifier Wc (z==L, hi/lo planes)
__global__ void convert_oc_kernel(const float* __restrict__ Wo,
                                  const float* __restrict__ Wc,
                                  __half* __restrict__ oH,
                                  __half* __restrict__ cH,
                                  __half* __restrict__ cL)
{
    __shared__ float t[32][33];
    int z = blockIdx.z;
    int k0 = blockIdx.x * 32, n0 = blockIdx.y * 32;
    int tx = threadIdx.x, ty = threadIdx.y;
    if (z < L_) {
        const float* W = Wo + (size_t)z * D_ * D_;
        __half* Hz = oH + (size_t)z * D_ * D_;
#pragma unroll
        for (int r = 0; r < 4; r++)
            t[ty + 8 * r][tx] = W[(size_t)(k0 + ty + 8 * r) * D_ + n0 + tx];
        __syncthreads();
#pragma unroll
        for (int r = 0; r < 4; r++) {
            int n = n0 + ty + 8 * r;
            int k = k0 + tx;
            Hz[(size_t)n * D_ + k] = __float2half_rn(t[tx][ty + 8 * r]);
        }
    } else {
        if (blockIdx.y >= 4) return;   // Npad=128 -> 4 col-tiles
#pragma unroll
        for (int r = 0; r < 4; r++) {
            int n = n0 + tx;
            t[ty + 8 * r][tx] = (n < V_) ? Wc[(size_t)(k0 + ty + 8 * r) * V_ + n] : 0.0f;
        }
        __syncthreads();
#pragma unroll
        for (int r = 0; r < 4; r++) {
            int n = n0 + ty + 8 * r;
            int k = k0 + tx;
            float v = t[tx][ty + 8 * r];
            __half h = __float2half_rn(v);
            cH[(size_t)n * D_ + k] = h;
            cL[(size_t)n * D_ + k] = __float2half_rn(v - __half2float(h));
        }
    }
}

// ====================== HMMA fp16 split-precision GEMM ====================
// C = A*B^T + bias. A: [M,K] fp16 hi/lo planes. B: [Npad,K] fp16 (optional lo).
__device__ __forceinline__ void gemm_fill(
    uint32_t smU, int b, int kb,
    const __half* __restrict__ AHi, const __half* __restrict__ ALo,
    const __half* __restrict__ BHi, const __half* __restrict__ BLo,
    int K, int bm, int bn, int tid)
{
    const int k0 = kb * GKB;
    uint32_t aHiU = smU + b * BUFB;
    uint32_t aLoU = aHiU + APLANE;
    uint32_t bHiU = aHiU + 2 * APLANE;
    uint32_t bLoU = bHiU + BPLANE;

#pragma unroll
    for (int i = 0; i < 4; i++) {
        int j   = tid + 256 * i;
        int row = j >> 3;
        int ch  = (j & 7) << 4;
        uint32_t off = swz128((uint32_t)(row * 128 + ch));
        size_t srcb = ((size_t)(bm + row) * K + k0) * 2 + ch;
        cp_async16(aHiU + off, (const char*)AHi + srcb);
        cp_async16(aLoU + off, (const char*)ALo + srcb);
    }
#pragma unroll
    for (int i = 0; i < 2; i++) {
        int j   = tid + 256 * i;
        int row = j >> 3;
        int ch  = (j & 7) << 4;
        uint32_t off = swz128((uint32_t)(row * 128 + ch));
        size_t srcb = ((size_t)(bn + row) * K + k0) * 2 + ch;
        cp_async16(bHiU + off, (const char*)BHi + srcb);
        if (BLo) cp_async16(bLoU + off, (const char*)BLo + srcb);
    }
}

template<bool THREE>
__device__ __forceinline__ void gemm_compute(
    uint32_t smU, int b, int m0, int n0, int lane, float (*acc)[4][4])
{
    const uint32_t aU = smU + b * BUFB;
    const uint32_t bU = aU + 2 * APLANE;

    const int a_row = m0 + (lane & 15);
    const int a_kb  = (lane >> 4) * 16;
    const int b_row = n0 + ((lane >> 4) << 3) + (lane & 7);
    const int b_kb  = ((lane >> 3) & 1) * 16;

#pragma unroll
    for (int ks = 0; ks < 4; ks++) {
        const int kbase = ks * 32;
        uint32_t ah[2][4], al[2][4], bh[2][4], bl[2][4];
#pragma unroll
        for (int mi = 0; mi < 2; mi++) {
            uint32_t off = swz128((uint32_t)((a_row + mi * 16) * 128 + kbase + a_kb));
            ldsm_x4(ah[mi], aU + off);
            ldsm_x4(al[mi], aU + APLANE + off);
        }
#pragma unroll
        for (int bi = 0; bi < 2; bi++) {
            uint32_t off = swz128((uint32_t)((b_row + bi * 16) * 128 + kbase + b_kb));
            ldsm_x4(bh[bi], bU + off);
            if (THREE) ldsm_x4(bl[bi], bU + BPLANE + off);
        }
#pragma unroll
        for (int mi = 0; mi < 2; mi++)
#pragma unroll
            for (int ni = 0; ni < 4; ni++) {
                uint32_t h0 = bh[ni >> 1][(ni & 1) * 2];
                uint32_t h1 = bh[ni >> 1][(ni & 1) * 2 + 1];
                mma_f16(acc[mi][ni], ah[mi], h0, h1);
                mma_f16(acc[mi][ni], al[mi], h0, h1);
                if (THREE) {
                    uint32_t l0 = bl[ni >> 1][(ni & 1) * 2];
                    uint32_t l1 = bl[ni >> 1][(ni & 1) * 2 + 1];
                    mma_f16(acc[mi][ni], ah[mi], l0, l1);
                }
            }
    }
}

__global__ __launch_bounds__(256, 2)
void gemm_tc(const __half* __restrict__ AHi,
             const __half* __restrict__ ALo,
             const __half* __restrict__ BHi,
             const __half* __restrict__ BLo,
             const float* __restrict__ bias,
             float* __restrict__ C,
             __half* __restrict__ CHi,
             __half* __restrict__ CLo,
             int K, int N, int relu)
{
    extern __shared__ char dsm_raw[];
    const int tid  = threadIdx.x;
    const int lane = tid & 31;
    const int wid  = tid >> 5;
    const int m0   = (wid >> 1) * 32;
    const int n0   = (wid & 1) * 32;
    const int bm   = blockIdx.y * GBM;
    const int bn   = blockIdx.x * GBN;
    const int nk   = K / GKB;
    const bool three = (BLo != 0);

    uint32_t rawU = smem_u32(dsm_raw);
    uint32_t smU  = (rawU + 1023u) & ~1023u;

    float acc[2][4][4];
#pragma unroll
    for (int mi = 0; mi < 2; mi++)
#pragma unroll
        for (int ni = 0; ni < 4; ni++)
#pragma unroll
            for (int e = 0; e < 4; e++) acc[mi][ni][e] = 0.0f;

    gemm_fill(smU, 0, 0, AHi, ALo, BHi, BLo, K, bm, bn, tid);
    cp_commit();

    for (int kb = 0; kb < nk; kb++) {
        const int b = kb & 1;
        if (kb + 1 < nk) {
            gemm_fill(smU, b ^ 1, kb + 1, AHi, ALo, BHi, BLo, K, bm, bn, tid);
            cp_commit();
            cp_wait1();
        } else {
            cp_wait0();
        }
        __syncthreads();
        if (three) gemm_compute<true >(smU, b, m0, n0, lane, acc);
        else       gemm_compute<false>(smU, b, m0, n0, lane, acc);
        __syncthreads();
    }

    const int gr = lane >> 2;
    const int gc = (lane & 3) * 2;
#pragma unroll
    for (int mi = 0; mi < 2; mi++) {
        int r0 = bm + m0 + mi * 16 + gr;
#pragma unroll
        for (int ni = 0; ni < 4; ni++) {
            int c = bn + n0 + ni * 8 + gc;
            int c0s = (c < N) ? c : N - 1;
            int c1s = (c + 1 < N) ? c + 1 : N - 1;
            float v00 = acc[mi][ni][0] + bias[c0s];
            float v01 = acc[mi][ni][1] + bias[c1s];
            float v10 = acc[mi][ni][2] + bias[c0s];
            float v11 = acc[mi][ni][3] + bias[c1s];
            if (relu) {
                v00 = fmaxf(v00, 0.f); v01 = fmaxf(v01, 0.f);
                v10 = fmaxf(v10, 0.f); v11 = fmaxf(v11, 0.f);
            }
            if (CHi) {
                uint32_t h0, l0, h1, l1;
                split2h(v00, v01, h0, l0);
                split2h(v10, v11, h1, l1);
                *(uint32_t*)(CHi + (size_t)r0 * N + c) = h0;
                *(uint32_t*)(CLo + (size_t)r0 * N + c) = l0;
                *(uint32_t*)(CHi + (size_t)(r0 + 8) * N + c) = h1;
                *(uint32_t*)(CLo + (size_t)(r0 + 8) * N + c) = l1;
            } else if (c + 1 < N) {
                *(float2*)(C + (size_t)r0 * N + c) = make_float2(v00, v01);
                *(float2*)(C + (size_t)(r0 + 8) * N + c) = make_float2(v10, v11);
            } else if (c < N) {
                C[(size_t)r0 * N + c] = v00;
                C[(size_t)(r0 + 8) * N + c] = v10;
            }
        }
    }
}

// ========== fused GEMM (N=256) + bias + residual + LayerNorm ==============
// X <- LN(X + A*B^T + bias); also emits XH/XL fp16 planes.
// Tile 64x256, 512 threads (16 warps: 4 m-groups x 4 n-groups).
#define LN_BM 64
#define LN_AP 8192
#define LN_BP 32768
#define LN_STAGE (2*LN_AP + LN_BP)     // 49152
#define LN_SMEM (2*LN_STAGE)           // 98304

__device__ __forceinline__ void ln_fill(
    uint32_t smU, int b, int kb,
    const __half* __restrict__ AHi, const __half* __restrict__ ALo,
    const __half* __restrict__ BHi,
    int K, int bm, int tid)
{
    const int k0 = kb * GKB;
    uint32_t aHiU = smU + b * LN_STAGE;
    uint32_t aLoU = aHiU + LN_AP;
    uint32_t bHiU = aHiU + 2 * LN_AP;

    {
        int row = tid >> 3;               // 0..63
        int ch  = (tid & 7) << 4;
        uint32_t off = swz128((uint32_t)(row * 128 + ch));
        size_t srcb = ((size_t)(bm + row) * K + k0) * 2 + ch;
        cp_async16(aHiU + off, (const char*)AHi + srcb);
        cp_async16(aLoU + off, (const char*)ALo + srcb);
    }
#pragma unroll
    for (int i = 0; i < 4; i++) {
        int j   = tid + 512 * i;          // 0..2047
        int row = j >> 3;                 // 0..255
        int ch  = (j & 7) << 4;
        uint32_t off = swz128((uint32_t)(row * 128 + ch));
        size_t srcb = ((size_t)row * K + k0) * 2 + ch;
        cp_async16(bHiU + off, (const char*)BHi + srcb);
    }
}

__global__ __launch_bounds__(512)
void gemm_ln(const __half* __restrict__ AHi,
             const __half* __restrict__ ALo,
             const __half* __restrict__ BHi,
             const float* __restrict__ bias,
             const float* __restrict__ g,
             const float* __restrict__ be,
             float* __restrict__ X,
             __half* __restrict__ XH,
             __half* __restrict__ XL,
             int K)
{
    extern __shared__ char dsm_raw[];
    __shared__ float redS[64][4], redQ[64][4];

    const int tid  = threadIdx.x;
    const int lane = tid & 31;
    const int wid  = tid >> 5;            // 0..15
    const int m0   = (wid >> 2) * 16;     // 0,16,32,48
    const int n0   = (wid & 3) * 64;      // 0,64,128,192
    const int bm   = blockIdx.x * LN_BM;
    const int nk   = K / GKB;

    uint32_t rawU = smem_u32(dsm_raw);
    uint32_t smU  = (rawU + 1023u) & ~1023u;

    float acc[8][4];
#pragma unroll
    for (int ni = 0; ni < 8; ni++)
#pragma unroll
        for (int e = 0; e < 4; e++) acc[ni][e] = 0.0f;

    ln_fill(smU, 0, 0, AHi, ALo, BHi, K, bm, tid);
    cp_commit();

    const int a_row = m0 + (lane & 15);
    const int a_kb  = (lane >> 4) * 16;
    const int b_rowL = ((lane >> 4) << 3) + (lane & 7);
    const int b_kb  = ((lane >> 3) & 1) * 16;

    for (int kb = 0; kb < nk; kb++) {
        const int b = kb & 1;
        if (kb + 1 < nk) {
            ln_fill(smU, b ^ 1, kb + 1, AHi, ALo, BHi, K, bm, tid);
            cp_commit();
            cp_wait1();
        } else {
            cp_wait0();
        }
        __syncthreads();

        const uint32_t aU = smU + b * LN_STAGE;
        const uint32_t bU = aU + 2 * LN_AP;
#pragma unroll
        for (int ks = 0; ks < 4; ks++) {
            const int kbase = ks * 32;
            uint32_t ah[4], al[4], bh[4][4];
            {
                uint32_t off = swz128((uint32_t)(a_row * 128 + kbase + a_kb));
                ldsm_x4(ah, aU + off);
                ldsm_x4(al, aU + LN_AP + off);
            }
#pragma unroll
            for (int bi = 0; bi < 4; bi++) {
                uint32_t off = swz128((uint32_t)((n0 + bi * 16 + b_rowL) * 128 + kbase + b_kb));
                ldsm_x4(bh[bi], bU + off);
            }
#pragma unroll
            for (int ni = 0; ni < 8; ni++) {
                uint32_t h0 = bh[ni >> 1][(ni & 1) * 2];
                uint32_t h1 = bh[ni >> 1][(ni & 1) * 2 + 1];
                mma_f16(acc[ni], ah, h0, h1);
                mma_f16(acc[ni], al, h0, h1);
            }
        }
        __syncthreads();
    }

    // ---- epilogue: bias + residual, row stats, LN, write ----
    const int gr = lane >> 2;
    const int tg = lane & 3;
    const int nw = wid & 3;

    int rl0 = m0 + gr;
    int rl1 = rl0 + 8;
    size_t gb0 = (size_t)(bm + rl0) * D_;
    size_t gb1 = (size_t)(bm + rl1) * D_;
    {
        float s0 = 0.f, q0 = 0.f, s1 = 0.f, q1 = 0.f;
#pragma unroll
        for (int ni = 0; ni < 8; ni++) {
            int c = n0 + ni * 8 + tg * 2;
            float2 bv = *(const float2*)(bias + c);
            float2 x0 = *(const float2*)(X + gb0 + c);
            float2 x1 = *(const float2*)(X + gb1 + c);
            acc[ni][0] += bv.x + x0.x;
            acc[ni][1] += bv.y + x0.y;
            acc[ni][2] += bv.x + x1.x;
            acc[ni][3] += bv.y + x1.y;
            s0 += acc[ni][0] + acc[ni][1];
            q0 += acc[ni][0] * acc[ni][0] + acc[ni][1] * acc[ni][1];
            s1 += acc[ni][2] + acc[ni][3];
            q1 += acc[ni][2] * acc[ni][2] + acc[ni][3] * acc[ni][3];
        }
#pragma unroll
        for (int o = 1; o <= 2; o <<= 1) {
            s0 += __shfl_xor_sync(0xFFFFFFFFu, s0, o);
            q0 += __shfl_xor_sync(0xFFFFFFFFu, q0, o);
            s1 += __shfl_xor_sync(0xFFFFFFFFu, s1, o);
            q1 += __shfl_xor_sync(0xFFFFFFFFu, q1, o);
        }
        if (tg == 0) {
            redS[rl0][nw] = s0; redQ[rl0][nw] = q0;
            redS[rl1][nw] = s1; redQ[rl1][nw] = q1;
        }
    }
    __syncthreads();

    {
        float S0 = redS[rl0][0] + redS[rl0][1] + redS[rl0][2] + redS[rl0][3];
        float Q0 = redQ[rl0][0] + redQ[rl0][1] + redQ[rl0][2] + redQ[rl0][3];
        float S1 = redS[rl1][0] + redS[rl1][1] + redS[rl1][2] + redS[rl1][3];
        float Q1 = redQ[rl1][0] + redQ[rl1][1] + redQ[rl1][2] + redQ[rl1][3];
        float mean0 = S0 * (1.0f / D_);
        float mean1 = S1 * (1.0f / D_);
        float r0 = rsqrtf(Q0 * (1.0f / D_) - mean0 * mean0 + 1e-5f);
        float r1 = rsqrtf(Q1 * (1.0f / D_) - mean1 * mean1 + 1e-5f);
#pragma unroll
        for (int ni = 0; ni < 8; ni++) {
            int c = n0 + ni * 8 + tg * 2;
            float2 gv = *(const float2*)(g + c);
            float2 bev = *(const float2*)(be + c);
            float o00 = (acc[ni][0] - mean0) * r0 * gv.x + bev.x;
            float o01 = (acc[ni][1] - mean0) * r0 * gv.y + bev.y;
            float o10 = (acc[ni][2] - mean1) * r1 * gv.x + bev.x;
            float o11 = (acc[ni][3] - mean1) * r1 * gv.y + bev.y;
            *(float2*)(X + gb0 + c) = make_float2(o00, o01);
            *(float2*)(X + gb1 + c) = make_float2(o10, o11);
            uint32_t hp, lp;
            split2h(o00, o01, hp, lp);
            *(uint32_t*)(XH + gb0 + c) = hp;
            *(uint32_t*)(XL + gb0 + c) = lp;
            split2h(o10, o11, hp, lp);
            *(uint32_t*)(XH + gb1 + c) = hp;
            *(uint32_t*)(XL + gb1 + c) = lp;
        }
    }
}

// ====== embedding + positions (+ bias pack) + fp16 hi/lo planes ===========
__global__ void embed_kernel(const int* __restrict__ ids,
                             const float* __restrict__ emb,
                             const float* __restrict__ bq,
                             const float* __restrict__ bk,
                             const float* __restrict__ bv,
                             float* __restrict__ bqkv,
                             float* __restrict__ X,
                             __half* __restrict__ XH,
                             __half* __restrict__ XL)
{
    int t = blockIdx.x;
    int d = threadIdx.x;
    if (t >= M_TOK) {
        int idx = t - M_TOK;
        int l = idx / 3, seg = idx % 3;
        const float* src = (seg == 0) ? bq : (seg == 1) ? bk : bv;
        bqkv[l * QKV_N + seg * 256 + d] = src[l * 256 + d];
        return;
    }
    int s = t & (S_ - 1);
    int id = ids[t];
    float f = (d < D_ / 2) ? (2.0f * d) : (2.0f * (d - D_ / 2) + 1.0f);
    float inv = exp2f(-f * 13.287712379549449f / (float)D_);
    float v = emb[(size_t)id * D_ + d] + sinf((float)s * inv);
    size_t idx = (size_t)t * D_ + d;
    X[idx] = v;
    __half h = __float2half_rn(v);
    XH[idx] = h;
    XL[idx] = __float2half_rn(v - __half2float(h));
}

// ================= tensor-core causal flash attention ====================
// 64 queries per CTA, 4 warps x 16 rows. K/V single fp16 plane, Q hi/lo.
#define AT_PITCH 80
#define AT_QH 0
#define AT_QL 5120
#define AT_KV 10240
#define AT_BUF 10240                 // K 5120 | V 5120
#define AT_SMEM (AT_KV + 2*AT_BUF)   // 30720
#define SCL2E 0.2550348243f          // log2(e)/sqrt(32)

__device__ __forceinline__ void attn_fill_kv(
    uint32_t smU, int buf,
    const __half* __restrict__ Ph,
    size_t rowbase, int kt, int h, int tid)
{
    uint32_t base = smU + AT_KV + buf * AT_BUF;
#pragma unroll
    for (int i = 0; i < 2; i++) {
        int j = tid + 128 * i;
        int row = j >> 2, ch = (j & 3) * 16;
        size_t gk = ((rowbase + kt + row) * QKV_N + 256 + h * DH_) * 2 + ch;
        size_t gv = gk + 512;
        uint32_t d = row * AT_PITCH + ch;
        cp_async16(base + d,        (const char*)Ph + gk);
        cp_async16(base + 5120 + d, (const char*)Ph + gv);
    }
}

__global__ __launch_bounds__(128)
void attn_tc(const __half* __restrict__ Ph,
             const __half* __restrict__ Pl,
             __half* __restrict__ YH, __half* __restrict__ YL,
             const int* __restrict__ tsl)
{
    extern __shared__ char asmem[];
    const int tid = threadIdx.x, lane = tid & 31, w = tid >> 5;
    const int qblk = (gridDim.x - 1) - blockIdx.x;   // longest-first
    const int h = blockIdx.y, b = blockIdx.z;
    const int q0 = qblk * 64;
    const int len = tsl[b];
    const int gr = lane >> 2, tg = lane & 3;
    const uint32_t smU = smem_u32(asmem);
    const size_t rowbase = (size_t)b * S_;

    // stage Q hi/lo (64 rows)
#pragma unroll
    for (int i = 0; i < 2; i++) {
        int j = tid + 128 * i;
        int row = j >> 2, ch = (j & 3) * 16;
        size_t src = ((rowbase + q0 + row) * QKV_N + h * DH_) * 2 + ch;
        cp_async16(smU + AT_QH + row * AT_PITCH + ch, (const char*)Ph + src);
        cp_async16(smU + AT_QL + row * AT_PITCH + ch, (const char*)Pl + src);
    }
    attn_fill_kv(smU, 0, Ph, rowbase, 0, h, tid);
    cp_commit();
    cp_wait0();
    __syncthreads();

    // Q fragments (registers for whole kernel)
    uint32_t qfh[2][4], qfl[2][4];
    {
        int r8 = (lane & 7) + ((lane >> 3) & 1) * 8;
        int cb = ((lane >> 4) & 1) * 16;
#pragma unroll
        for (int kk = 0; kk < 2; kk++) {
            uint32_t off = (uint32_t)(w * 16 + r8) * AT_PITCH + kk * 32 + cb;
            ldsm_x4(qfh[kk], smU + AT_QH + off);
            ldsm_x4(qfl[kk], smU + AT_QL + off);
        }
    }

    float o[4][4];
    float mrow[2] = {-1e30f, -1e30f}, lrow[2] = {0.f, 0.f};
#pragma unroll
    for (int nd = 0; nd < 4; nd++)
#pragma unroll
        for (int e = 0; e < 4; e++) o[nd][e] = 0.f;

    const int qw0 = q0 + w * 16;
    const int nt = qblk + 1;

    for (int t = 0; t < nt; t++) {
        const int kt = t * 64;
        if (t + 1 < nt) {
            attn_fill_kv(smU, (t + 1) & 1, Ph, rowbase, kt + 64, h, tid);
            cp_commit();
            cp_wait1();
        } else {
            cp_wait0();
        }
        __syncthreads();

        const uint32_t kb = smU + AT_KV + (t & 1) * AT_BUF;
        const uint32_t vb = kb + 5120;

        // scores: S = (Qh + Ql) * K
        float s[8][4];
#pragma unroll
        for (int ni = 0; ni < 8; ni++)
#pragma unroll
            for (int e = 0; e < 4; e++) s[ni][e] = 0.f;
        {
            int l7 = lane & 7;
            int hb = ((lane >> 3) & 1) * 16;
#pragma unroll
            for (int kk = 0; kk < 2; kk++)
#pragma unroll
                for (int ni = 0; ni < 8; ni++) {
                    uint32_t off = (uint32_t)(ni * 8 + l7) * AT_PITCH + kk * 32 + hb;
                    uint32_t khf[2];
                    ldsm_x2(khf, kb + off);
                    mma_f16(s[ni], qfh[kk], khf[0], khf[1]);
                    mma_f16(s[ni], qfl[kk], khf[0], khf[1]);
                }
        }

        // causal/length mask (only diagonal tiles need it)
        if (kt + 63 > qw0 || kt + 64 > len) {
            int r0 = qw0 + gr, r1 = r0 + 8;
#pragma unroll
            for (int ni = 0; ni < 8; ni++) {
                int c0 = kt + ni * 8 + tg * 2, c1 = c0 + 1;
                if (c0 > r0 || c0 >= len) s[ni][0] = -1e30f;
                if (c1 > r0 || c1 >= len) s[ni][1] = -1e30f;
                if (c0 > r1 || c0 >= len) s[ni][2] = -1e30f;
                if (c1 > r1 || c1 >= len) s[ni][3] = -1e30f;
            }
        }

        // row max
        float mx[2] = {-1e30f, -1e30f};
#pragma unroll
        for (int ni = 0; ni < 8; ni++) {
            mx[0] = fmaxf(mx[0], fmaxf(s[ni][0], s[ni][1]));
            mx[1] = fmaxf(mx[1], fmaxf(s[ni][2], s[ni][3]));
        }
#pragma unroll
        for (int hh = 0; hh < 2; hh++) {
            float v = mx[hh];
            v = fmaxf(v, __shfl_xor_sync(0xFFFFFFFFu, v, 1));
            v = fmaxf(v, __shfl_xor_sync(0xFFFFFFFFu, v, 2));
            mx[hh] = v;
        }

        // online softmax update
        float corr[2];
#pragma unroll
        for (int hh = 0; hh < 2; hh++) {
            float mn = fmaxf(mrow[hh], mx[hh]);
            corr[hh] = exp2f((mrow[hh] - mn) * SCL2E);
            mrow[hh] = mn;
            lrow[hh] *= corr[hh];
        }
#pragma unroll
        for (int nd = 0; nd < 4; nd++) {
            o[nd][0] *= corr[0];
            o[nd][1] *= corr[0];
            o[nd][2] *= corr[1];
            o[nd][3] *= corr[1];
        }
        float ls[2] = {0.f, 0.f};
#pragma unroll
        for (int ni = 0; ni < 8; ni++) {
            float p0 = exp2f((s[ni][0] - mrow[0]) * SCL2E);
            float p1 = exp2f((s[ni][1] - mrow[0]) * SCL2E);
            float p2 = exp2f((s[ni][2] - mrow[1]) * SCL2E);
            float p3 = exp2f((s[ni][3] - mrow[1]) * SCL2E);
            s[ni][0] = p0; s[ni][1] = p1; s[ni][2] = p2; s[ni][3] = p3;
            ls[0] += p0 + p1;
            ls[1] += p2 + p3;
        }
#pragma unroll
        for (int hh = 0; hh < 2; hh++) {
            float v = ls[hh];
            v += __shfl_xor_sync(0xFFFFFFFFu, v, 1);
            v += __shfl_xor_sync(0xFFFFFFFFu, v, 2);
            lrow[hh] += v;
        }

        // O += (Ph + Pl) * V
        int l15 = lane & 15;
#pragma unroll
        for (int j = 0; j < 4; j++) {
            uint32_t pah[4], pal[4];
            split2h(s[2*j][0],   s[2*j][1],   pah[0], pal[0]);
            split2h(s[2*j][2],   s[2*j][3],   pah[1], pal[1]);
            split2h(s[2*j+1][0], s[2*j+1][1], pah[2], pal[2]);
            split2h(s[2*j+1][2], s[2*j+1][3], pah[3], pal[3]);
#pragma unroll
            for (int nd = 0; nd < 4; nd++) {
                uint32_t off = (uint32_t)(16 * j + l15) * AT_PITCH + nd * 16;
                uint32_t vhf[2];
                ldsm_x2t(vhf, vb + off);
                mma_f16(o[nd], pah, vhf[0], vhf[1]);
                mma_f16(o[nd], pal, vhf[0], vhf[1]);
            }
        }
        __syncthreads();
    }

    // normalize + write hi/lo planes
    int r0 = qw0 + gr, r1 = r0 + 8;
    float inv0 = (r0 < len && lrow[0] > 0.f) ? 1.0f / lrow[0] : 0.f;
    float inv1 = (r1 < len && lrow[1] > 0.f) ? 1.0f / lrow[1] : 0.f;
#pragma unroll
    for (int nd = 0; nd < 4; nd++) {
        int col = h * DH_ + nd * 8 + tg * 2;
        uint32_t hp, lp;
        split2h(o[nd][0] * inv0, o[nd][1] * inv0, hp, lp);
        *(uint32_t*)(YH + (rowbase + r0) * D_ + col) = hp;
        *(uint32_t*)(YL + (rowbase + r0) * D_ + col) = lp;
        split2h(o[nd][2] * inv1, o[nd][3] * inv1, hp, lp);
        *(uint32_t*)(YH + (rowbase + r1) * D_ + col) = hp;
        *(uint32_t*)(YL + (rowbase + r1) * D_ + col) = lp;
    }
}

// =========================== launcher ====================================
extern "C" void kernel_launch(void* const* d_in, const int* in_sizes, int n_in,
                              void* d_out, int out_size)
{
    const int*   ids = (const int*)  d_in[0];
    const int*   tsl = (const int*)  d_in[1];
    const float* emb = (const float*)d_in[2];
    const float* Wq  = (const float*)d_in[3];
    const float* bq  = (const float*)d_in[4];
    const float* Wk  = (const float*)d_in[5];
    const float* bk  = (const float*)d_in[6];
    const float* Wv  = (const float*)d_in[7];
    const float* bv  = (const float*)d_in[8];
    const float* Wo  = (const float*)d_in[9];
    const float* bo  = (const float*)d_in[10];
    const float* W1  = (const float*)d_in[11];
    const float* b1  = (const float*)d_in[12];
    const float* W2  = (const float*)d_in[13];
    const float* b2  = (const float*)d_in[14];
    const float* g1  = (const float*)d_in[15];
    const float* be1 = (const float*)d_in[16];
    const float* g2  = (const float*)d_in[17];
    const float* be2 = (const float*)d_in[18];
    const float* Wc  = (const float*)d_in[19];
    const float* bc  = (const float*)d_in[20];
    float* out = (float*)d_out;

    float *x, *bqkv;
    cudaGetSymbolAddress((void**)&x,   g_x);
    cudaGetSymbolAddress((void**)&bqkv, g_bqkv);

    __half *xh, *xl, *yh, *yl, *ffh, *ffl, *qkvh, *qkvl;
    cudaGetSymbolAddress((void**)&xh,  g_xh);   cudaGetSymbolAddress((void**)&xl,  g_xl);
    cudaGetSymbolAddress((void**)&yh,  g_yh);   cudaGetSymbolAddress((void**)&yl,  g_yl);
    cudaGetSymbolAddress((void**)&ffh, g_ffh);  cudaGetSymbolAddress((void**)&ffl, g_ffl);
    cudaGetSymbolAddress((void**)&qkvh, g_qkvh); cudaGetSymbolAddress((void**)&qkvl, g_qkvl);

    __half *qkvT, *oT, *w1T, *w2T, *wch, *wcl;
    cudaGetSymbolAddress((void**)&qkvT, g_qkvT);
    cudaGetSymbolAddress((void**)&oT,   g_oT);
    cudaGetSymbolAddress((void**)&w1T,  g_1T);
    cudaGetSymbolAddress((void**)&w2T,  g_2T);
    cudaGetSymbolAddress((void**)&wch,  g_cT_hi);
    cudaGetSymbolAddress((void**)&wcl,  g_cT_lo);

    cudaFuncSetAttribute((const void*)gemm_tc,
                         cudaFuncAttributeMaxDynamicSharedMemorySize, GEMM_SMEM);
    cudaFuncSetAttribute((const void*)gemm_ln,
                         cudaFuncAttributeMaxDynamicSharedMemorySize, LN_SMEM);
    cudaFuncSetAttribute((const void*)attn_tc,
                         cudaFuncAttributeMaxDynamicSharedMemorySize, AT_SMEM);

    dim3 tb(32, 8);
    embed_kernel<<<M_TOK + 3 * L_, 256>>>(ids, emb, bq, bk, bv, bqkv, x, xh, xl);
    convert_qkv_kernel<<<dim3(8, 8, 3 * L_), tb>>>(Wq, Wk, Wv, qkvT);
    convert_oc_kernel<<<dim3(8, 8, L_ + 1), tb>>>(Wo, Wc, oT, wch, wcl);
    convert_w_kernel<<<dim3(8, 32, L_), tb>>>(W1, w1T, 256, 1024, 1024);
    convert_w_kernel<<<dim3(32, 8, L_), tb>>>(W2, w2T, 1024, 256, 256);

    dim3 gQKV(QKV_N / GBN, M_TOK / GBM);
    dim3 gF  (DFF_ / GBN,  M_TOK / GBM);
    dim3 gC  (2,           M_TOK / GBM);
    const int gLN = M_TOK / LN_BM;   // 128

    for (int l = 0; l < L_; l++) {
        size_t qoff  = (size_t)l * QKV_N * D_;
        size_t ooff  = (size_t)l * D_ * D_;
        size_t w1off = (size_t)l * DFF_ * D_;

        gemm_tc<<<gQKV, 256, GEMM_SMEM>>>(xh, xl, qkvT + qoff, 0,
                                          bqkv + l * QKV_N, 0, qkvh, qkvl, D_, QKV_N, 0);
        attn_tc<<<dim3(S_ / 64, H_, B_), 128, AT_SMEM>>>(qkvh, qkvl, yh, yl, tsl);

        gemm_ln<<<gLN, 512, LN_SMEM>>>(yh, yl, oT + ooff,
                                       bo + l * D_, g1 + l * D_, be1 + l * D_,
                                       x, xh, xl, D_);

        gemm_tc<<<gF, 256, GEMM_SMEM>>>(xh, xl, w1T + w1off, 0,
                                        b1 + l * DFF_, 0, ffh, ffl, D_, DFF_, 1);

        gemm_ln<<<gLN, 512, LN_SMEM>>>(ffh, ffl, w2T + w1off,
                                       b2 + l * D_, g2 + l * D_, be2 + l * D_,
                                       x, xh, xl, DFF_);
    }

    // classifier keeps 3-term (Wc hi/lo) so logits see no 2^-12 direct error
    gemm_tc<<<gC, 256, GEMM_SMEM>>>(xh, xl, wch, wcl, bc, out, 0, 0, D_, V_, 0);
}

// round 9
// speedup vs baseline: 6.4814x; 1.5006x over previous
#include <cuda_runtime.h>
#include <cuda_fp16.h>
#include <math.h>
#include <stdint.h>

// Problem constants
#define B_  8
#define S_  1024
#define D_  256
#define H_  8
#define DH_ 32
#define L_  4
#define V_  100
#define DFF_ 1024
#define M_TOK (B_ * S_)   // 8192
#define QKV_N 768

// -------- scratch (static device globals; no runtime allocation) --------
__device__ float g_x [M_TOK * D_];

// activation fp16 planes ([M,K] row-major); lo-planes only where needed
__device__ __half g_xh  [M_TOK * D_],  g_xl[M_TOK * D_];
__device__ __half g_yh  [M_TOK * D_];
__device__ __half g_ffh [M_TOK * DFF_];
__device__ __half g_qkvh[M_TOK * QKV_N];

// K-major ([N,K]) fp16 weight planes (single-plane except classifier)
__device__ __half g_qkvT[L_*QKV_N*D_];
__device__ __half g_oT  [L_*D_*D_];
__device__ __half g_1T  [L_*DFF_*D_];
__device__ __half g_2T  [L_*D_*DFF_];
__device__ __half g_cT_hi[128*D_], g_cT_lo[128*D_];
__device__ float g_bqkv[L_ * QKV_N];

// =========================== PTX helpers ==================================
__device__ __forceinline__ uint32_t smem_u32(const void* p) {
    uint32_t r;
    asm("{ .reg .u64 t; cvta.to.shared.u64 t, %1; cvt.u32.u64 %0, t; }"
        : "=r"(r) : "l"(p));
    return r;
}
__device__ __forceinline__ void cp_async16(uint32_t dst, const void* src) {
    asm volatile("cp.async.cg.shared.global [%0], [%1], 16;"
                 :: "r"(dst), "l"(src));
}
__device__ __forceinline__ void cp_commit() {
    asm volatile("cp.async.commit_group;" ::: "memory");
}
__device__ __forceinline__ void cp_wait1() {
    asm volatile("cp.async.wait_group 1;" ::: "memory");
}
__device__ __forceinline__ void cp_wait0() {
    asm volatile("cp.async.wait_group 0;" ::: "memory");
}
__device__ __forceinline__ void ldsm_x4(uint32_t* r, uint32_t addr) {
    asm volatile("ldmatrix.sync.aligned.m8n8.x4.shared.b16 {%0,%1,%2,%3}, [%4];"
                 : "=r"(r[0]), "=r"(r[1]), "=r"(r[2]), "=r"(r[3]) : "r"(addr));
}
__device__ __forceinline__ void ldsm_x2(uint32_t* r, uint32_t addr) {
    asm volatile("ldmatrix.sync.aligned.m8n8.x2.shared.b16 {%0,%1}, [%2];"
                 : "=r"(r[0]), "=r"(r[1]) : "r"(addr));
}
__device__ __forceinline__ void ldsm_x2t(uint32_t* r, uint32_t addr) {
    asm volatile("ldmatrix.sync.aligned.m8n8.x2.trans.shared.b16 {%0,%1}, [%2];"
                 : "=r"(r[0]), "=r"(r[1]) : "r"(addr));
}
__device__ __forceinline__ void mma_f16(float* d, const uint32_t* a,
                                        uint32_t b0, uint32_t b1) {
    asm volatile(
        "mma.sync.aligned.m16n8k16.row.col.f32.f16.f16.f32 "
        "{%0,%1,%2,%3}, {%4,%5,%6,%7}, {%8,%9}, {%0,%1,%2,%3};"
        : "+f"(d[0]), "+f"(d[1]), "+f"(d[2]), "+f"(d[3])
        : "r"(a[0]), "r"(a[1]), "r"(a[2]), "r"(a[3]), "r"(b0), "r"(b1));
}
__device__ __forceinline__ uint32_t swz128(uint32_t x) {
    return x ^ ((x >> 3) & 0x70u);
}
__device__ __forceinline__ uint32_t pack_h2(__half a, __half b) {
    __half2 t(a, b);
    return *reinterpret_cast<uint32_t*>(&t);
}
__device__ __forceinline__ uint32_t pack_f2h(float a, float b) {
    __half2 t = __floats2half2_rn(a, b);
    return *reinterpret_cast<uint32_t*>(&t);
}
__device__ __forceinline__ void split2h(float a, float b, uint32_t& hi, uint32_t& lo) {
    __half h0 = __float2half_rn(a);
    __half h1 = __float2half_rn(b);
    __half l0 = __float2half_rn(a - __half2float(h0));
    __half l1 = __float2half_rn(b - __half2float(h1));
    hi = pack_h2(h0, h1);
    lo = pack_h2(l0, l1);
}

// ===================== GEMM tiling constants ==============================
#define GBM 128
#define GBN 64
#define GKB 64
#define APLANE 16384     // 128 rows x 128B
#define BPLANE 8192      // 64 rows x 128B
#define BUFB (APLANE + BPLANE)          // 24576 (1-pass: A hi | B hi)
#define GEMM_SMEM (2*BUFB + 1024)       // 50176
#define CLS_BUFB (2*APLANE + 2*BPLANE)  // classifier 3-pass layout
#define CLS_SMEM (2*CLS_BUFB + 1024)

// ======== weight transpose + fp16 convert kernels =========================
__global__ void convert_w_kernel(const float* __restrict__ W,
                                 __half* __restrict__ Hi,
                                 int K, int N, int Npad)
{
    __shared__ float t[32][33];
    const float* Wz = W + (size_t)blockIdx.z * K * N;
    __half* Hz = Hi + (size_t)blockIdx.z * Npad * K;
    int k0 = blockIdx.x * 32, n0 = blockIdx.y * 32;
    int tx = threadIdx.x, ty = threadIdx.y;
#pragma unroll
    for (int r = 0; r < 4; r++) {
        int k = k0 + ty + 8 * r;
        int n = n0 + tx;
        t[ty + 8 * r][tx] = (n < N) ? Wz[(size_t)k * N + n] : 0.0f;
    }
    __syncthreads();
#pragma unroll
    for (int r = 0; r < 4; r++) {
        int n = n0 + ty + 8 * r;
        int k = k0 + tx;
        Hz[(size_t)n * K + k] = __float2half_rn(t[tx][ty + 8 * r]);
    }
}

__global__ void convert_qkv_kernel(const float* __restrict__ Wq,
                                   const float* __restrict__ Wk,
                                   const float* __restrict__ Wv,
                                   __half* __restrict__ Hi)
{
    __shared__ float t[32][33];
    int z = blockIdx.z;
    int src = z / L_, l = z % L_;
    const float* W = ((src == 0) ? Wq : (src == 1) ? Wk : Wv) + (size_t)l * D_ * D_;
    __half* Hz = Hi + (size_t)l * QKV_N * D_ + (size_t)src * 256 * D_;
    int k0 = blockIdx.x * 32, n0 = blockIdx.y * 32;
    int tx = threadIdx.x, ty = threadIdx.y;
#pragma unroll
    for (int r = 0; r < 4; r++)
        t[ty + 8 * r][tx] = W[(size_t)(k0 + ty + 8 * r) * D_ + n0 + tx];
    __syncthreads();
#pragma unroll
    for (int r = 0; r < 4; r++) {
        int n = n0 + ty + 8 * r;
        int k = k0 + tx;
        Hz[(size_t)n * D_ + k] = __float2half_rn(t[tx][ty + 8 * r]);
    }
}

__global__ void convert_oc_kernel(const float* __restrict__ Wo,
                                  const float* __restrict__ Wc,
                                  __half* __restrict__ oH,
                                  __half* __restrict__ cH,
                                  __half* __restrict__ cL)
{
    __shared__ float t[32][33];
    int z = blockIdx.z;
    int k0 = blockIdx.x * 32, n0 = blockIdx.y * 32;
    int tx = threadIdx.x, ty = threadIdx.y;
    if (z < L_) {
        const float* W = Wo + (size_t)z * D_ * D_;
        __half* Hz = oH + (size_t)z * D_ * D_;
#pragma unroll
        for (int r = 0; r < 4; r++)
            t[ty + 8 * r][tx] = W[(size_t)(k0 + ty + 8 * r) * D_ + n0 + tx];
        __syncthreads();
#pragma unroll
        for (int r = 0; r < 4; r++) {
            int n = n0 + ty + 8 * r;
            int k = k0 + tx;
            Hz[(size_t)n * D_ + k] = __float2half_rn(t[tx][ty + 8 * r]);
        }
    } else {
        if (blockIdx.y >= 4) return;
#pragma unroll
        for (int r = 0; r < 4; r++) {
            int n = n0 + tx;
            t[ty + 8 * r][tx] = (n < V_) ? Wc[(size_t)(k0 + ty + 8 * r) * V_ + n] : 0.0f;
        }
        __syncthreads();
#pragma unroll
        for (int r = 0; r < 4; r++) {
            int n = n0 + ty + 8 * r;
            int k = k0 + tx;
            float v = t[tx][ty + 8 * r];
            __half h = __float2half_rn(v);
            cH[(size_t)n * D_ + k] = h;
            cL[(size_t)n * D_ + k] = __float2half_rn(v - __half2float(h));
        }
    }
}

// ================== HMMA fp16 single-pass GEMM ============================
// C = A*B^T + bias. A: [M,K] fp16 plane. B: [Npad,K] fp16 plane.
__device__ __forceinline__ void gemm_fill(
    uint32_t smU, int b, int kb,
    const __half* __restrict__ AHi, const __half* __restrict__ BHi,
    int K, int bm, int bn, int tid)
{
    const int k0 = kb * GKB;
    uint32_t aU = smU + b * BUFB;
    uint32_t bU = aU + APLANE;
#pragma unroll
    for (int i = 0; i < 4; i++) {
        int j   = tid + 256 * i;
        int row = j >> 3;
        int ch  = (j & 7) << 4;
        uint32_t off = swz128((uint32_t)(row * 128 + ch));
        cp_async16(aU + off, (const char*)AHi + ((size_t)(bm + row) * K + k0) * 2 + ch);
    }
#pragma unroll
    for (int i = 0; i < 2; i++) {
        int j   = tid + 256 * i;
        int row = j >> 3;
        int ch  = (j & 7) << 4;
        uint32_t off = swz128((uint32_t)(row * 128 + ch));
        cp_async16(bU + off, (const char*)BHi + ((size_t)(bn + row) * K + k0) * 2 + ch);
    }
}

__global__ __launch_bounds__(256, 3)
void gemm_tc(const __half* __restrict__ AHi,
             const __half* __restrict__ BHi,
             const float* __restrict__ bias,
             float* __restrict__ C,
             __half* __restrict__ CHi,
             int K, int N, int relu)
{
    extern __shared__ char dsm_raw[];
    const int tid  = threadIdx.x;
    const int lane = tid & 31;
    const int wid  = tid >> 5;
    const int m0   = (wid >> 1) * 32;
    const int n0   = (wid & 1) * 32;
    const int bm   = blockIdx.y * GBM;
    const int bn   = blockIdx.x * GBN;
    const int nk   = K / GKB;

    uint32_t rawU = smem_u32(dsm_raw);
    uint32_t smU  = (rawU + 1023u) & ~1023u;

    float acc[2][4][4];
#pragma unroll
    for (int mi = 0; mi < 2; mi++)
#pragma unroll
        for (int ni = 0; ni < 4; ni++)
#pragma unroll
            for (int e = 0; e < 4; e++) acc[mi][ni][e] = 0.0f;

    gemm_fill(smU, 0, 0, AHi, BHi, K, bm, bn, tid);
    cp_commit();

    const int a_row = m0 + (lane & 15);
    const int a_kb  = (lane >> 4) * 16;
    const int b_row = n0 + ((lane >> 4) << 3) + (lane & 7);
    const int b_kb  = ((lane >> 3) & 1) * 16;

    for (int kb = 0; kb < nk; kb++) {
        const int b = kb & 1;
        if (kb + 1 < nk) {
            gemm_fill(smU, b ^ 1, kb + 1, AHi, BHi, K, bm, bn, tid);
            cp_commit();
            cp_wait1();
        } else {
            cp_wait0();
        }
        __syncthreads();

        const uint32_t aU = smU + b * BUFB;
        const uint32_t bU = aU + APLANE;
#pragma unroll
        for (int ks = 0; ks < 4; ks++) {
            const int kbase = ks * 32;
            uint32_t ah[2][4], bh[2][4];
#pragma unroll
            for (int mi = 0; mi < 2; mi++)
                ldsm_x4(ah[mi], aU + swz128((uint32_t)((a_row + mi * 16) * 128 + kbase + a_kb)));
#pragma unroll
            for (int bi = 0; bi < 2; bi++)
                ldsm_x4(bh[bi], bU + swz128((uint32_t)((b_row + bi * 16) * 128 + kbase + b_kb)));
#pragma unroll
            for (int mi = 0; mi < 2; mi++)
#pragma unroll
                for (int ni = 0; ni < 4; ni++)
                    mma_f16(acc[mi][ni], ah[mi],
                            bh[ni >> 1][(ni & 1) * 2], bh[ni >> 1][(ni & 1) * 2 + 1]);
        }
        __syncthreads();
    }

    const int gr = lane >> 2;
    const int gc = (lane & 3) * 2;
#pragma unroll
    for (int mi = 0; mi < 2; mi++) {
        int r0 = bm + m0 + mi * 16 + gr;
#pragma unroll
        for (int ni = 0; ni < 4; ni++) {
            int c = bn + n0 + ni * 8 + gc;
            int c0s = (c < N) ? c : N - 1;
            int c1s = (c + 1 < N) ? c + 1 : N - 1;
            float v00 = acc[mi][ni][0] + bias[c0s];
            float v01 = acc[mi][ni][1] + bias[c1s];
            float v10 = acc[mi][ni][2] + bias[c0s];
            float v11 = acc[mi][ni][3] + bias[c1s];
            if (relu) {
                v00 = fmaxf(v00, 0.f); v01 = fmaxf(v01, 0.f);
                v10 = fmaxf(v10, 0.f); v11 = fmaxf(v11, 0.f);
            }
            if (CHi) {
                *(uint32_t*)(CHi + (size_t)r0 * N + c) = pack_f2h(v00, v01);
                *(uint32_t*)(CHi + (size_t)(r0 + 8) * N + c) = pack_f2h(v10, v11);
            } else if (c + 1 < N) {
                *(float2*)(C + (size_t)r0 * N + c) = make_float2(v00, v01);
                *(float2*)(C + (size_t)(r0 + 8) * N + c) = make_float2(v10, v11);
            } else if (c < N) {
                C[(size_t)r0 * N + c] = v00;
                C[(size_t)(r0 + 8) * N + c] = v10;
            }
        }
    }
}

// ============= classifier GEMM: 3-pass split precision ====================
__device__ __forceinline__ void cls_fill(
    uint32_t smU, int b, int kb,
    const __half* __restrict__ AHi, const __half* __restrict__ ALo,
    const __half* __restrict__ BHi, const __half* __restrict__ BLo,
    int K, int bm, int bn, int tid)
{
    const int k0 = kb * GKB;
    uint32_t aHiU = smU + b * CLS_BUFB;
    uint32_t aLoU = aHiU + APLANE;
    uint32_t bHiU = aHiU + 2 * APLANE;
    uint32_t bLoU = bHiU + BPLANE;
#pragma unroll
    for (int i = 0; i < 4; i++) {
        int j   = tid + 256 * i;
        int row = j >> 3;
        int ch  = (j & 7) << 4;
        uint32_t off = swz128((uint32_t)(row * 128 + ch));
        size_t srcb = ((size_t)(bm + row) * K + k0) * 2 + ch;
        cp_async16(aHiU + off, (const char*)AHi + srcb);
        cp_async16(aLoU + off, (const char*)ALo + srcb);
    }
#pragma unroll
    for (int i = 0; i < 2; i++) {
        int j   = tid + 256 * i;
        int row = j >> 3;
        int ch  = (j & 7) << 4;
        uint32_t off = swz128((uint32_t)(row * 128 + ch));
        size_t srcb = ((size_t)(bn + row) * K + k0) * 2 + ch;
        cp_async16(bHiU + off, (const char*)BHi + srcb);
        cp_async16(bLoU + off, (const char*)BLo + srcb);
    }
}

__global__ __launch_bounds__(256, 2)
void gemm_cls(const __half* __restrict__ AHi,
              const __half* __restrict__ ALo,
              const __half* __restrict__ BHi,
              const __half* __restrict__ BLo,
              const float* __restrict__ bias,
              float* __restrict__ C,
              int K, int N)
{
    extern __shared__ char dsm_raw[];
    const int tid  = threadIdx.x;
    const int lane = tid & 31;
    const int wid  = tid >> 5;
    const int m0   = (wid >> 1) * 32;
    const int n0   = (wid & 1) * 32;
    const int bm   = blockIdx.y * GBM;
    const int bn   = blockIdx.x * GBN;
    const int nk   = K / GKB;

    uint32_t rawU = smem_u32(dsm_raw);
    uint32_t smU  = (rawU + 1023u) & ~1023u;

    float acc[2][4][4];
#pragma unroll
    for (int mi = 0; mi < 2; mi++)
#pragma unroll
        for (int ni = 0; ni < 4; ni++)
#pragma unroll
            for (int e = 0; e < 4; e++) acc[mi][ni][e] = 0.0f;

    cls_fill(smU, 0, 0, AHi, ALo, BHi, BLo, K, bm, bn, tid);
    cp_commit();

    const int a_row = m0 + (lane & 15);
    const int a_kb  = (lane >> 4) * 16;
    const int b_row = n0 + ((lane >> 4) << 3) + (lane & 7);
    const int b_kb  = ((lane >> 3) & 1) * 16;

    for (int kb = 0; kb < nk; kb++) {
        const int b = kb & 1;
        if (kb + 1 < nk) {
            cls_fill(smU, b ^ 1, kb + 1, AHi, ALo, BHi, BLo, K, bm, bn, tid);
            cp_commit();
            cp_wait1();
        } else {
            cp_wait0();
        }
        __syncthreads();

        const uint32_t aU = smU + b * CLS_BUFB;
        const uint32_t bU = aU + 2 * APLANE;
#pragma unroll
        for (int ks = 0; ks < 4; ks++) {
            const int kbase = ks * 32;
            uint32_t ah[2][4], al[2][4], bh[2][4], bl[2][4];
#pragma unroll
            for (int mi = 0; mi < 2; mi++) {
                uint32_t off = swz128((uint32_t)((a_row + mi * 16) * 128 + kbase + a_kb));
                ldsm_x4(ah[mi], aU + off);
                ldsm_x4(al[mi], aU + APLANE + off);
            }
#pragma unroll
            for (int bi = 0; bi < 2; bi++) {
                uint32_t off = swz128((uint32_t)((b_row + bi * 16) * 128 + kbase + b_kb));
                ldsm_x4(bh[bi], bU + off);
                ldsm_x4(bl[bi], bU + BPLANE + off);
            }
#pragma unroll
            for (int mi = 0; mi < 2; mi++)
#pragma unroll
                for (int ni = 0; ni < 4; ni++) {
                    uint32_t h0 = bh[ni >> 1][(ni & 1) * 2];
                    uint32_t h1 = bh[ni >> 1][(ni & 1) * 2 + 1];
                    uint32_t l0 = bl[ni >> 1][(ni & 1) * 2];
                    uint32_t l1 = bl[ni >> 1][(ni & 1) * 2 + 1];
                    mma_f16(acc[mi][ni], ah[mi], h0, h1);
                    mma_f16(acc[mi][ni], ah[mi], l0, l1);
                    mma_f16(acc[mi][ni], al[mi], h0, h1);
                }
        }
        __syncthreads();
    }

    const int gr = lane >> 2;
    const int gc = (lane & 3) * 2;
#pragma unroll
    for (int mi = 0; mi < 2; mi++) {
        int r0 = bm + m0 + mi * 16 + gr;
#pragma unroll
        for (int ni = 0; ni < 4; ni++) {
            int c = bn + n0 + ni * 8 + gc;
            if (c + 1 < N) {
                *(float2*)(C + (size_t)r0 * N + c) =
                    make_float2(acc[mi][ni][0] + bias[c], acc[mi][ni][1] + bias[c + 1]);
                *(float2*)(C + (size_t)(r0 + 8) * N + c) =
                    make_float2(acc[mi][ni][2] + bias[c], acc[mi][ni][3] + bias[c + 1]);
            } else if (c < N) {
                C[(size_t)r0 * N + c] = acc[mi][ni][0] + bias[c];
                C[(size_t)(r0 + 8) * N + c] = acc[mi][ni][2] + bias[c];
            }
        }
    }
}

// ========== fused GEMM (N=256) + bias + residual + LayerNorm ==============
#define LN_BM 64
#define LN_AP 8192
#define LN_BP 32768
#define LN_STAGE (LN_AP + LN_BP)       // 40960
#define LN_SMEM (2*LN_STAGE + 1024)

__device__ __forceinline__ void ln_fill(
    uint32_t smU, int b, int kb,
    const __half* __restrict__ AHi, const __half* __restrict__ BHi,
    int K, int bm, int tid)
{
    const int k0 = kb * GKB;
    uint32_t aU = smU + b * LN_STAGE;
    uint32_t bU = aU + LN_AP;
    {
        int row = tid >> 3;
        int ch  = (tid & 7) << 4;
        uint32_t off = swz128((uint32_t)(row * 128 + ch));
        cp_async16(aU + off, (const char*)AHi + ((size_t)(bm + row) * K + k0) * 2 + ch);
    }
#pragma unroll
    for (int i = 0; i < 4; i++) {
        int j   = tid + 512 * i;
        int row = j >> 3;
        int ch  = (j & 7) << 4;
        uint32_t off = swz128((uint32_t)(row * 128 + ch));
        cp_async16(bU + off, (const char*)BHi + ((size_t)row * K + k0) * 2 + ch);
    }
}

__global__ __launch_bounds__(512)
void gemm_ln(const __half* __restrict__ AHi,
             const __half* __restrict__ BHi,
             const float* __restrict__ bias,
             const float* __restrict__ g,
             const float* __restrict__ be,
             float* __restrict__ X,
             __half* __restrict__ XH,
             __half* __restrict__ XL,
             int K)
{
    extern __shared__ char dsm_raw[];
    __shared__ float redS[64][4], redQ[64][4];

    const int tid  = threadIdx.x;
    const int lane = tid & 31;
    const int wid  = tid >> 5;
    const int m0   = (wid >> 2) * 16;
    const int n0   = (wid & 3) * 64;
    const int bm   = blockIdx.x * LN_BM;
    const int nk   = K / GKB;

    uint32_t rawU = smem_u32(dsm_raw);
    uint32_t smU  = (rawU + 1023u) & ~1023u;

    float acc[8][4];
#pragma unroll
    for (int ni = 0; ni < 8; ni++)
#pragma unroll
        for (int e = 0; e < 4; e++) acc[ni][e] = 0.0f;

    ln_fill(smU, 0, 0, AHi, BHi, K, bm, tid);
    cp_commit();

    const int a_row = m0 + (lane & 15);
    const int a_kb  = (lane >> 4) * 16;
    const int b_rowL = ((lane >> 4) << 3) + (lane & 7);
    const int b_kb  = ((lane >> 3) & 1) * 16;

    for (int kb = 0; kb < nk; kb++) {
        const int b = kb & 1;
        if (kb + 1 < nk) {
            ln_fill(smU, b ^ 1, kb + 1, AHi, BHi, K, bm, tid);
            cp_commit();
            cp_wait1();
        } else {
            cp_wait0();
        }
        __syncthreads();

        const uint32_t aU = smU + b * LN_STAGE;
        const uint32_t bU = aU + LN_AP;
#pragma unroll
        for (int ks = 0; ks < 4; ks++) {
            const int kbase = ks * 32;
            uint32_t ah[4], bh[4][4];
            ldsm_x4(ah, aU + swz128((uint32_t)(a_row * 128 + kbase + a_kb)));
#pragma unroll
            for (int bi = 0; bi < 4; bi++)
                ldsm_x4(bh[bi], bU + swz128((uint32_t)((n0 + bi * 16 + b_rowL) * 128 + kbase + b_kb)));
#pragma unroll
            for (int ni = 0; ni < 8; ni++)
                mma_f16(acc[ni], ah,
                        bh[ni >> 1][(ni & 1) * 2], bh[ni >> 1][(ni & 1) * 2 + 1]);
        }
        __syncthreads();
    }

    // ---- epilogue: bias + residual, row stats, LN, write ----
    const int gr = lane >> 2;
    const int tg = lane & 3;
    const int nw = wid & 3;

    int rl0 = m0 + gr;
    int rl1 = rl0 + 8;
    size_t gb0 = (size_t)(bm + rl0) * D_;
    size_t gb1 = (size_t)(bm + rl1) * D_;
    {
        float s0 = 0.f, q0 = 0.f, s1 = 0.f, q1 = 0.f;
#pragma unroll
        for (int ni = 0; ni < 8; ni++) {
            int c = n0 + ni * 8 + tg * 2;
            float2 bv = *(const float2*)(bias + c);
            float2 x0 = *(const float2*)(X + gb0 + c);
            float2 x1 = *(const float2*)(X + gb1 + c);
            acc[ni][0] += bv.x + x0.x;
            acc[ni][1] += bv.y + x0.y;
            acc[ni][2] += bv.x + x1.x;
            acc[ni][3] += bv.y + x1.y;
            s0 += acc[ni][0] + acc[ni][1];
            q0 += acc[ni][0] * acc[ni][0] + acc[ni][1] * acc[ni][1];
            s1 += acc[ni][2] + acc[ni][3];
            q1 += acc[ni][2] * acc[ni][2] + acc[ni][3] * acc[ni][3];
        }
#pragma unroll
        for (int o = 1; o <= 2; o <<= 1) {
            s0 += __shfl_xor_sync(0xFFFFFFFFu, s0, o);
            q0 += __shfl_xor_sync(0xFFFFFFFFu, q0, o);
            s1 += __shfl_xor_sync(0xFFFFFFFFu, s1, o);
            q1 += __shfl_xor_sync(0xFFFFFFFFu, q1, o);
        }
        if (tg == 0) {
            redS[rl0][nw] = s0; redQ[rl0][nw] = q0;
            redS[rl1][nw] = s1; redQ[rl1][nw] = q1;
        }
    }
    __syncthreads();

    {
        float S0 = redS[rl0][0] + redS[rl0][1] + redS[rl0][2] + redS[rl0][3];
        float Q0 = redQ[rl0][0] + redQ[rl0][1] + redQ[rl0][2] + redQ[rl0][3];
        float S1 = redS[rl1][0] + redS[rl1][1] + redS[rl1][2] + redS[rl1][3];
        float Q1 = redQ[rl1][0] + redQ[rl1][1] + redQ[rl1][2] + redQ[rl1][3];
        float mean0 = S0 * (1.0f / D_);
        float mean1 = S1 * (1.0f / D_);
        float r0 = rsqrtf(Q0 * (1.0f / D_) - mean0 * mean0 + 1e-5f);
        float r1 = rsqrtf(Q1 * (1.0f / D_) - mean1 * mean1 + 1e-5f);
#pragma unroll
        for (int ni = 0; ni < 8; ni++) {
            int c = n0 + ni * 8 + tg * 2;
            float2 gv = *(const float2*)(g + c);
            float2 bev = *(const float2*)(be + c);
            float o00 = (acc[ni][0] - mean0) * r0 * gv.x + bev.x;
            float o01 = (acc[ni][1] - mean0) * r0 * gv.y + bev.y;
            float o10 = (acc[ni][2] - mean1) * r1 * gv.x + bev.x;
            float o11 = (acc[ni][3] - mean1) * r1 * gv.y + bev.y;
            *(float2*)(X + gb0 + c) = make_float2(o00, o01);
            *(float2*)(X + gb1 + c) = make_float2(o10, o11);
            uint32_t hp, lp;
            split2h(o00, o01, hp, lp);
            *(uint32_t*)(XH + gb0 + c) = hp;
            *(uint32_t*)(XL + gb0 + c) = lp;
            split2h(o10, o11, hp, lp);
            *(uint32_t*)(XH + gb1 + c) = hp;
            *(uint32_t*)(XL + gb1 + c) = lp;
        }
    }
}

// ====== embedding + positions (+ bias pack) + fp16 hi/lo planes ===========
__global__ void embed_kernel(const int* __restrict__ ids,
                             const float* __restrict__ emb,
                             const float* __restrict__ bq,
                             const float* __restrict__ bk,
                             const float* __restrict__ bv,
                             float* __restrict__ bqkv,
                             float* __restrict__ X,
                             __half* __restrict__ XH,
                             __half* __restrict__ XL)
{
    int t = blockIdx.x;
    int d = threadIdx.x;
    if (t >= M_TOK) {
        int idx = t - M_TOK;
        int l = idx / 3, seg = idx % 3;
        const float* src = (seg == 0) ? bq : (seg == 1) ? bk : bv;
        bqkv[l * QKV_N + seg * 256 + d] = src[l * 256 + d];
        return;
    }
    int s = t & (S_ - 1);
    int id = ids[t];
    float f = (d < D_ / 2) ? (2.0f * d) : (2.0f * (d - D_ / 2) + 1.0f);
    float inv = exp2f(-f * 13.287712379549449f / (float)D_);
    float v = emb[(size_t)id * D_ + d] + sinf((float)s * inv);
    size_t idx = (size_t)t * D_ + d;
    X[idx] = v;
    __half h = __float2half_rn(v);
    XH[idx] = h;
    XL[idx] = __float2half_rn(v - __half2float(h));
}

// ================= tensor-core causal flash attention ====================
// 64 queries/CTA, 4 warps x 16 rows. Q/K/V single fp16 plane, 1-pass MMA.
#define AT_PITCH 80
#define AT_Q 0
#define AT_KV 5120
#define AT_BUF 10240                 // K 5120 | V 5120
#define AT_SMEM (AT_KV + 2*AT_BUF + 1024)   // 26624
#define SCL2E 0.2550348243f          // log2(e)/sqrt(32)

__device__ __forceinline__ void attn_fill_kv(
    uint32_t smU, int buf,
    const __half* __restrict__ Ph,
    size_t rowbase, int kt, int h, int tid)
{
    uint32_t base = smU + AT_KV + buf * AT_BUF;
#pragma unroll
    for (int i = 0; i < 2; i++) {
        int j = tid + 128 * i;
        int row = j >> 2, ch = (j & 3) * 16;
        size_t gk = ((rowbase + kt + row) * QKV_N + 256 + h * DH_) * 2 + ch;
        size_t gv = gk + 512;
        uint32_t d = row * AT_PITCH + ch;
        cp_async16(base + d,        (const char*)Ph + gk);
        cp_async16(base + 5120 + d, (const char*)Ph + gv);
    }
}

__global__ __launch_bounds__(128)
void attn_tc(const __half* __restrict__ Ph,
             __half* __restrict__ YH,
             const int* __restrict__ tsl)
{
    extern __shared__ char asmem_raw[];
    const int tid = threadIdx.x, lane = tid & 31, w = tid >> 5;
    const int qblk = (gridDim.x - 1) - blockIdx.x;   // longest-first
    const int h = blockIdx.y, b = blockIdx.z;
    const int q0 = qblk * 64;
    const int len = tsl[b];
    const int gr = lane >> 2, tg = lane & 3;
    uint32_t rawU = smem_u32(asmem_raw);
    const uint32_t smU = (rawU + 1023u) & ~1023u;
    const size_t rowbase = (size_t)b * S_;

    // stage Q (64 rows, single plane)
    {
        int j = tid;                      // 0..127 -> 2 chunks per row... 64 rows x 64B = 256 chunks
#pragma unroll
        for (int i = 0; i < 2; i++) {
            int jj = j + 128 * i;
            int row = jj >> 2, ch = (jj & 3) * 16;
            size_t src = ((rowbase + q0 + row) * QKV_N + h * DH_) * 2 + ch;
            cp_async16(smU + AT_Q + row * AT_PITCH + ch, (const char*)Ph + src);
        }
    }
    attn_fill_kv(smU, 0, Ph, rowbase, 0, h, tid);
    cp_commit();
    cp_wait0();
    __syncthreads();

    // Q fragments (registers for whole kernel)
    uint32_t qf[2][4];
    {
        int r8 = (lane & 7) + ((lane >> 3) & 1) * 8;
        int cb = ((lane >> 4) & 1) * 16;
#pragma unroll
        for (int kk = 0; kk < 2; kk++)
            ldsm_x4(qf[kk], smU + AT_Q + (uint32_t)(w * 16 + r8) * AT_PITCH + kk * 32 + cb);
    }

    float o[4][4];
    float mrow[2] = {-1e30f, -1e30f}, lrow[2] = {0.f, 0.f};
#pragma unroll
    for (int nd = 0; nd < 4; nd++)
#pragma unroll
        for (int e = 0; e < 4; e++) o[nd][e] = 0.f;

    const int qw0 = q0 + w * 16;
    const int nt = qblk + 1;

    for (int t = 0; t < nt; t++) {
        const int kt = t * 64;
        if (t + 1 < nt) {
            attn_fill_kv(smU, (t + 1) & 1, Ph, rowbase, kt + 64, h, tid);
            cp_commit();
            cp_wait1();
        } else {
            cp_wait0();
        }
        __syncthreads();

        const uint32_t kb = smU + AT_KV + (t & 1) * AT_BUF;
        const uint32_t vb = kb + 5120;

        // scores: S = Q * K (single pass)
        float s[8][4];
#pragma unroll
        for (int ni = 0; ni < 8; ni++)
#pragma unroll
            for (int e = 0; e < 4; e++) s[ni][e] = 0.f;
        {
            int l7 = lane & 7;
            int hb = ((lane >> 3) & 1) * 16;
#pragma unroll
            for (int kk = 0; kk < 2; kk++)
#pragma unroll
                for (int ni = 0; ni < 8; ni++) {
                    uint32_t khf[2];
                    ldsm_x2(khf, kb + (uint32_t)(ni * 8 + l7) * AT_PITCH + kk * 32 + hb);
                    mma_f16(s[ni], qf[kk], khf[0], khf[1]);
                }
        }

        // causal/length mask
        if (kt + 63 > qw0 || kt + 64 > len) {
            int r0 = qw0 + gr, r1 = r0 + 8;
#pragma unroll
            for (int ni = 0; ni < 8; ni++) {
                int c0 = kt + ni * 8 + tg * 2, c1 = c0 + 1;
                if (c0 > r0 || c0 >= len) s[ni][0] = -1e30f;
                if (c1 > r0 || c1 >= len) s[ni][1] = -1e30f;
                if (c0 > r1 || c0 >= len) s[ni][2] = -1e30f;
                if (c1 > r1 || c1 >= len) s[ni][3] = -1e30f;
            }
        }

        // row max
        float mx[2] = {-1e30f, -1e30f};
#pragma unroll
        for (int ni = 0; ni < 8; ni++) {
            mx[0] = fmaxf(mx[0], fmaxf(s[ni][0], s[ni][1]));
            mx[1] = fmaxf(mx[1], fmaxf(s[ni][2], s[ni][3]));
        }
#pragma unroll
        for (int hh = 0; hh < 2; hh++) {
            float v = mx[hh];
            v = fmaxf(v, __shfl_xor_sync(0xFFFFFFFFu, v, 1));
            v = fmaxf(v, __shfl_xor_sync(0xFFFFFFFFu, v, 2));
            mx[hh] = v;
        }

        // online softmax update
        float corr[2];
#pragma unroll
        for (int hh = 0; hh < 2; hh++) {
            float mn = fmaxf(mrow[hh], mx[hh]);
            corr[hh] = exp2f((mrow[hh] - mn) * SCL2E);
            mrow[hh] = mn;
            lrow[hh] *= corr[hh];
        }
#pragma unroll
        for (int nd = 0; nd < 4; nd++) {
            o[nd][0] *= corr[0];
            o[nd][1] *= corr[0];
            o[nd][2] *= corr[1];
            o[nd][3] *= corr[1];
        }
        float ls[2] = {0.f, 0.f};
#pragma unroll
        for (int ni = 0; ni < 8; ni++) {
            float p0 = exp2f((s[ni][0] - mrow[0]) * SCL2E);
            float p1 = exp2f((s[ni][1] - mrow[0]) * SCL2E);
            float p2 = exp2f((s[ni][2] - mrow[1]) * SCL2E);
            float p3 = exp2f((s[ni][3] - mrow[1]) * SCL2E);
            s[ni][0] = p0; s[ni][1] = p1; s[ni][2] = p2; s[ni][3] = p3;
            ls[0] += p0 + p1;
            ls[1] += p2 + p3;
        }
#pragma unroll
        for (int hh = 0; hh < 2; hh++) {
            float v = ls[hh];
            v += __shfl_xor_sync(0xFFFFFFFFu, v, 1);
            v += __shfl_xor_sync(0xFFFFFFFFu, v, 2);
            lrow[hh] += v;
        }

        // O += P * V (single pass, P packed to fp16 directly)
        int l15 = lane & 15;
#pragma unroll
        for (int j = 0; j < 4; j++) {
            uint32_t pa[4];
            pa[0] = pack_f2h(s[2*j][0],   s[2*j][1]);
            pa[1] = pack_f2h(s[2*j][2],   s[2*j][3]);
            pa[2] = pack_f2h(s[2*j+1][0], s[2*j+1][1]);
            pa[3] = pack_f2h(s[2*j+1][2], s[2*j+1][3]);
#pragma unroll
            for (int nd = 0; nd < 4; nd++) {
                uint32_t vhf[2];
                ldsm_x2t(vhf, vb + (uint32_t)(16 * j + l15) * AT_PITCH + nd * 16);
                mma_f16(o[nd], pa, vhf[0], vhf[1]);
            }
        }
        __syncthreads();
    }

    // normalize + write single hi plane
    int r0 = qw0 + gr, r1 = r0 + 8;
    float inv0 = (r0 < len && lrow[0] > 0.f) ? 1.0f / lrow[0] : 0.f;
    float inv1 = (r1 < len && lrow[1] > 0.f) ? 1.0f / lrow[1] : 0.f;
#pragma unroll
    for (int nd = 0; nd < 4; nd++) {
        int col = h * DH_ + nd * 8 + tg * 2;
        *(uint32_t*)(YH + (rowbase + r0) * D_ + col) = pack_f2h(o[nd][0] * inv0, o[nd][1] * inv0);
        *(uint32_t*)(YH + (rowbase + r1) * D_ + col) = pack_f2h(o[nd][2] * inv1, o[nd][3] * inv1);
    }
}

// =========================== launcher ====================================
extern "C" void kernel_launch(void* const* d_in, const int* in_sizes, int n_in,
                              void* d_out, int out_size)
{
    const int*   ids = (const int*)  d_in[0];
    const int*   tsl = (const int*)  d_in[1];
    const float* emb = (const float*)d_in[2];
    const float* Wq  = (const float*)d_in[3];
    const float* bq  = (const float*)d_in[4];
    const float* Wk  = (const float*)d_in[5];
    const float* bk  = (const float*)d_in[6];
    const float* Wv  = (const float*)d_in[7];
    const float* bv  = (const float*)d_in[8];
    const float* Wo  = (const float*)d_in[9];
    const float* bo  = (const float*)d_in[10];
    const float* W1  = (const float*)d_in[11];
    const float* b1  = (const float*)d_in[12];
    const float* W2  = (const float*)d_in[13];
    const float* b2  = (const float*)d_in[14];
    const float* g1  = (const float*)d_in[15];
    const float* be1 = (const float*)d_in[16];
    const float* g2  = (const float*)d_in[17];
    const float* be2 = (const float*)d_in[18];
    const float* Wc  = (const float*)d_in[19];
    const float* bc  = (const float*)d_in[20];
    float* out = (float*)d_out;

    float *x, *bqkv;
    cudaGetSymbolAddress((void**)&x,   g_x);
    cudaGetSymbolAddress((void**)&bqkv, g_bqkv);

    __half *xh, *xl, *yh, *ffh, *qkvh;
    cudaGetSymbolAddress((void**)&xh,  g_xh);
    cudaGetSymbolAddress((void**)&xl,  g_xl);
    cudaGetSymbolAddress((void**)&yh,  g_yh);
    cudaGetSymbolAddress((void**)&ffh, g_ffh);
    cudaGetSymbolAddress((void**)&qkvh, g_qkvh);

    __half *qkvT, *oT, *w1T, *w2T, *wch, *wcl;
    cudaGetSymbolAddress((void**)&qkvT, g_qkvT);
    cudaGetSymbolAddress((void**)&oT,   g_oT);
    cudaGetSymbolAddress((void**)&w1T,  g_1T);
    cudaGetSymbolAddress((void**)&w2T,  g_2T);
    cudaGetSymbolAddress((void**)&wch,  g_cT_hi);
    cudaGetSymbolAddress((void**)&wcl,  g_cT_lo);

    cudaFuncSetAttribute((const void*)gemm_tc,
                         cudaFuncAttributeMaxDynamicSharedMemorySize, GEMM_SMEM);
    cudaFuncSetAttribute((const void*)gemm_cls,
                         cudaFuncAttributeMaxDynamicSharedMemorySize, CLS_SMEM);
    cudaFuncSetAttribute((const void*)gemm_ln,
                         cudaFuncAttributeMaxDynamicSharedMemorySize, LN_SMEM);
    cudaFuncSetAttribute((const void*)attn_tc,
                         cudaFuncAttributeMaxDynamicSharedMemorySize, AT_SMEM);

    dim3 tb(32, 8);
    embed_kernel<<<M_TOK + 3 * L_, 256>>>(ids, emb, bq, bk, bv, bqkv, x, xh, xl);
    convert_qkv_kernel<<<dim3(8, 8, 3 * L_), tb>>>(Wq, Wk, Wv, qkvT);
    convert_oc_kernel<<<dim3(8, 8, L_ + 1), tb>>>(Wo, Wc, oT, wch, wcl);
    convert_w_kernel<<<dim3(8, 32, L_), tb>>>(W1, w1T, 256, 1024, 1024);
    convert_w_kernel<<<dim3(32, 8, L_), tb>>>(W2, w2T, 1024, 256, 256);

    dim3 gQKV(QKV_N / GBN, M_TOK / GBM);
    dim3 gF  (DFF_ / GBN,  M_TOK / GBM);
    dim3 gC  (2,           M_TOK / GBM);
    const int gLN = M_TOK / LN_BM;   // 128

    for (int l = 0; l < L_; l++) {
        size_t qoff  = (size_t)l * QKV_N * D_;
        size_t ooff  = (size_t)l * D_ * D_;
        size_t w1off = (size_t)l * DFF_ * D_;

        gemm_tc<<<gQKV, 256, GEMM_SMEM>>>(xh, qkvT + qoff,
                                          bqkv + l * QKV_N, 0, qkvh, D_, QKV_N, 0);
        attn_tc<<<dim3(S_ / 64, H_, B_), 128, AT_SMEM>>>(qkvh, yh, tsl);

        gemm_ln<<<gLN, 512, LN_SMEM>>>(yh, oT + ooff,
                                       bo + l * D_, g1 + l * D_, be1 + l * D_,
                                       x, xh, xl, D_);

        gemm_tc<<<gF, 256, GEMM_SMEM>>>(xh, w1T + w1off,
                                        b1 + l * DFF_, 0, ffh, D_, DFF_, 1);

        gemm_ln<<<gLN, 512, LN_SMEM>>>(ffh, w2T + w1off,
                                       b2 + l * D_, g2 + l * D_, be2 + l * D_,
                                       x, xh, xl, DFF_);
    }

    // classifier: 3-pass split precision (logits see no direct fp16 error)
    gemm_cls<<<gC, 256, CLS_SMEM>>>(xh, xl, wch, wcl, bc, out, D_, V_);
}